// round 11
// baseline (speedup 1.0000x reference)
#include <cuda_runtime.h>
#include <math.h>
#include <stdint.h>

#define L_   12
#define S_   512
#define B_   4
#define DIN_ 768
#define D_   1024
#define H_   16
#define F_   4096
#define HD_  64
#define T_   (S_*B_)   // 2048 tokens

// ---------------- scratch (static device globals; no runtime allocation) ----
__device__ float g_h[T_*D_];
__device__ float g_q[T_*D_];
__device__ float g_k[T_*D_];
__device__ float g_v[T_*D_];
__device__ float g_attn[T_*D_];
__device__ float g_ff[(size_t)T_*F_];
__device__ float g_scores[(size_t)B_*H_*S_*S_];   // 67 MB

// ---------------- bf16 split helpers ---------------------------------------
__device__ __forceinline__ unsigned pack_bf16(float x0, float x1) {
    unsigned u;
    asm("cvt.rn.bf16x2.f32 %0, %1, %2;" : "=r"(u) : "f"(x1), "f"(x0));
    return u;
}
__device__ __forceinline__ void split4_bf16(float4 v, unsigned& h0, unsigned& h1,
                                            unsigned& l0, unsigned& l1)
{
    h0 = pack_bf16(v.x, v.y);
    h1 = pack_bf16(v.z, v.w);
    const float hx = __uint_as_float(h0 << 16);
    const float hy = __uint_as_float(h0 & 0xffff0000u);
    const float hz = __uint_as_float(h1 << 16);
    const float hw = __uint_as_float(h1 & 0xffff0000u);
    l0 = pack_bf16(v.x - hx, v.y - hy);
    l1 = pack_bf16(v.z - hz, v.w - hw);
}
__device__ __forceinline__ void splitp_bf16(float a, float b, unsigned& h, unsigned& l)
{
    h = pack_bf16(a, b);
    const float ha = __uint_as_float(h << 16);
    const float hb = __uint_as_float(h & 0xffff0000u);
    l = pack_bf16(a - ha, b - hb);
}

__device__ __forceinline__ void mma_bf16(float c[4],
    unsigned a0, unsigned a1, unsigned a2, unsigned a3,
    unsigned b0, unsigned b1)
{
    asm volatile(
        "mma.sync.aligned.m16n8k16.row.col.f32.bf16.bf16.f32 "
        "{%0,%1,%2,%3}, {%4,%5,%6,%7}, {%8,%9}, {%0,%1,%2,%3};"
        : "+f"(c[0]), "+f"(c[1]), "+f"(c[2]), "+f"(c[3])
        : "r"(a0), "r"(a1), "r"(a2), "r"(a3), "r"(b0), "r"(b1));
}

// ---------------- tensor-core GEMM (3x bf16 split, BM=64, 2 CTA/SM) --------
// C = A[MxK] @ W[KxN] + bias[c] + bias2[c] + rowvec[r]*colvec[c];
// optional exact GELU; + residual[r,c]
// block tile 64x128x32, 8 warps (2x4), warp tile 32x32, m16n8k16 bf16
// smem per stage (u32): A frag-major [4 mtiles][2 steps][2 hl][32 lanes][4]
//                       = 2048 u32; B k-pair-major hi/lo [16][136] x2 = 4352
#define TBM 64
#define TBN 128
#define TBK 32
#define B_STU 136
#define AFRAG_U 2048
#define OFF_BHU AFRAG_U                        // 2048
#define OFF_BLU (AFRAG_U + 16*B_STU)           // 4224
#define STAGE_U (AFRAG_U + 2*16*B_STU)         // 6400
#define SMEM_BYTES (2*STAGE_U*4)               // 51200

// A fragment index: ((mt4*2 + step)*2 + hl)*128 + lane*4
__device__ __forceinline__ int afrag_idx(int mt4, int step, int hl, int lane) {
    return (((mt4 * 2 + step) * 2 + hl) * 128) + lane * 4;
}

__device__ __forceinline__ void store_split_tile(
    unsigned* stage, int tid, const float4* pa,
    const float4* pb0, const float4* pb1)
{
    // A: 64x32 floats -> frag-major hi/lo bf16x2
    #pragma unroll
    for (int it = 0; it < 2; it++) {
        const int s = tid + it * 256;
        const int r = s >> 3, kc = (s & 7) * 4;   // k floats kc..kc+3
        unsigned h[2], l[2];
        split4_bf16(pa[it], h[0], h[1], l[0], l[1]);
        const int rr  = r & 15;
        const int mt4 = r >> 4;                   // 0..3
        const int P0  = kc >> 1;                  // first k-pair
        #pragma unroll
        for (int j = 0; j < 2; j++) {
            const int p    = P0 + j;
            const int step = p >> 3;
            const int pp   = p & 7;
            const int lane = (rr & 7) * 4 + (pp & 3);
            const int reg  = (rr >> 3) + ((pp >> 2) << 1);
            stage[afrag_idx(mt4, step, 0, lane) + reg] = h[j];
            stage[afrag_idx(mt4, step, 1, lane) + reg] = l[j];
        }
    }
    // B: 32x128 floats -> k-pair packed hi/lo [16][136] u32
    #pragma unroll
    for (int it = 0; it < 2; it++) {
        const int s = tid + it * 256;
        const int p  = s >> 5;            // k-pair 0..15
        const int nq = (s & 31) * 4;      // n offset
        uint4 hv, lv;
        splitp_bf16(pb0[it].x, pb1[it].x, hv.x, lv.x);
        splitp_bf16(pb0[it].y, pb1[it].y, hv.y, lv.y);
        splitp_bf16(pb0[it].z, pb1[it].z, hv.z, lv.z);
        splitp_bf16(pb0[it].w, pb1[it].w, hv.w, lv.w);
        *(uint4*)&stage[OFF_BHU + p * B_STU + nq] = hv;
        *(uint4*)&stage[OFF_BLU + p * B_STU + nq] = lv;
    }
}

__global__ __launch_bounds__(256, 2) void gemm_tc(
    const float* __restrict__ A, const float* __restrict__ Bw,
    const float* __restrict__ bias, const float* __restrict__ bias2,
    const float* __restrict__ rowvec, const float* __restrict__ colvec,
    const float* __restrict__ residual,
    float* __restrict__ C, int M, int N, int K, int gelu_flag)
{
    extern __shared__ unsigned smbuf[];
    unsigned* cur = smbuf;
    unsigned* nxt = smbuf + STAGE_U;

    const int tid  = threadIdx.x;
    const int warp = tid >> 5;
    const int lane = tid & 31;
    const int g    = lane >> 2;      // 0..7
    const int tig  = lane & 3;       // 0..3
    const int wr   = warp >> 2;          // warp row 0..1
    const int wmt  = wr * 2;             // first m-tile (of 16 rows)
    const int wm   = wr * 32;
    const int wn   = (warp & 3) * 32;    // 0,32,64,96

    const int row0 = blockIdx.y * TBM;
    const int col0 = blockIdx.x * TBN;

    float acc[2][4][4];
    #pragma unroll
    for (int mt = 0; mt < 2; mt++)
        #pragma unroll
        for (int nt = 0; nt < 4; nt++)
            #pragma unroll
            for (int r = 0; r < 4; r++) acc[mt][nt][r] = 0.f;

    float4 pa[2], pb0[2], pb1[2];

    // ---- prologue: load tile 0 and split into cur
    #pragma unroll
    for (int it = 0; it < 2; it++) {
        const int s = tid + it * 256;
        pa[it] = *(const float4*)(A + (size_t)(row0 + (s >> 3)) * K + (s & 7) * 4);
    }
    #pragma unroll
    for (int it = 0; it < 2; it++) {
        const int s = tid + it * 256;
        const int p = s >> 5, nq = (s & 31) * 4;
        pb0[it] = *(const float4*)(Bw + (size_t)(2 * p)     * N + col0 + nq);
        pb1[it] = *(const float4*)(Bw + (size_t)(2 * p + 1) * N + col0 + nq);
    }
    store_split_tile(cur, tid, pa, pb0, pb1);
    __syncthreads();

    const int nk = K / TBK;
    for (int ki = 0; ki < nk; ki++) {
        const bool more = (ki + 1 < nk);
        if (more) {
            const int k0n = (ki + 1) * TBK;
            #pragma unroll
            for (int it = 0; it < 2; it++) {
                const int s = tid + it * 256;
                pa[it] = *(const float4*)(A + (size_t)(row0 + (s >> 3)) * K + k0n + (s & 7) * 4);
            }
            #pragma unroll
            for (int it = 0; it < 2; it++) {
                const int s = tid + it * 256;
                const int p = s >> 5, nq = (s & 31) * 4;
                pb0[it] = *(const float4*)(Bw + (size_t)(k0n + 2 * p)     * N + col0 + nq);
                pb1[it] = *(const float4*)(Bw + (size_t)(k0n + 2 * p + 1) * N + col0 + nq);
            }
        }

        // ---- compute current stage: 2 x k16 steps; A frags via LDS.128
        const unsigned* Bh = cur + OFF_BHU;
        const unsigned* Bl = cur + OFF_BLU;
        #pragma unroll
        for (int st = 0; st < 2; st++) {
            const int pb = st * 8;
            unsigned ah[2][4], al[2][4];
            #pragma unroll
            for (int mt = 0; mt < 2; mt++) {
                uint4 av = *(const uint4*)&cur[afrag_idx(wmt + mt, st, 0, lane)];
                ah[mt][0] = av.x; ah[mt][1] = av.y; ah[mt][2] = av.z; ah[mt][3] = av.w;
                uint4 lv = *(const uint4*)&cur[afrag_idx(wmt + mt, st, 1, lane)];
                al[mt][0] = lv.x; al[mt][1] = lv.y; al[mt][2] = lv.z; al[mt][3] = lv.w;
            }
            unsigned bh[4][2], bl[4][2];
            #pragma unroll
            for (int nt = 0; nt < 4; nt++) {
                const int n = wn + nt * 8 + g;
                const int c0i = (pb + tig) * B_STU + n;
                const int c1i = (pb + tig + 4) * B_STU + n;
                bh[nt][0] = Bh[c0i]; bh[nt][1] = Bh[c1i];
                bl[nt][0] = Bl[c0i]; bl[nt][1] = Bl[c1i];
            }
            #pragma unroll
            for (int mt = 0; mt < 2; mt++)
                #pragma unroll
                for (int nt = 0; nt < 4; nt++) {
                    mma_bf16(acc[mt][nt], ah[mt][0], ah[mt][1], ah[mt][2], ah[mt][3],
                             bh[nt][0], bh[nt][1]);
                    mma_bf16(acc[mt][nt], al[mt][0], al[mt][1], al[mt][2], al[mt][3],
                             bh[nt][0], bh[nt][1]);
                    mma_bf16(acc[mt][nt], ah[mt][0], ah[mt][1], ah[mt][2], ah[mt][3],
                             bl[nt][0], bl[nt][1]);
                }
        }

        if (more) store_split_tile(nxt, tid, pa, pb0, pb1);
        __syncthreads();
        unsigned* t = cur; cur = nxt; nxt = t;
    }

    // ---- epilogue
    #pragma unroll
    for (int mt = 0; mt < 2; mt++) {
        #pragma unroll
        for (int half = 0; half < 2; half++) {
            const int r = row0 + wm + mt * 16 + g + half * 8;
            const float rv = rowvec ? rowvec[r] : 0.f;
            #pragma unroll
            for (int nt = 0; nt < 4; nt++) {
                const int c = col0 + wn + nt * 8 + 2 * tig;
                float v0 = acc[mt][nt][half * 2 + 0];
                float v1 = acc[mt][nt][half * 2 + 1];
                if (bias)  { v0 += bias[c];  v1 += bias[c + 1]; }
                if (bias2) { v0 += bias2[c]; v1 += bias2[c + 1]; }
                if (rowvec) { v0 += rv * colvec[c]; v1 += rv * colvec[c + 1]; }
                if (gelu_flag) {
                    v0 = 0.5f * v0 * (1.f + erff(v0 * 0.70710678118654752f));
                    v1 = 0.5f * v1 * (1.f + erff(v1 * 0.70710678118654752f));
                }
                if (residual) {
                    float2 rr = *(const float2*)(residual + (size_t)r * N + c);
                    v0 += rr.x; v1 += rr.y;
                }
                float2 o; o.x = v0; o.y = v1;
                *(float2*)(C + (size_t)r * N + c) = o;
            }
        }
    }
}

// ---------------- LayerNorm: one block per token ---------------------------
__global__ __launch_bounds__(256) void ln_kernel(
    const float* __restrict__ x, const float* __restrict__ g,
    const float* __restrict__ bta, float* __restrict__ out)
{
    const int t = blockIdx.x;
    const int tid = threadIdx.x;
    const float* xr = x + (size_t)t * D_;

    float v[4];
    float s = 0.f, s2 = 0.f;
    #pragma unroll
    for (int i = 0; i < 4; i++) {
        v[i] = xr[tid + i*256];
        s  += v[i];
        s2 += v[i] * v[i];
    }
    #pragma unroll
    for (int o = 16; o; o >>= 1) {
        s  += __shfl_xor_sync(0xffffffffu, s,  o);
        s2 += __shfl_xor_sync(0xffffffffu, s2, o);
    }
    __shared__ float ss[8], ss2[8];
    if ((tid & 31) == 0) { ss[tid >> 5] = s; ss2[tid >> 5] = s2; }
    __syncthreads();
    s = 0.f; s2 = 0.f;
    #pragma unroll
    for (int w = 0; w < 8; w++) { s += ss[w]; s2 += ss2[w]; }

    const float mean = s * (1.f / D_);
    const float var  = s2 * (1.f / D_) - mean * mean;
    const float inv  = rsqrtf(var + 1e-5f);

    float* orow = out + (size_t)t * D_;
    #pragma unroll
    for (int i = 0; i < 4; i++) {
        const int c = tid + i*256;
        orow[c] = (v[i] - mean) * inv * g[c] + bta[c];
    }
}

// ---------------- RoPE (in-place, one thread owns the rotation pair) -------
__global__ __launch_bounds__(256) void rope_kernel(float* __restrict__ x)
{
    const int idx = blockIdx.x * 256 + threadIdx.x;
    const int j = idx & 31;
    const int h = (idx >> 5) & 15;
    const int t = idx >> 9;
    const int s = t >> 2;

    const float inv_freq = powf(10000.f, -((float)(2*j)) * (1.f / HD_));
    float sn, c;
    sincosf((float)s * inv_freq, &sn, &c);

    float* base = x + (size_t)t * D_ + h * HD_;
    const float x1 = base[j];
    const float x2 = base[j + 32];
    base[j]      = x1 * c - x2 * sn;
    base[j + 32] = x2 * c + x1 * sn;
}

// ---------------- scores = scale * Q K^T, masked ---------------------------
__global__ __launch_bounds__(256) void qk_kernel(
    const float* __restrict__ q, const float* __restrict__ k,
    const int* __restrict__ mask, float* __restrict__ scores)
{
    const int bh = blockIdx.z;
    const int b = bh >> 4;
    const int h = bh & 15;
    const int qt = blockIdx.y * 64;
    const int kt = blockIdx.x * 64;

    __shared__ float Qs[HD_][65];
    __shared__ float Ks[HD_][65];

    const int tid = threadIdx.x;
    const int ty = tid >> 4, tx = tid & 15;
    const int lr = tid >> 4;
    const int lc = (tid & 15) * 4;

    #pragma unroll
    for (int it = 0; it < 4; it++) {
        const int m = lr + it*16;
        float4 a = *(const float4*)(q + ((size_t)(qt + m) * B_ + b) * D_ + h*HD_ + lc);
        Qs[lc+0][m]=a.x; Qs[lc+1][m]=a.y; Qs[lc+2][m]=a.z; Qs[lc+3][m]=a.w;
        float4 bb = *(const float4*)(k + ((size_t)(kt + m) * B_ + b) * D_ + h*HD_ + lc);
        Ks[lc+0][m]=bb.x; Ks[lc+1][m]=bb.y; Ks[lc+2][m]=bb.z; Ks[lc+3][m]=bb.w;
    }
    __syncthreads();

    float acc[4][4];
    #pragma unroll
    for (int i = 0; i < 4; i++)
        #pragma unroll
        for (int j = 0; j < 4; j++) acc[i][j] = 0.f;

    #pragma unroll
    for (int kk = 0; kk < HD_; kk++) {
        float av[4], bv[4];
        #pragma unroll
        for (int i = 0; i < 4; i++) av[i] = Qs[kk][ty*4 + i];
        #pragma unroll
        for (int j = 0; j < 4; j++) bv[j] = Ks[kk][tx*4 + j];
        #pragma unroll
        for (int i = 0; i < 4; i++)
            #pragma unroll
            for (int j = 0; j < 4; j++)
                acc[i][j] = fmaf(av[i], bv[j], acc[i][j]);
    }

    const float scale = 0.125f;
    #pragma unroll
    for (int i = 0; i < 4; i++) {
        const int qpos = qt + ty*4 + i;
        float* out = scores + ((size_t)bh * S_ + qpos) * S_;
        #pragma unroll
        for (int j = 0; j < 4; j++) {
            const int kpos = kt + tx*4 + j;
            float vsc = acc[i][j] * scale;
            if (mask[b * S_ + kpos] != 0) vsc = -1e30f;
            out[kpos] = vsc;
        }
    }
}

// ---------------- row softmax over 512 keys --------------------------------
__global__ __launch_bounds__(128) void softmax_kernel(float* __restrict__ scores)
{
    const size_t row = blockIdx.x;
    float* p = scores + row * S_;
    const int tid = threadIdx.x;

    float vals[4];
    float m = -3.0e38f;
    #pragma unroll
    for (int i = 0; i < 4; i++) { vals[i] = p[tid + i*128]; m = fmaxf(m, vals[i]); }
    #pragma unroll
    for (int o = 16; o; o >>= 1) m = fmaxf(m, __shfl_xor_sync(0xffffffffu, m, o));
    __shared__ float sm[4], ssum[4];
    if ((tid & 31) == 0) sm[tid >> 5] = m;
    __syncthreads();
    m = fmaxf(fmaxf(sm[0], sm[1]), fmaxf(sm[2], sm[3]));

    float s = 0.f;
    #pragma unroll
    for (int i = 0; i < 4; i++) { vals[i] = __expf(vals[i] - m); s += vals[i]; }
    #pragma unroll
    for (int o = 16; o; o >>= 1) s += __shfl_xor_sync(0xffffffffu, s, o);
    if ((tid & 31) == 0) ssum[tid >> 5] = s;
    __syncthreads();
    const float inv = 1.f / (ssum[0] + ssum[1] + ssum[2] + ssum[3]);

    #pragma unroll
    for (int i = 0; i < 4; i++) p[tid + i*128] = vals[i] * inv;
}

// ---------------- attn = probs @ V, scattered to [t, d] layout -------------
__global__ __launch_bounds__(256) void pv_kernel(
    const float* __restrict__ scores, const float* __restrict__ v,
    float* __restrict__ attn)
{
    const int bh = blockIdx.z;
    const int b = bh >> 4, h = bh & 15;
    const int qt = blockIdx.y * 64;

    __shared__ float Ps[32][65];
    __shared__ float Vs[32][64];

    const int tid = threadIdx.x;
    const int ty = tid >> 4, tx = tid & 15;
    const int pr = tid >> 3;
    const int pc = (tid & 7) * 4;
    const int vr = tid >> 4;
    const int vc = (tid & 15) * 4;

    float acc[4][4];
    #pragma unroll
    for (int i = 0; i < 4; i++)
        #pragma unroll
        for (int j = 0; j < 4; j++) acc[i][j] = 0.f;

    for (int kt = 0; kt < S_; kt += 32) {
        #pragma unroll
        for (int it = 0; it < 2; it++) {
            const int m = pr + it*32;
            float4 a = *(const float4*)(scores + ((size_t)bh*S_ + qt + m)*S_ + kt + pc);
            Ps[pc+0][m]=a.x; Ps[pc+1][m]=a.y; Ps[pc+2][m]=a.z; Ps[pc+3][m]=a.w;
        }
        #pragma unroll
        for (int it = 0; it < 2; it++) {
            const int kr = vr + it*16;
            float4 bb = *(const float4*)(v + ((size_t)(kt + kr)*B_ + b)*D_ + h*HD_ + vc);
            *(float4*)&Vs[kr][vc] = bb;
        }
        __syncthreads();

        #pragma unroll
        for (int kk = 0; kk < 32; kk++) {
            float av[4], bv[4];
            #pragma unroll
            for (int i = 0; i < 4; i++) av[i] = Ps[kk][ty*4 + i];
            #pragma unroll
            for (int j = 0; j < 4; j++) bv[j] = Vs[kk][tx*4 + j];
            #pragma unroll
            for (int i = 0; i < 4; i++)
                #pragma unroll
                for (int j = 0; j < 4; j++)
                    acc[i][j] = fmaf(av[i], bv[j], acc[i][j]);
        }
        __syncthreads();
    }

    #pragma unroll
    for (int i = 0; i < 4; i++) {
        const int qpos = qt + ty*4 + i;
        float* orow = attn + ((size_t)qpos * B_ + b) * D_ + h*HD_;
        #pragma unroll
        for (int j = 0; j < 4; j++)
            orow[tx*4 + j] = acc[i][j];
    }
}

// ---------------- host orchestration ---------------------------------------
extern "C" void kernel_launch(void* const* d_in, const int* in_sizes, int n_in,
                              void* d_out, int out_size)
{
    (void)in_sizes; (void)n_in; (void)out_size;

    const float* segments  = (const float*)d_in[0];
    const float* durations = (const float*)d_in[1];
    const int*   padmask   = (const int*)d_in[2];   // bool promoted to int32
    const float* Wproj = (const float*)d_in[3];
    const float* bproj = (const float*)d_in[4];
    const float* Wdur  = (const float*)d_in[5];
    const float* bdur  = (const float*)d_in[6];
    const float* ln1_g = (const float*)d_in[7];
    const float* ln1_b = (const float*)d_in[8];
    const float* Wq = (const float*)d_in[9];
    const float* bq = (const float*)d_in[10];
    const float* Wk = (const float*)d_in[11];
    const float* bk = (const float*)d_in[12];
    const float* Wv = (const float*)d_in[13];
    const float* bv = (const float*)d_in[14];
    const float* Wo = (const float*)d_in[15];
    const float* bo = (const float*)d_in[16];
    const float* ln2_g = (const float*)d_in[17];
    const float* ln2_b = (const float*)d_in[18];
    const float* Wff1 = (const float*)d_in[19];
    const float* bff1 = (const float*)d_in[20];
    const float* Wff2 = (const float*)d_in[21];
    const float* bff2 = (const float*)d_in[22];

    float* x = (float*)d_out;

    float *h, *q, *k, *v, *attn, *ff, *scores;
    cudaGetSymbolAddress((void**)&h,      g_h);
    cudaGetSymbolAddress((void**)&q,      g_q);
    cudaGetSymbolAddress((void**)&k,      g_k);
    cudaGetSymbolAddress((void**)&v,      g_v);
    cudaGetSymbolAddress((void**)&attn,   g_attn);
    cudaGetSymbolAddress((void**)&ff,     g_ff);
    cudaGetSymbolAddress((void**)&scores, g_scores);

    cudaFuncSetAttribute(gemm_tc,
        cudaFuncAttributeMaxDynamicSharedMemorySize, SMEM_BYTES);

    const dim3 blk(256);

    // x = segments @ Wproj + bproj + durations*Wdur + bdur
    gemm_tc<<<dim3(D_/TBN, T_/TBM), blk, SMEM_BYTES>>>(
        segments, Wproj, bproj, bdur, durations, Wdur, nullptr,
        x, T_, D_, DIN_, 0);

    for (int l = 0; l < L_; l++) {
        const float* wq = Wq + (size_t)l*D_*D_;
        const float* wk = Wk + (size_t)l*D_*D_;
        const float* wv = Wv + (size_t)l*D_*D_;
        const float* wo = Wo + (size_t)l*D_*D_;
        const float* w1 = Wff1 + (size_t)l*D_*F_;
        const float* w2 = Wff2 + (size_t)l*F_*D_;

        ln_kernel<<<T_, 256>>>(x, ln1_g + l*D_, ln1_b + l*D_, h);

        gemm_tc<<<dim3(D_/TBN, T_/TBM), blk, SMEM_BYTES>>>(h, wq, bq + l*D_,
            nullptr, nullptr, nullptr, nullptr, q, T_, D_, D_, 0);
        gemm_tc<<<dim3(D_/TBN, T_/TBM), blk, SMEM_BYTES>>>(h, wk, bk + l*D_,
            nullptr, nullptr, nullptr, nullptr, k, T_, D_, D_, 0);
        gemm_tc<<<dim3(D_/TBN, T_/TBM), blk, SMEM_BYTES>>>(h, wv, bv + l*D_,
            nullptr, nullptr, nullptr, nullptr, v, T_, D_, D_, 0);

        rope_kernel<<<(T_*H_*32)/256, 256>>>(q);
        rope_kernel<<<(T_*H_*32)/256, 256>>>(k);

        qk_kernel<<<dim3(S_/64, S_/64, B_*H_), dim3(256)>>>(q, k, padmask, scores);
        softmax_kernel<<<B_*H_*S_, 128>>>(scores);
        pv_kernel<<<dim3(1, S_/64, B_*H_), dim3(256)>>>(scores, v, attn);

        // x = x + attn @ Wo + bo
        gemm_tc<<<dim3(D_/TBN, T_/TBM), blk, SMEM_BYTES>>>(attn, wo, bo + l*D_,
            nullptr, nullptr, nullptr, x, x, T_, D_, D_, 0);

        ln_kernel<<<T_, 256>>>(x, ln2_g + l*D_, ln2_b + l*D_, h);

        // ff = gelu(h @ W1 + b1)
        gemm_tc<<<dim3(F_/TBN, T_/TBM), blk, SMEM_BYTES>>>(h, w1, bff1 + l*F_,
            nullptr, nullptr, nullptr, nullptr, ff, T_, F_, D_, 1);

        // x = x + ff @ W2 + b2
        gemm_tc<<<dim3(D_/TBN, T_/TBM), blk, SMEM_BYTES>>>(ff, w2, bff2 + l*D_,
            nullptr, nullptr, nullptr, x, x, T_, D_, F_, 0);
    }
}

// round 12
// speedup vs baseline: 1.0469x; 1.0469x over previous
#include <cuda_runtime.h>
#include <math.h>
#include <stdint.h>

#define L_   12
#define S_   512
#define B_   4
#define DIN_ 768
#define D_   1024
#define H_   16
#define F_   4096
#define HD_  64
#define T_   (S_*B_)   // 2048 tokens

// ---------------- scratch (static device globals; no runtime allocation) ----
__device__ float g_q[T_*D_];
__device__ float g_k[T_*D_];
__device__ float g_v[T_*D_];
__device__ float g_x_never[1]; // placeholder
__device__ float g_scores[(size_t)B_*H_*S_*S_];   // 67 MB

// frag-major bf16x2 hi/lo activation buffers (u32 count = element count)
__device__ unsigned g_segf[T_*DIN_];
__device__ unsigned g_hf[T_*D_];
__device__ unsigned g_attnf[T_*D_];
__device__ unsigned g_fff[(size_t)T_*F_];

// packed k-pair bf16x2 hi/lo weight planes ([layer][2 planes][K/2][N] u32)
__device__ unsigned g_wprojp[DIN_*D_];
__device__ unsigned g_wqp[(size_t)L_*D_*D_];
__device__ unsigned g_wkp[(size_t)L_*D_*D_];
__device__ unsigned g_wvp[(size_t)L_*D_*D_];
__device__ unsigned g_wop[(size_t)L_*D_*D_];
__device__ unsigned g_w1p[(size_t)L_*D_*F_];
__device__ unsigned g_w2p[(size_t)L_*F_*D_];

// ---------------- bf16 split helpers ---------------------------------------
__device__ __forceinline__ unsigned pack_bf16(float x0, float x1) {
    unsigned u;
    asm("cvt.rn.bf16x2.f32 %0, %1, %2;" : "=r"(u) : "f"(x1), "f"(x0));
    return u;
}
// pack pair {low=a, high=b}; hi/lo split
__device__ __forceinline__ void splitp_bf16(float a, float b, unsigned& h, unsigned& l)
{
    h = pack_bf16(a, b);
    const float ha = __uint_as_float(h << 16);
    const float hb = __uint_as_float(h & 0xffff0000u);
    l = pack_bf16(a - ha, b - hb);
}

__device__ __forceinline__ void mma_bf16(float c[4],
    unsigned a0, unsigned a1, unsigned a2, unsigned a3,
    unsigned b0, unsigned b1)
{
    asm volatile(
        "mma.sync.aligned.m16n8k16.row.col.f32.bf16.bf16.f32 "
        "{%0,%1,%2,%3}, {%4,%5,%6,%7}, {%8,%9}, {%0,%1,%2,%3};"
        : "+f"(c[0]), "+f"(c[1]), "+f"(c[2]), "+f"(c[3])
        : "r"(a0), "r"(a1), "r"(a2), "r"(a3), "r"(b0), "r"(b1));
}

__device__ __forceinline__ void cp16(uint32_t dst, const void* src) {
    asm volatile("cp.async.cg.shared.global [%0], [%1], 16;"
                 :: "r"(dst), "l"(src) : "memory");
}
#define CP_COMMIT() asm volatile("cp.async.commit_group;" ::: "memory")
#define CP_WAIT1()  asm volatile("cp.async.wait_group 1;" ::: "memory")
#define CP_WAIT0()  asm volatile("cp.async.wait_group 0;" ::: "memory")

// A-frag index helper: element (row r, k-pair p) of a matrix with KT k-tiles
// -> u32 index (((gmt*KT + kt)*4 + step*2 + hl)*128 + lane*4 + reg); hl adds +128
__device__ __forceinline__ size_t afr_index(int r, int p, int KT) {
    const int gmt = r >> 4, rr = r & 15;
    const int kt = p >> 4, step = (p >> 3) & 1, pp = p & 7;
    const int lane = (rr & 7) * 4 + (pp & 3);
    const int reg  = (rr >> 3) + ((pp >> 2) << 1);
    return (((size_t)gmt * KT + kt) * 4 + step * 2) * 128 + lane * 4 + reg;
}

// ---------------- prep: weight pack ([K][N] -> 2 planes [K/2][N] u32) ------
__global__ void wsplit(const float* __restrict__ in, unsigned* __restrict__ out,
                       int K, int N)
{
    const size_t half = (size_t)(K / 2) * N;
    in  += (size_t)blockIdx.z * K * N;
    out += (size_t)blockIdx.z * K * N;
    for (size_t idx = blockIdx.x * 256 + threadIdx.x; idx < half;
         idx += (size_t)gridDim.x * 256) {
        const int p = (int)(idx / N), n = (int)(idx % N);
        unsigned h, l;
        splitp_bf16(in[(size_t)(2 * p) * N + n], in[(size_t)(2 * p + 1) * N + n], h, l);
        out[idx] = h;
        out[half + idx] = l;
    }
}

// ---------------- prep: segments -> frag-major -----------------------------
__global__ void asplit(const float* __restrict__ in, unsigned* __restrict__ out,
                       int K)   // rows = T_
{
    const int KP = K / 2, KT = K / 32;
    const int total = T_ * KP;
    for (int idx = blockIdx.x * 256 + threadIdx.x; idx < total;
         idx += gridDim.x * 256) {
        const int t = idx / KP, p = idx % KP;
        unsigned h, l;
        splitp_bf16(in[(size_t)t * K + 2 * p], in[(size_t)t * K + 2 * p + 1], h, l);
        const size_t o = afr_index(t, p, KT);
        out[o] = h;
        out[o + 128] = l;
    }
}

// ---------------- tensor-core GEMM (bf16 3-term, cp.async 3-stage) ---------
// C[M,N] = A@W + bias + bias2 + rowvec*colvec; GELU; residual
// A: frag-major hi/lo u32; B: packed k-pair planes. BM=128,BN=128,TBK=32.
#define TBM 128
#define TBN 128
#define B_STU 136
#define AFRAG_U 4096
#define OFF_B 4096
#define STAGE_U (AFRAG_U + 2*16*B_STU)   // 8448
#define NSTAGE 3
#define SMEM_BYTES (NSTAGE*STAGE_U*4)    // 101376

__global__ __launch_bounds__(256, 1) void gemm_tc(
    const unsigned* __restrict__ Afr, const unsigned* __restrict__ Bp,
    const float* __restrict__ bias, const float* __restrict__ bias2,
    const float* __restrict__ rowvec, const float* __restrict__ colvec,
    const float* __restrict__ residual,
    float* __restrict__ C, unsigned* __restrict__ Cfr,
    int M, int N, int K, int gelu_flag)
{
    extern __shared__ unsigned smbuf[];
    const uint32_t smu = (uint32_t)__cvta_generic_to_shared(smbuf);

    const int tid  = threadIdx.x;
    const int warp = tid >> 5;
    const int lane = tid & 31;
    const int g    = lane >> 2;
    const int tig  = lane & 3;
    const int wmt  = (warp >> 2) * 4;
    const int wm   = wmt * 16;
    const int wn   = (warp & 3) * 32;

    const int row0 = blockIdx.y * TBM;
    const int col0 = blockIdx.x * TBN;
    const int KT   = K >> 5;
    const int gmt0 = row0 >> 4;
    const size_t bplane = (size_t)(K >> 1) * N;

    // stage loader: pure cp.async (A frag blocks + B rows)
    auto issue = [&](int kt, int stg) {
        const uint32_t base = smu + stg * STAGE_U * 4;
        #pragma unroll
        for (int u = 0; u < 4; u++) {
            const int s = tid + u * 256;          // 0..1023
            const int f = s >> 5;                 // frag block 0..31
            const int w16 = s & 31;
            const int mt8 = f >> 2, rem = f & 3;  // rem = step*2+hl
            const unsigned* src = Afr +
                ((((size_t)(gmt0 + mt8) * KT + kt) * 4 + rem) * 128) + w16 * 4;
            cp16(base + (f * 128 + w16 * 4) * 4, src);
        }
        #pragma unroll
        for (int u = 0; u < 4; u++) {
            const int s = tid + u * 256;          // 0..1023
            const int hl = s >> 9, rem = s & 511;
            const int p = rem >> 5, w16 = rem & 31;
            const unsigned* src = Bp + (size_t)hl * bplane +
                (size_t)(kt * 16 + p) * N + col0 + w16 * 4;
            cp16(base + (OFF_B + hl * 16 * B_STU + p * B_STU + w16 * 4) * 4, src);
        }
        CP_COMMIT();
    };

    float acc[4][4][4];
    #pragma unroll
    for (int mt = 0; mt < 4; mt++)
        #pragma unroll
        for (int nt = 0; nt < 4; nt++)
            #pragma unroll
            for (int r = 0; r < 4; r++) acc[mt][nt][r] = 0.f;

    const int nk = KT;
    issue(0, 0);
    issue(1, 1);

    for (int ki = 0; ki < nk; ki++) {
        if (ki + 1 < nk) { CP_WAIT1(); } else { CP_WAIT0(); }
        __syncthreads();
        if (ki + 2 < nk) issue(ki + 2, (ki + 2) % NSTAGE);

        const unsigned* cur = smbuf + (ki % NSTAGE) * STAGE_U;
        const unsigned* Bh = cur + OFF_B;
        const unsigned* Bl = cur + OFF_B + 16 * B_STU;
        #pragma unroll
        for (int st = 0; st < 2; st++) {
            const int pb = st * 8;
            unsigned ah[4][4], al[4][4];
            #pragma unroll
            for (int mt = 0; mt < 4; mt++) {
                const int f = ((wmt + mt) * 2 + st) * 2;
                uint4 av = *(const uint4*)&cur[f * 128 + lane * 4];
                ah[mt][0] = av.x; ah[mt][1] = av.y; ah[mt][2] = av.z; ah[mt][3] = av.w;
                uint4 lv = *(const uint4*)&cur[(f + 1) * 128 + lane * 4];
                al[mt][0] = lv.x; al[mt][1] = lv.y; al[mt][2] = lv.z; al[mt][3] = lv.w;
            }
            unsigned bh[4][2], bl[4][2];
            #pragma unroll
            for (int nt = 0; nt < 4; nt++) {
                const int n = wn + nt * 8 + g;
                const int c0i = (pb + tig) * B_STU + n;
                const int c1i = (pb + tig + 4) * B_STU + n;
                bh[nt][0] = Bh[c0i]; bh[nt][1] = Bh[c1i];
                bl[nt][0] = Bl[c0i]; bl[nt][1] = Bl[c1i];
            }
            #pragma unroll
            for (int mt = 0; mt < 4; mt++)
                #pragma unroll
                for (int nt = 0; nt < 4; nt++) {
                    mma_bf16(acc[mt][nt], ah[mt][0], ah[mt][1], ah[mt][2], ah[mt][3],
                             bh[nt][0], bh[nt][1]);
                    mma_bf16(acc[mt][nt], al[mt][0], al[mt][1], al[mt][2], al[mt][3],
                             bh[nt][0], bh[nt][1]);
                    mma_bf16(acc[mt][nt], ah[mt][0], ah[mt][1], ah[mt][2], ah[mt][3],
                             bl[nt][0], bl[nt][1]);
                }
        }
    }
    __syncthreads();

    // ---- epilogue
    const int KTo = N >> 5;
    #pragma unroll
    for (int mt = 0; mt < 4; mt++) {
        #pragma unroll
        for (int half = 0; half < 2; half++) {
            const int r = row0 + wm + mt * 16 + g + half * 8;
            const float rv = rowvec ? rowvec[r] : 0.f;
            #pragma unroll
            for (int nt = 0; nt < 4; nt++) {
                const int c = col0 + wn + nt * 8 + 2 * tig;
                float v0 = acc[mt][nt][half * 2 + 0];
                float v1 = acc[mt][nt][half * 2 + 1];
                if (bias)  { v0 += bias[c];  v1 += bias[c + 1]; }
                if (bias2) { v0 += bias2[c]; v1 += bias2[c + 1]; }
                if (rowvec) { v0 += rv * colvec[c]; v1 += rv * colvec[c + 1]; }
                if (gelu_flag) {
                    v0 = 0.5f * v0 * (1.f + erff(v0 * 0.70710678118654752f));
                    v1 = 0.5f * v1 * (1.f + erff(v1 * 0.70710678118654752f));
                }
                if (residual) {
                    float2 rr = *(const float2*)(residual + (size_t)r * N + c);
                    v0 += rr.x; v1 += rr.y;
                }
                if (Cfr) {
                    unsigned h, l;
                    splitp_bf16(v0, v1, h, l);
                    const size_t o = afr_index(r, c >> 1, KTo);
                    Cfr[o] = h;
                    Cfr[o + 128] = l;
                } else {
                    float2 o; o.x = v0; o.y = v1;
                    *(float2*)(C + (size_t)r * N + c) = o;
                }
            }
        }
    }
}

// ---------------- LayerNorm: one block per token, frag-major split out -----
__global__ __launch_bounds__(256) void ln_kernel(
    const float* __restrict__ x, const float* __restrict__ g,
    const float* __restrict__ bta, unsigned* __restrict__ outf)
{
    const int t = blockIdx.x;
    const int tid = threadIdx.x;
    const float* xr = x + (size_t)t * D_;
    const int c4 = tid * 4;

    float4 v = *(const float4*)(xr + c4);
    float s  = v.x + v.y + v.z + v.w;
    float s2 = v.x*v.x + v.y*v.y + v.z*v.z + v.w*v.w;
    #pragma unroll
    for (int o = 16; o; o >>= 1) {
        s  += __shfl_xor_sync(0xffffffffu, s,  o);
        s2 += __shfl_xor_sync(0xffffffffu, s2, o);
    }
    __shared__ float ss[8], ss2[8];
    if ((tid & 31) == 0) { ss[tid >> 5] = s; ss2[tid >> 5] = s2; }
    __syncthreads();
    s = 0.f; s2 = 0.f;
    #pragma unroll
    for (int w = 0; w < 8; w++) { s += ss[w]; s2 += ss2[w]; }

    const float mean = s * (1.f / D_);
    const float var  = s2 * (1.f / D_) - mean * mean;
    const float inv  = rsqrtf(var + 1e-5f);

    const float4 gg = *(const float4*)(g + c4);
    const float4 bb = *(const float4*)(bta + c4);
    const float y0 = (v.x - mean) * inv * gg.x + bb.x;
    const float y1 = (v.y - mean) * inv * gg.y + bb.y;
    const float y2 = (v.z - mean) * inv * gg.z + bb.z;
    const float y3 = (v.w - mean) * inv * gg.w + bb.w;

    unsigned h, l;
    splitp_bf16(y0, y1, h, l);
    size_t o = afr_index(t, c4 >> 1, D_ / 32);
    outf[o] = h; outf[o + 128] = l;
    splitp_bf16(y2, y3, h, l);
    o = afr_index(t, (c4 >> 1) + 1, D_ / 32);
    outf[o] = h; outf[o + 128] = l;
}

// ---------------- RoPE (in-place, fp32 q/k) --------------------------------
__global__ __launch_bounds__(256) void rope_kernel(float* __restrict__ x)
{
    const int idx = blockIdx.x * 256 + threadIdx.x;
    const int j = idx & 31;
    const int h = (idx >> 5) & 15;
    const int t = idx >> 9;
    const int s = t >> 2;

    const float inv_freq = powf(10000.f, -((float)(2*j)) * (1.f / HD_));
    float sn, c;
    sincosf((float)s * inv_freq, &sn, &c);

    float* base = x + (size_t)t * D_ + h * HD_;
    const float x1 = base[j];
    const float x2 = base[j + 32];
    base[j]      = x1 * c - x2 * sn;
    base[j + 32] = x2 * c + x1 * sn;
}

// ---------------- scores = scale * Q K^T, masked ---------------------------
__global__ __launch_bounds__(256) void qk_kernel(
    const float* __restrict__ q, const float* __restrict__ k,
    const int* __restrict__ mask, float* __restrict__ scores)
{
    const int bh = blockIdx.z;
    const int b = bh >> 4;
    const int h = bh & 15;
    const int qt = blockIdx.y * 64;
    const int kt = blockIdx.x * 64;

    __shared__ float Qs[HD_][65];
    __shared__ float Ks[HD_][65];

    const int tid = threadIdx.x;
    const int ty = tid >> 4, tx = tid & 15;
    const int lr = tid >> 4;
    const int lc = (tid & 15) * 4;

    #pragma unroll
    for (int it = 0; it < 4; it++) {
        const int m = lr + it*16;
        float4 a = *(const float4*)(q + ((size_t)(qt + m) * B_ + b) * D_ + h*HD_ + lc);
        Qs[lc+0][m]=a.x; Qs[lc+1][m]=a.y; Qs[lc+2][m]=a.z; Qs[lc+3][m]=a.w;
        float4 bb = *(const float4*)(k + ((size_t)(kt + m) * B_ + b) * D_ + h*HD_ + lc);
        Ks[lc+0][m]=bb.x; Ks[lc+1][m]=bb.y; Ks[lc+2][m]=bb.z; Ks[lc+3][m]=bb.w;
    }
    __syncthreads();

    float acc[4][4];
    #pragma unroll
    for (int i = 0; i < 4; i++)
        #pragma unroll
        for (int j = 0; j < 4; j++) acc[i][j] = 0.f;

    #pragma unroll
    for (int kk = 0; kk < HD_; kk++) {
        float av[4], bv[4];
        #pragma unroll
        for (int i = 0; i < 4; i++) av[i] = Qs[kk][ty*4 + i];
        #pragma unroll
        for (int j = 0; j < 4; j++) bv[j] = Ks[kk][tx*4 + j];
        #pragma unroll
        for (int i = 0; i < 4; i++)
            #pragma unroll
            for (int j = 0; j < 4; j++)
                acc[i][j] = fmaf(av[i], bv[j], acc[i][j]);
    }

    const float scale = 0.125f;
    #pragma unroll
    for (int i = 0; i < 4; i++) {
        const int qpos = qt + ty*4 + i;
        float* out = scores + ((size_t)bh * S_ + qpos) * S_;
        #pragma unroll
        for (int j = 0; j < 4; j++) {
            const int kpos = kt + tx*4 + j;
            float vsc = acc[i][j] * scale;
            if (mask[b * S_ + kpos] != 0) vsc = -1e30f;
            out[kpos] = vsc;
        }
    }
}

// ---------------- row softmax over 512 keys --------------------------------
__global__ __launch_bounds__(128) void softmax_kernel(float* __restrict__ scores)
{
    const size_t row = blockIdx.x;
    float* p = scores + row * S_;
    const int tid = threadIdx.x;

    float vals[4];
    float m = -3.0e38f;
    #pragma unroll
    for (int i = 0; i < 4; i++) { vals[i] = p[tid + i*128]; m = fmaxf(m, vals[i]); }
    #pragma unroll
    for (int o = 16; o; o >>= 1) m = fmaxf(m, __shfl_xor_sync(0xffffffffu, m, o));
    __shared__ float sm[4], ssum[4];
    if ((tid & 31) == 0) sm[tid >> 5] = m;
    __syncthreads();
    m = fmaxf(fmaxf(sm[0], sm[1]), fmaxf(sm[2], sm[3]));

    float s = 0.f;
    #pragma unroll
    for (int i = 0; i < 4; i++) { vals[i] = __expf(vals[i] - m); s += vals[i]; }
    #pragma unroll
    for (int o = 16; o; o >>= 1) s += __shfl_xor_sync(0xffffffffu, s, o);
    if ((tid & 31) == 0) ssum[tid >> 5] = s;
    __syncthreads();
    const float inv = 1.f / (ssum[0] + ssum[1] + ssum[2] + ssum[3]);

    #pragma unroll
    for (int i = 0; i < 4; i++) p[tid + i*128] = vals[i] * inv;
}

// ---------------- attn = probs @ V, frag-major split scatter ---------------
__global__ __launch_bounds__(256) void pv_kernel(
    const float* __restrict__ scores, const float* __restrict__ v,
    unsigned* __restrict__ attnf)
{
    const int bh = blockIdx.z;
    const int b = bh >> 4, h = bh & 15;
    const int qt = blockIdx.y * 64;

    __shared__ float Ps[32][65];
    __shared__ float Vs[32][64];

    const int tid = threadIdx.x;
    const int ty = tid >> 4, tx = tid & 15;
    const int pr = tid >> 3;
    const int pc = (tid & 7) * 4;
    const int vr = tid >> 4;
    const int vc = (tid & 15) * 4;

    float acc[4][4];
    #pragma unroll
    for (int i = 0; i < 4; i++)
        #pragma unroll
        for (int j = 0; j < 4; j++) acc[i][j] = 0.f;

    for (int kt = 0; kt < S_; kt += 32) {
        #pragma unroll
        for (int it = 0; it < 2; it++) {
            const int m = pr + it*32;
            float4 a = *(const float4*)(scores + ((size_t)bh*S_ + qt + m)*S_ + kt + pc);
            Ps[pc+0][m]=a.x; Ps[pc+1][m]=a.y; Ps[pc+2][m]=a.z; Ps[pc+3][m]=a.w;
        }
        #pragma unroll
        for (int it = 0; it < 2; it++) {
            const int kr = vr + it*16;
            float4 bb = *(const float4*)(v + ((size_t)(kt + kr)*B_ + b)*D_ + h*HD_ + vc);
            *(float4*)&Vs[kr][vc] = bb;
        }
        __syncthreads();

        #pragma unroll
        for (int kk = 0; kk < 32; kk++) {
            float av[4], bv[4];
            #pragma unroll
            for (int i = 0; i < 4; i++) av[i] = Ps[kk][ty*4 + i];
            #pragma unroll
            for (int j = 0; j < 4; j++) bv[j] = Vs[kk][tx*4 + j];
            #pragma unroll
            for (int i = 0; i < 4; i++)
                #pragma unroll
                for (int j = 0; j < 4; j++)
                    acc[i][j] = fmaf(av[i], bv[j], acc[i][j]);
        }
        __syncthreads();
    }

    #pragma unroll
    for (int i = 0; i < 4; i++) {
        const int qpos = qt + ty*4 + i;
        const int t = qpos * B_ + b;
        const int c0 = h * HD_ + tx * 4;     // even
        unsigned hh, ll;
        splitp_bf16(acc[i][0], acc[i][1], hh, ll);
        size_t o = afr_index(t, c0 >> 1, D_ / 32);
        attnf[o] = hh; attnf[o + 128] = ll;
        splitp_bf16(acc[i][2], acc[i][3], hh, ll);
        o = afr_index(t, (c0 >> 1) + 1, D_ / 32);
        attnf[o] = hh; attnf[o + 128] = ll;
    }
}

// ---------------- host orchestration ---------------------------------------
extern "C" void kernel_launch(void* const* d_in, const int* in_sizes, int n_in,
                              void* d_out, int out_size)
{
    (void)in_sizes; (void)n_in; (void)out_size;

    const float* segments  = (const float*)d_in[0];
    const float* durations = (const float*)d_in[1];
    const int*   padmask   = (const int*)d_in[2];
    const float* Wproj = (const float*)d_in[3];
    const float* bproj = (const float*)d_in[4];
    const float* Wdur  = (const float*)d_in[5];
    const float* bdur  = (const float*)d_in[6];
    const float* ln1_g = (const float*)d_in[7];
    const float* ln1_b = (const float*)d_in[8];
    const float* Wq = (const float*)d_in[9];
    const float* bq = (const float*)d_in[10];
    const float* Wk = (const float*)d_in[11];
    const float* bk = (const float*)d_in[12];
    const float* Wv = (const float*)d_in[13];
    const float* bv = (const float*)d_in[14];
    const float* Wo = (const float*)d_in[15];
    const float* bo = (const float*)d_in[16];
    const float* ln2_g = (const float*)d_in[17];
    const float* ln2_b = (const float*)d_in[18];
    const float* Wff1 = (const float*)d_in[19];
    const float* bff1 = (const float*)d_in[20];
    const float* Wff2 = (const float*)d_in[21];
    const float* bff2 = (const float*)d_in[22];

    float* x = (float*)d_out;

    float *q, *k, *v, *scores;
    unsigned *segf, *hf, *attnf, *fff;
    unsigned *wprojp, *wqp, *wkp, *wvp, *wop, *w1p, *w2p;
    cudaGetSymbolAddress((void**)&q,      g_q);
    cudaGetSymbolAddress((void**)&k,      g_k);
    cudaGetSymbolAddress((void**)&v,      g_v);
    cudaGetSymbolAddress((void**)&scores, g_scores);
    cudaGetSymbolAddress((void**)&segf,   g_segf);
    cudaGetSymbolAddress((void**)&hf,     g_hf);
    cudaGetSymbolAddress((void**)&attnf,  g_attnf);
    cudaGetSymbolAddress((void**)&fff,    g_fff);
    cudaGetSymbolAddress((void**)&wprojp, g_wprojp);
    cudaGetSymbolAddress((void**)&wqp,    g_wqp);
    cudaGetSymbolAddress((void**)&wkp,    g_wkp);
    cudaGetSymbolAddress((void**)&wvp,    g_wvp);
    cudaGetSymbolAddress((void**)&wop,    g_wop);
    cudaGetSymbolAddress((void**)&w1p,    g_w1p);
    cudaGetSymbolAddress((void**)&w2p,    g_w2p);

    cudaFuncSetAttribute(gemm_tc,
        cudaFuncAttributeMaxDynamicSharedMemorySize, SMEM_BYTES);

    // ---- prep pass
    asplit<<<1184, 256>>>(segments, segf, DIN_);
    wsplit<<<dim3(1184, 1, 1),  256>>>(Wproj, wprojp, DIN_, D_);
    wsplit<<<dim3(256, 1, L_),  256>>>(Wq, wqp, D_, D_);
    wsplit<<<dim3(256, 1, L_),  256>>>(Wk, wkp, D_, D_);
    wsplit<<<dim3(256, 1, L_),  256>>>(Wv, wvp, D_, D_);
    wsplit<<<dim3(256, 1, L_),  256>>>(Wo, wop, D_, D_);
    wsplit<<<dim3(1024, 1, L_), 256>>>(Wff1, w1p, D_, F_);
    wsplit<<<dim3(1024, 1, L_), 256>>>(Wff2, w2p, F_, D_);

    const dim3 blk(256);

    // proj: x = segments @ Wproj + bproj + durations*Wdur + bdur
    gemm_tc<<<dim3(D_/TBN, T_/TBM), blk, SMEM_BYTES>>>(
        segf, wprojp, bproj, bdur, durations, Wdur, nullptr,
        x, nullptr, T_, D_, DIN_, 0);

    for (int l = 0; l < L_; l++) {
        const size_t od = (size_t)l*D_*D_;
        const size_t o1 = (size_t)l*D_*F_;
        const size_t o2 = (size_t)l*F_*D_;

        ln_kernel<<<T_, 256>>>(x, ln1_g + l*D_, ln1_b + l*D_, hf);

        gemm_tc<<<dim3(D_/TBN, T_/TBM), blk, SMEM_BYTES>>>(
            hf, wqp + od, bq + l*D_, nullptr, nullptr, nullptr, nullptr,
            q, nullptr, T_, D_, D_, 0);
        gemm_tc<<<dim3(D_/TBN, T_/TBM), blk, SMEM_BYTES>>>(
            hf, wkp + od, bk + l*D_, nullptr, nullptr, nullptr, nullptr,
            k, nullptr, T_, D_, D_, 0);
        gemm_tc<<<dim3(D_/TBN, T_/TBM), blk, SMEM_BYTES>>>(
            hf, wvp + od, bv + l*D_, nullptr, nullptr, nullptr, nullptr,
            v, nullptr, T_, D_, D_, 0);

        rope_kernel<<<(T_*H_*32)/256, 256>>>(q);
        rope_kernel<<<(T_*H_*32)/256, 256>>>(k);

        qk_kernel<<<dim3(S_/64, S_/64, B_*H_), dim3(256)>>>(q, k, padmask, scores);
        softmax_kernel<<<B_*H_*S_, 128>>>(scores);
        pv_kernel<<<dim3(1, S_/64, B_*H_), dim3(256)>>>(scores, v, attnf);

        // x = x + attn @ Wo + bo
        gemm_tc<<<dim3(D_/TBN, T_/TBM), blk, SMEM_BYTES>>>(
            attnf, wop + od, bo + l*D_, nullptr, nullptr, nullptr, x,
            x, nullptr, T_, D_, D_, 0);

        ln_kernel<<<T_, 256>>>(x, ln2_g + l*D_, ln2_b + l*D_, hf);

        // ff = gelu(h @ W1 + b1), frag-major output
        gemm_tc<<<dim3(F_/TBN, T_/TBM), blk, SMEM_BYTES>>>(
            hf, w1p + o1, bff1 + l*F_, nullptr, nullptr, nullptr, nullptr,
            nullptr, fff, T_, F_, D_, 1);

        // x = x + ff @ W2 + b2
        gemm_tc<<<dim3(D_/TBN, T_/TBM), blk, SMEM_BYTES>>>(
            fff, w2p + o2, bff2 + l*D_, nullptr, nullptr, nullptr, x,
            x, nullptr, T_, D_, F_, 0);
    }
}

// round 13
// speedup vs baseline: 1.1068x; 1.0572x over previous
#include <cuda_runtime.h>
#include <math.h>
#include <stdint.h>

#define L_   12
#define S_   512
#define B_   4
#define DIN_ 768
#define D_   1024
#define H_   16
#define F_   4096
#define HD_  64
#define T_   (S_*B_)   // 2048 tokens

// ---------------- scratch (static device globals; no runtime allocation) ----
__device__ float g_q[T_*D_];
__device__ float g_k[T_*D_];
__device__ float g_v[T_*D_];

// frag-major bf16x2 hi/lo activation buffers
__device__ unsigned g_segf[T_*DIN_];
__device__ unsigned g_hf[T_*D_];
__device__ unsigned g_attnf[T_*D_];
__device__ unsigned g_fff[(size_t)T_*F_];

// packed k-pair bf16x2 hi/lo weight planes ([layer][2 planes][K/2][N] u32)
__device__ unsigned g_wprojp[DIN_*D_];
__device__ unsigned g_wqp[(size_t)L_*D_*D_];
__device__ unsigned g_wkp[(size_t)L_*D_*D_];
__device__ unsigned g_wvp[(size_t)L_*D_*D_];
__device__ unsigned g_wop[(size_t)L_*D_*D_];
__device__ unsigned g_w1p[(size_t)L_*D_*F_];
__device__ unsigned g_w2p[(size_t)L_*F_*D_];

// ---------------- bf16 split helpers ---------------------------------------
__device__ __forceinline__ unsigned pack_bf16(float x0, float x1) {
    unsigned u;
    asm("cvt.rn.bf16x2.f32 %0, %1, %2;" : "=r"(u) : "f"(x1), "f"(x0));
    return u;
}
__device__ __forceinline__ void splitp_bf16(float a, float b, unsigned& h, unsigned& l)
{
    h = pack_bf16(a, b);
    const float ha = __uint_as_float(h << 16);
    const float hb = __uint_as_float(h & 0xffff0000u);
    l = pack_bf16(a - ha, b - hb);
}

__device__ __forceinline__ void mma_bf16(float c[4],
    unsigned a0, unsigned a1, unsigned a2, unsigned a3,
    unsigned b0, unsigned b1)
{
    asm volatile(
        "mma.sync.aligned.m16n8k16.row.col.f32.bf16.bf16.f32 "
        "{%0,%1,%2,%3}, {%4,%5,%6,%7}, {%8,%9}, {%0,%1,%2,%3};"
        : "+f"(c[0]), "+f"(c[1]), "+f"(c[2]), "+f"(c[3])
        : "r"(a0), "r"(a1), "r"(a2), "r"(a3), "r"(b0), "r"(b1));
}

__device__ __forceinline__ void cp16(uint32_t dst, const void* src) {
    asm volatile("cp.async.cg.shared.global [%0], [%1], 16;"
                 :: "r"(dst), "l"(src) : "memory");
}
#define CP_COMMIT() asm volatile("cp.async.commit_group;" ::: "memory")
#define CP_WAIT1()  asm volatile("cp.async.wait_group 1;" ::: "memory")
#define CP_WAIT0()  asm volatile("cp.async.wait_group 0;" ::: "memory")

// A-frag index: element (row r, k-pair p), KT = K/32 k-tiles
__device__ __forceinline__ size_t afr_index(int r, int p, int KT) {
    const int gmt = r >> 4, rr = r & 15;
    const int kt = p >> 4, step = (p >> 3) & 1, pp = p & 7;
    const int lane = (rr & 7) * 4 + (pp & 3);
    const int reg  = (rr >> 3) + ((pp >> 2) << 1);
    return (((size_t)gmt * KT + kt) * 4 + step * 2) * 128 + lane * 4 + reg;
}

// ---------------- prep kernels ----------------------------------------------
__global__ void wsplit(const float* __restrict__ in, unsigned* __restrict__ out,
                       int K, int N)
{
    const size_t half = (size_t)(K / 2) * N;
    in  += (size_t)blockIdx.z * K * N;
    out += (size_t)blockIdx.z * K * N;
    for (size_t idx = blockIdx.x * 256 + threadIdx.x; idx < half;
         idx += (size_t)gridDim.x * 256) {
        const int p = (int)(idx / N), n = (int)(idx % N);
        unsigned h, l;
        splitp_bf16(in[(size_t)(2 * p) * N + n], in[(size_t)(2 * p + 1) * N + n], h, l);
        out[idx] = h;
        out[half + idx] = l;
    }
}

__global__ void asplit(const float* __restrict__ in, unsigned* __restrict__ out,
                       int K)
{
    const int KP = K / 2, KT = K / 32;
    const int total = T_ * KP;
    for (int idx = blockIdx.x * 256 + threadIdx.x; idx < total;
         idx += gridDim.x * 256) {
        const int t = idx / KP, p = idx % KP;
        unsigned h, l;
        splitp_bf16(in[(size_t)t * K + 2 * p], in[(size_t)t * K + 2 * p + 1], h, l);
        const size_t o = afr_index(t, p, KT);
        out[o] = h;
        out[o + 128] = l;
    }
}

// ---------------- tensor-core GEMM (bf16 3-term, cp.async, seg-select) -----
#define TBM 128
#define TBN 128
#define B_STU 136
#define AFRAG_U 4096
#define OFF_B 4096
#define STAGE_U (AFRAG_U + 2*16*B_STU)   // 8448
#define NSTAGE 3
#define SMEM_BYTES (NSTAGE*STAGE_U*4)    // 101376

__global__ __launch_bounds__(256, 1) void gemm_tc(
    const unsigned* __restrict__ Afr,
    const unsigned* __restrict__ Bp0, const unsigned* __restrict__ Bp1,
    const unsigned* __restrict__ Bp2,
    const float* __restrict__ bias0s, const float* __restrict__ bias1s,
    const float* __restrict__ bias2s,
    const float* __restrict__ biasadd,
    const float* __restrict__ rowvec, const float* __restrict__ colvec,
    const float* __restrict__ residual,
    float* __restrict__ C0, float* __restrict__ C1, float* __restrict__ C2,
    unsigned* __restrict__ Cfr,
    int M, int N, int K, int gelu_flag)
{
    extern __shared__ unsigned smbuf[];
    const uint32_t smu = (uint32_t)__cvta_generic_to_shared(smbuf);

    const int tid  = threadIdx.x;
    const int warp = tid >> 5;
    const int lane = tid & 31;
    const int g    = lane >> 2;
    const int tig  = lane & 3;
    const int wmt  = (warp >> 2) * 4;
    const int wm   = wmt * 16;
    const int wn   = (warp & 3) * 32;

    const int nxb  = N / TBN;
    const int seg  = blockIdx.x / nxb;
    const int col0 = (blockIdx.x - seg * nxb) * TBN;
    const int row0 = blockIdx.y * TBM;
    const int KT   = K >> 5;
    const int gmt0 = row0 >> 4;
    const size_t bplane = (size_t)(K >> 1) * N;

    const unsigned* Bp = (seg == 0) ? Bp0 : (seg == 1) ? Bp1 : Bp2;
    const float* bias  = (seg == 0) ? bias0s : (seg == 1) ? bias1s : bias2s;
    float* Cg          = (seg == 0) ? C0 : (seg == 1) ? C1 : C2;

    auto issue = [&](int kt, int stg) {
        const uint32_t base = smu + stg * STAGE_U * 4;
        #pragma unroll
        for (int u = 0; u < 4; u++) {
            const int s = tid + u * 256;
            const int f = s >> 5;
            const int w16 = s & 31;
            const int mt8 = f >> 2, rem = f & 3;
            const unsigned* src = Afr +
                ((((size_t)(gmt0 + mt8) * KT + kt) * 4 + rem) * 128) + w16 * 4;
            cp16(base + (f * 128 + w16 * 4) * 4, src);
        }
        #pragma unroll
        for (int u = 0; u < 4; u++) {
            const int s = tid + u * 256;
            const int hl = s >> 9, rem = s & 511;
            const int p = rem >> 5, w16 = rem & 31;
            const unsigned* src = Bp + (size_t)hl * bplane +
                (size_t)(kt * 16 + p) * N + col0 + w16 * 4;
            cp16(base + (OFF_B + hl * 16 * B_STU + p * B_STU + w16 * 4) * 4, src);
        }
        CP_COMMIT();
    };

    float acc[4][4][4];
    #pragma unroll
    for (int mt = 0; mt < 4; mt++)
        #pragma unroll
        for (int nt = 0; nt < 4; nt++)
            #pragma unroll
            for (int r = 0; r < 4; r++) acc[mt][nt][r] = 0.f;

    const int nk = KT;
    issue(0, 0);
    issue(1, 1);

    for (int ki = 0; ki < nk; ki++) {
        if (ki + 1 < nk) { CP_WAIT1(); } else { CP_WAIT0(); }
        __syncthreads();
        if (ki + 2 < nk) issue(ki + 2, (ki + 2) % NSTAGE);

        const unsigned* cur = smbuf + (ki % NSTAGE) * STAGE_U;
        const unsigned* Bh = cur + OFF_B;
        const unsigned* Bl = cur + OFF_B + 16 * B_STU;
        #pragma unroll
        for (int st = 0; st < 2; st++) {
            const int pb = st * 8;
            unsigned ah[4][4], al[4][4];
            #pragma unroll
            for (int mt = 0; mt < 4; mt++) {
                const int f = ((wmt + mt) * 2 + st) * 2;
                uint4 av = *(const uint4*)&cur[f * 128 + lane * 4];
                ah[mt][0] = av.x; ah[mt][1] = av.y; ah[mt][2] = av.z; ah[mt][3] = av.w;
                uint4 lv = *(const uint4*)&cur[(f + 1) * 128 + lane * 4];
                al[mt][0] = lv.x; al[mt][1] = lv.y; al[mt][2] = lv.z; al[mt][3] = lv.w;
            }
            unsigned bh[4][2], bl[4][2];
            #pragma unroll
            for (int nt = 0; nt < 4; nt++) {
                const int n = wn + nt * 8 + g;
                const int c0i = (pb + tig) * B_STU + n;
                const int c1i = (pb + tig + 4) * B_STU + n;
                bh[nt][0] = Bh[c0i]; bh[nt][1] = Bh[c1i];
                bl[nt][0] = Bl[c0i]; bl[nt][1] = Bl[c1i];
            }
            #pragma unroll
            for (int mt = 0; mt < 4; mt++)
                #pragma unroll
                for (int nt = 0; nt < 4; nt++) {
                    mma_bf16(acc[mt][nt], ah[mt][0], ah[mt][1], ah[mt][2], ah[mt][3],
                             bh[nt][0], bh[nt][1]);
                    mma_bf16(acc[mt][nt], al[mt][0], al[mt][1], al[mt][2], al[mt][3],
                             bh[nt][0], bh[nt][1]);
                    mma_bf16(acc[mt][nt], ah[mt][0], ah[mt][1], ah[mt][2], ah[mt][3],
                             bl[nt][0], bl[nt][1]);
                }
        }
    }
    __syncthreads();

    // ---- epilogue
    const int KTo = N >> 5;
    #pragma unroll
    for (int mt = 0; mt < 4; mt++) {
        #pragma unroll
        for (int half = 0; half < 2; half++) {
            const int r = row0 + wm + mt * 16 + g + half * 8;
            const float rv = rowvec ? rowvec[r] : 0.f;
            #pragma unroll
            for (int nt = 0; nt < 4; nt++) {
                const int c = col0 + wn + nt * 8 + 2 * tig;
                float v0 = acc[mt][nt][half * 2 + 0];
                float v1 = acc[mt][nt][half * 2 + 1];
                if (bias)    { v0 += bias[c];    v1 += bias[c + 1]; }
                if (biasadd) { v0 += biasadd[c]; v1 += biasadd[c + 1]; }
                if (rowvec)  { v0 += rv * colvec[c]; v1 += rv * colvec[c + 1]; }
                if (gelu_flag) {
                    v0 = 0.5f * v0 * (1.f + erff(v0 * 0.70710678118654752f));
                    v1 = 0.5f * v1 * (1.f + erff(v1 * 0.70710678118654752f));
                }
                if (residual) {
                    float2 rr = *(const float2*)(residual + (size_t)r * N + c);
                    v0 += rr.x; v1 += rr.y;
                }
                if (Cfr) {
                    unsigned h, l;
                    splitp_bf16(v0, v1, h, l);
                    const size_t o = afr_index(r, c >> 1, KTo);
                    Cfr[o] = h;
                    Cfr[o + 128] = l;
                } else {
                    float2 o; o.x = v0; o.y = v1;
                    *(float2*)(Cg + (size_t)r * N + c) = o;
                }
            }
        }
    }
}

// ---------------- LayerNorm: one block per token, frag-major split out -----
__global__ __launch_bounds__(256) void ln_kernel(
    const float* __restrict__ x, const float* __restrict__ g,
    const float* __restrict__ bta, unsigned* __restrict__ outf)
{
    const int t = blockIdx.x;
    const int tid = threadIdx.x;
    const float* xr = x + (size_t)t * D_;
    const int c4 = tid * 4;

    float4 v = *(const float4*)(xr + c4);
    float s  = v.x + v.y + v.z + v.w;
    float s2 = v.x*v.x + v.y*v.y + v.z*v.z + v.w*v.w;
    #pragma unroll
    for (int o = 16; o; o >>= 1) {
        s  += __shfl_xor_sync(0xffffffffu, s,  o);
        s2 += __shfl_xor_sync(0xffffffffu, s2, o);
    }
    __shared__ float ss[8], ss2[8];
    if ((tid & 31) == 0) { ss[tid >> 5] = s; ss2[tid >> 5] = s2; }
    __syncthreads();
    s = 0.f; s2 = 0.f;
    #pragma unroll
    for (int w = 0; w < 8; w++) { s += ss[w]; s2 += ss2[w]; }

    const float mean = s * (1.f / D_);
    const float var  = s2 * (1.f / D_) - mean * mean;
    const float inv  = rsqrtf(var + 1e-5f);

    const float4 gg = *(const float4*)(g + c4);
    const float4 bb = *(const float4*)(bta + c4);
    const float y0 = (v.x - mean) * inv * gg.x + bb.x;
    const float y1 = (v.y - mean) * inv * gg.y + bb.y;
    const float y2 = (v.z - mean) * inv * gg.z + bb.z;
    const float y3 = (v.w - mean) * inv * gg.w + bb.w;

    unsigned h, l;
    splitp_bf16(y0, y1, h, l);
    size_t o = afr_index(t, c4 >> 1, D_ / 32);
    outf[o] = h; outf[o + 128] = l;
    splitp_bf16(y2, y3, h, l);
    o = afr_index(t, (c4 >> 1) + 1, D_ / 32);
    outf[o] = h; outf[o + 128] = l;
}

// ---------------- RoPE (in-place, fp32 q/k) --------------------------------
__global__ __launch_bounds__(256) void rope_kernel(float* __restrict__ x)
{
    const int idx = blockIdx.x * 256 + threadIdx.x;
    const int j = idx & 31;
    const int h = (idx >> 5) & 15;
    const int t = idx >> 9;
    const int s = t >> 2;

    const float inv_freq = powf(10000.f, -((float)(2*j)) * (1.f / HD_));
    float sn, c;
    sincosf((float)s * inv_freq, &sn, &c);

    float* base = x + (size_t)t * D_ + h * HD_;
    const float x1 = base[j];
    const float x2 = base[j + 32];
    base[j]      = x1 * c - x2 * sn;
    base[j + 32] = x2 * c + x1 * sn;
}

// ---------------- fused flash attention ------------------------------------
// grid (S/64, B*H), block 256. Per block: q-tile of 64 rows, all 512 keys in
// 8 tiles of 64. Online softmax. Output written frag-major (attnf).
// smem: Qs[64][65], Ks[64][65], Ps[64][65], Vs[64][68]
#define FL_QS 0
#define FL_KS (64*65)
#define FL_PS (2*64*65)
#define FL_VS (3*64*65)
#define FLASH_FLOATS (3*64*65 + 64*68)
#define FLASH_SMEM (FLASH_FLOATS*4)   // 67,392 B

__global__ __launch_bounds__(256) void flash_kernel(
    const float* __restrict__ q, const float* __restrict__ k,
    const float* __restrict__ v, const int* __restrict__ mask,
    unsigned* __restrict__ attnf)
{
    extern __shared__ float fsm[];
    float* Qs = fsm + FL_QS;
    float* Ks = fsm + FL_KS;
    float* Ps = fsm + FL_PS;
    float* Vs = fsm + FL_VS;

    const int bh = blockIdx.y;
    const int b = bh >> 4, h = bh & 15;
    const int qt = blockIdx.x * 64;

    const int tid = threadIdx.x;
    const int ty = tid >> 4, tx = tid & 15;
    const int lr = tid >> 4;           // 0..15
    const int lc = (tid & 15) * 4;

    // load Q tile (transposed: Qs[k][m])
    #pragma unroll
    for (int it = 0; it < 4; it++) {
        const int m = lr + it * 16;
        float4 a = *(const float4*)(q + ((size_t)(qt + m) * B_ + b) * D_ + h*HD_ + lc);
        Qs[(lc+0)*65 + m] = a.x; Qs[(lc+1)*65 + m] = a.y;
        Qs[(lc+2)*65 + m] = a.z; Qs[(lc+3)*65 + m] = a.w;
    }

    float mrow[4], sумD[4], acc_o[4][4];
    #pragma unroll
    for (int i = 0; i < 4; i++) {
        mrow[i] = -3.0e38f; sумD[i] = 0.f;
        #pragma unroll
        for (int j = 0; j < 4; j++) acc_o[i][j] = 0.f;
    }

    const float scale = 0.125f;  // 1/sqrt(64)
    const int msk[4] = {
        mask[b*S_ + 0], 0, 0, 0 };  // placeholder unused
    (void)msk;

    for (int kt = 0; kt < S_; kt += 64) {
        // load K tile (transposed) + V tile
        #pragma unroll
        for (int it = 0; it < 4; it++) {
            const int m = lr + it * 16;
            float4 kk4 = *(const float4*)(k + ((size_t)(kt + m) * B_ + b) * D_ + h*HD_ + lc);
            Ks[(lc+0)*65 + m] = kk4.x; Ks[(lc+1)*65 + m] = kk4.y;
            Ks[(lc+2)*65 + m] = kk4.z; Ks[(lc+3)*65 + m] = kk4.w;
            float4 vv4 = *(const float4*)(v + ((size_t)(kt + m) * B_ + b) * D_ + h*HD_ + lc);
            *(float4*)&Vs[m*68 + lc] = vv4;
        }
        __syncthreads();

        // S = scale * Q K^T for this tile (4x4 per thread)
        float sacc[4][4];
        #pragma unroll
        for (int i = 0; i < 4; i++)
            #pragma unroll
            for (int j = 0; j < 4; j++) sacc[i][j] = 0.f;
        #pragma unroll 16
        for (int kk = 0; kk < HD_; kk++) {
            float av[4], bv[4];
            #pragma unroll
            for (int i = 0; i < 4; i++) av[i] = Qs[kk*65 + ty*4 + i];
            #pragma unroll
            for (int j = 0; j < 4; j++) bv[j] = Ks[kk*65 + tx*4 + j];
            #pragma unroll
            for (int i = 0; i < 4; i++)
                #pragma unroll
                for (int j = 0; j < 4; j++)
                    sacc[i][j] = fmaf(av[i], bv[j], sacc[i][j]);
        }
        // mask + scale
        #pragma unroll
        for (int j = 0; j < 4; j++) {
            const int kpos = kt + tx*4 + j;
            const bool masked = (mask[b*S_ + kpos] != 0);
            #pragma unroll
            for (int i = 0; i < 4; i++) {
                float sv = sacc[i][j] * scale;
                sacc[i][j] = masked ? -1e30f : sv;
            }
        }
        // online softmax update per row (reduce across tx: 16 lanes)
        #pragma unroll
        for (int i = 0; i < 4; i++) {
            float rmax = fmaxf(fmaxf(sacc[i][0], sacc[i][1]),
                               fmaxf(sacc[i][2], sacc[i][3]));
            #pragma unroll
            for (int o = 8; o; o >>= 1)
                rmax = fmaxf(rmax, __shfl_xor_sync(0xffffffffu, rmax, o));
            const float mnew = fmaxf(mrow[i], rmax);
            const float corr = __expf(mrow[i] - mnew);
            float rsum = 0.f;
            #pragma unroll
            for (int j = 0; j < 4; j++) {
                const float p = __expf(sacc[i][j] - mnew);
                sacc[i][j] = p;
                rsum += p;
            }
            #pragma unroll
            for (int o = 8; o; o >>= 1)
                rsum += __shfl_xor_sync(0xffffffffu, rsum, o);
            mrow[i] = mnew;
            sумD[i] = sумD[i] * corr + rsum;
            #pragma unroll
            for (int j = 0; j < 4; j++) acc_o[i][j] *= corr;
        }
        // write P transposed: Ps[kcol][row]
        #pragma unroll
        for (int i = 0; i < 4; i++)
            #pragma unroll
            for (int j = 0; j < 4; j++)
                Ps[(tx*4 + j)*65 + ty*4 + i] = sacc[i][j];
        __syncthreads();

        // O += P V (4x4 per thread)
        #pragma unroll 16
        for (int kk = 0; kk < 64; kk++) {
            float pv[4], vv[4];
            #pragma unroll
            for (int i = 0; i < 4; i++) pv[i] = Ps[kk*65 + ty*4 + i];
            #pragma unroll
            for (int j = 0; j < 4; j++) vv[j] = Vs[kk*68 + tx*4 + j];
            #pragma unroll
            for (int i = 0; i < 4; i++)
                #pragma unroll
                for (int j = 0; j < 4; j++)
                    acc_o[i][j] = fmaf(pv[i], vv[j], acc_o[i][j]);
        }
        __syncthreads();
    }

    // normalize + frag-major split scatter
    #pragma unroll
    for (int i = 0; i < 4; i++) {
        const float inv = 1.f / sумD[i];
        const int qpos = qt + ty*4 + i;
        const int t = qpos * B_ + b;
        const int c0 = h * HD_ + tx * 4;
        unsigned hh, ll;
        splitp_bf16(acc_o[i][0] * inv, acc_o[i][1] * inv, hh, ll);
        size_t o = afr_index(t, c0 >> 1, D_ / 32);
        attnf[o] = hh; attnf[o + 128] = ll;
        splitp_bf16(acc_o[i][2] * inv, acc_o[i][3] * inv, hh, ll);
        o = afr_index(t, (c0 >> 1) + 1, D_ / 32);
        attnf[o] = hh; attnf[o + 128] = ll;
    }
}

// ---------------- host orchestration ---------------------------------------
extern "C" void kernel_launch(void* const* d_in, const int* in_sizes, int n_in,
                              void* d_out, int out_size)
{
    (void)in_sizes; (void)n_in; (void)out_size;

    const float* segments  = (const float*)d_in[0];
    const float* durations = (const float*)d_in[1];
    const int*   padmask   = (const int*)d_in[2];
    const float* Wproj = (const float*)d_in[3];
    const float* bproj = (const float*)d_in[4];
    const float* Wdur  = (const float*)d_in[5];
    const float* bdur  = (const float*)d_in[6];
    const float* ln1_g = (const float*)d_in[7];
    const float* ln1_b = (const float*)d_in[8];
    const float* Wq = (const float*)d_in[9];
    const float* bq = (const float*)d_in[10];
    const float* Wk = (const float*)d_in[11];
    const float* bk = (const float*)d_in[12];
    const float* Wv = (const float*)d_in[13];
    const float* bv = (const float*)d_in[14];
    const float* Wo = (const float*)d_in[15];
    const float* bo = (const float*)d_in[16];
    const float* ln2_g = (const float*)d_in[17];
    const float* ln2_b = (const float*)d_in[18];
    const float* Wff1 = (const float*)d_in[19];
    const float* bff1 = (const float*)d_in[20];
    const float* Wff2 = (const float*)d_in[21];
    const float* bff2 = (const float*)d_in[22];

    float* x = (float*)d_out;

    float *q, *k, *v;
    unsigned *segf, *hf, *attnf, *fff;
    unsigned *wprojp, *wqp, *wkp, *wvp, *wop, *w1p, *w2p;
    cudaGetSymbolAddress((void**)&q,      g_q);
    cudaGetSymbolAddress((void**)&k,      g_k);
    cudaGetSymbolAddress((void**)&v,      g_v);
    cudaGetSymbolAddress((void**)&segf,   g_segf);
    cudaGetSymbolAddress((void**)&hf,     g_hf);
    cudaGetSymbolAddress((void**)&attnf,  g_attnf);
    cudaGetSymbolAddress((void**)&fff,    g_fff);
    cudaGetSymbolAddress((void**)&wprojp, g_wprojp);
    cudaGetSymbolAddress((void**)&wqp,    g_wqp);
    cudaGetSymbolAddress((void**)&wkp,    g_wkp);
    cudaGetSymbolAddress((void**)&wvp,    g_wvp);
    cudaGetSymbolAddress((void**)&wop,    g_wop);
    cudaGetSymbolAddress((void**)&w1p,    g_w1p);
    cudaGetSymbolAddress((void**)&w2p,    g_w2p);

    cudaFuncSetAttribute(gemm_tc,
        cudaFuncAttributeMaxDynamicSharedMemorySize, SMEM_BYTES);
    cudaFuncSetAttribute(flash_kernel,
        cudaFuncAttributeMaxDynamicSharedMemorySize, FLASH_SMEM);

    // ---- prep pass
    asplit<<<1184, 256>>>(segments, segf, DIN_);
    wsplit<<<dim3(1184, 1, 1),  256>>>(Wproj, wprojp, DIN_, D_);
    wsplit<<<dim3(256, 1, L_),  256>>>(Wq, wqp, D_, D_);
    wsplit<<<dim3(256, 1, L_),  256>>>(Wk, wkp, D_, D_);
    wsplit<<<dim3(256, 1, L_),  256>>>(Wv, wvp, D_, D_);
    wsplit<<<dim3(256, 1, L_),  256>>>(Wo, wop, D_, D_);
    wsplit<<<dim3(1024, 1, L_), 256>>>(Wff1, w1p, D_, F_);
    wsplit<<<dim3(1024, 1, L_), 256>>>(Wff2, w2p, F_, D_);

    const dim3 blk(256);

    // proj: x = segments @ Wproj + bproj + durations*Wdur + bdur
    gemm_tc<<<dim3(D_/TBN, T_/TBM), blk, SMEM_BYTES>>>(
        segf, wprojp, wprojp, wprojp, bproj, bproj, bproj, bdur,
        durations, Wdur, nullptr,
        x, x, x, nullptr, T_, D_, DIN_, 0);

    for (int l = 0; l < L_; l++) {
        const size_t od = (size_t)l*D_*D_;
        const size_t o1 = (size_t)l*D_*F_;
        const size_t o2 = (size_t)l*F_*D_;

        ln_kernel<<<T_, 256>>>(x, ln1_g + l*D_, ln1_b + l*D_, hf);

        // fused QKV: 3 segments, grid 24 x 16 = 384 CTAs
        gemm_tc<<<dim3(3*D_/TBN, T_/TBM), blk, SMEM_BYTES>>>(
            hf, wqp + od, wkp + od, wvp + od,
            bq + l*D_, bk + l*D_, bv + l*D_, nullptr,
            nullptr, nullptr, nullptr,
            q, k, v, nullptr, T_, D_, D_, 0);

        rope_kernel<<<(T_*H_*32)/256, 256>>>(q);
        rope_kernel<<<(T_*H_*32)/256, 256>>>(k);

        flash_kernel<<<dim3(S_/64, B_*H_), blk, FLASH_SMEM>>>(
            q, k, v, padmask, attnf);

        // x = x + attn @ Wo + bo
        gemm_tc<<<dim3(D_/TBN, T_/TBM), blk, SMEM_BYTES>>>(
            attnf, wop + od, wop + od, wop + od,
            bo + l*D_, bo + l*D_, bo + l*D_, nullptr,
            nullptr, nullptr, x,
            x, x, x, nullptr, T_, D_, D_, 0);

        ln_kernel<<<T_, 256>>>(x, ln2_g + l*D_, ln2_b + l*D_, hf);

        // ff = gelu(h @ W1 + b1), frag-major output
        gemm_tc<<<dim3(F_/TBN, T_/TBM), blk, SMEM_BYTES>>>(
            hf, w1p + o1, w1p + o1, w1p + o1,
            bff1 + l*F_, bff1 + l*F_, bff1 + l*F_, nullptr,
            nullptr, nullptr, nullptr,
            nullptr, nullptr, nullptr, fff, T_, F_, D_, 1);

        // x = x + ff @ W2 + b2
        gemm_tc<<<dim3(D_/TBN, T_/TBM), blk, SMEM_BYTES>>>(
            fff, w2p + o2, w2p + o2, w2p + o2,
            bff2 + l*D_, bff2 + l*D_, bff2 + l*D_, nullptr,
            nullptr, nullptr, x,
            x, x, x, nullptr, T_, D_, F_, 0);
    }
}

// round 14
// speedup vs baseline: 1.1326x; 1.0233x over previous
#include <cuda_runtime.h>
#include <math.h>
#include <stdint.h>

#define L_   12
#define S_   512
#define B_   4
#define DIN_ 768
#define D_   1024
#define H_   16
#define F_   4096
#define HD_  64
#define T_   (S_*B_)   // 2048 tokens

// ---------------- scratch (static device globals; no runtime allocation) ----
__device__ float g_q[T_*D_];
__device__ float g_k[T_*D_];
__device__ float g_v[T_*D_];

// frag-major bf16x2 hi/lo activation buffers
__device__ unsigned g_segf[T_*DIN_];
__device__ unsigned g_hf[T_*D_];
__device__ unsigned g_attnf[T_*D_];
__device__ unsigned g_fff[(size_t)T_*F_];

// packed k-pair bf16x2 hi/lo weight planes ([layer][2 planes][K/2][N] u32)
__device__ unsigned g_wprojp[DIN_*D_];
__device__ unsigned g_wqp[(size_t)L_*D_*D_];
__device__ unsigned g_wkp[(size_t)L_*D_*D_];
__device__ unsigned g_wvp[(size_t)L_*D_*D_];
__device__ unsigned g_wop[(size_t)L_*D_*D_];
__device__ unsigned g_w1p[(size_t)L_*D_*F_];
__device__ unsigned g_w2p[(size_t)L_*F_*D_];

// ---------------- bf16 split helpers ---------------------------------------
__device__ __forceinline__ unsigned pack_bf16(float x0, float x1) {
    unsigned u;
    asm("cvt.rn.bf16x2.f32 %0, %1, %2;" : "=r"(u) : "f"(x1), "f"(x0));
    return u;
}
__device__ __forceinline__ void splitp_bf16(float a, float b, unsigned& h, unsigned& l)
{
    h = pack_bf16(a, b);
    const float ha = __uint_as_float(h << 16);
    const float hb = __uint_as_float(h & 0xffff0000u);
    l = pack_bf16(a - ha, b - hb);
}

__device__ __forceinline__ void mma_bf16(float c[4],
    unsigned a0, unsigned a1, unsigned a2, unsigned a3,
    unsigned b0, unsigned b1)
{
    asm volatile(
        "mma.sync.aligned.m16n8k16.row.col.f32.bf16.bf16.f32 "
        "{%0,%1,%2,%3}, {%4,%5,%6,%7}, {%8,%9}, {%0,%1,%2,%3};"
        : "+f"(c[0]), "+f"(c[1]), "+f"(c[2]), "+f"(c[3])
        : "r"(a0), "r"(a1), "r"(a2), "r"(a3), "r"(b0), "r"(b1));
}

__device__ __forceinline__ void cp16(uint32_t dst, const void* src) {
    asm volatile("cp.async.cg.shared.global [%0], [%1], 16;"
                 :: "r"(dst), "l"(src) : "memory");
}
#define CP_COMMIT() asm volatile("cp.async.commit_group;" ::: "memory")
#define CP_WAIT1()  asm volatile("cp.async.wait_group 1;" ::: "memory")
#define CP_WAIT0()  asm volatile("cp.async.wait_group 0;" ::: "memory")

// A-frag index: element (row r, k-pair p), KT = K/32 k-tiles (granularity 32)
__device__ __forceinline__ size_t afr_index(int r, int p, int KT) {
    const int gmt = r >> 4, rr = r & 15;
    const int kt = p >> 4, step = (p >> 3) & 1, pp = p & 7;
    const int lane = (rr & 7) * 4 + (pp & 3);
    const int reg  = (rr >> 3) + ((pp >> 2) << 1);
    return (((size_t)gmt * KT + kt) * 4 + step * 2) * 128 + lane * 4 + reg;
}

// ---------------- prep kernels ----------------------------------------------
__global__ void wsplit(const float* __restrict__ in, unsigned* __restrict__ out,
                       int K, int N)
{
    const size_t half = (size_t)(K / 2) * N;
    in  += (size_t)blockIdx.z * K * N;
    out += (size_t)blockIdx.z * K * N;
    for (size_t idx = blockIdx.x * 256 + threadIdx.x; idx < half;
         idx += (size_t)gridDim.x * 256) {
        const int p = (int)(idx / N), n = (int)(idx % N);
        unsigned h, l;
        splitp_bf16(in[(size_t)(2 * p) * N + n], in[(size_t)(2 * p + 1) * N + n], h, l);
        out[idx] = h;
        out[half + idx] = l;
    }
}

__global__ void asplit(const float* __restrict__ in, unsigned* __restrict__ out,
                       int K)
{
    const int KP = K / 2, KT = K / 32;
    const int total = T_ * KP;
    for (int idx = blockIdx.x * 256 + threadIdx.x; idx < total;
         idx += gridDim.x * 256) {
        const int t = idx / KP, p = idx % KP;
        unsigned h, l;
        splitp_bf16(in[(size_t)t * K + 2 * p], in[(size_t)t * K + 2 * p + 1], h, l);
        const size_t o = afr_index(t, p, KT);
        out[o] = h;
        out[o + 128] = l;
    }
}

// ---------------- tensor-core GEMM (bf16 3-term, TBK=64, 3-stage) ----------
#define TBM 128
#define TBN 128
#define B_STU 136
#define AFRAG_U 8192                     // A per stage: 64 frag blocks x 128
#define OFF_B 8192
#define STAGE_U (AFRAG_U + 2*32*B_STU)   // 16896
#define NSTAGE 3
#define SMEM_BYTES (NSTAGE*STAGE_U*4)    // 202752

__global__ __launch_bounds__(256, 1) void gemm_tc(
    const unsigned* __restrict__ Afr,
    const unsigned* __restrict__ Bp0, const unsigned* __restrict__ Bp1,
    const unsigned* __restrict__ Bp2,
    const float* __restrict__ bias0s, const float* __restrict__ bias1s,
    const float* __restrict__ bias2s,
    const float* __restrict__ biasadd,
    const float* __restrict__ rowvec, const float* __restrict__ colvec,
    const float* __restrict__ residual,
    float* __restrict__ C0, float* __restrict__ C1, float* __restrict__ C2,
    unsigned* __restrict__ Cfr,
    int M, int N, int K, int gelu_flag)
{
    extern __shared__ unsigned smbuf[];
    const uint32_t smu = (uint32_t)__cvta_generic_to_shared(smbuf);

    const int tid  = threadIdx.x;
    const int warp = tid >> 5;
    const int lane = tid & 31;
    const int g    = lane >> 2;
    const int tig  = lane & 3;
    const int wmt  = (warp >> 2) * 4;
    const int wm   = wmt * 16;
    const int wn   = (warp & 3) * 32;

    const int nxb  = N / TBN;
    const int seg  = blockIdx.x / nxb;
    const int col0 = (blockIdx.x - seg * nxb) * TBN;
    const int row0 = blockIdx.y * TBM;
    const int KT   = K >> 5;             // kt blocks of 32
    const int gmt0 = row0 >> 4;
    const size_t bplane = (size_t)(K >> 1) * N;

    const unsigned* Bp = (seg == 0) ? Bp0 : (seg == 1) ? Bp1 : Bp2;
    const float* bias  = (seg == 0) ? bias0s : (seg == 1) ? bias1s : bias2s;
    float* Cg          = (seg == 0) ? C0 : (seg == 1) ? C1 : C2;

    // stage covers 64 k (2 kt blocks); pure cp.async
    auto issue = [&](int kt2, int stg) {
        const uint32_t base = smu + stg * STAGE_U * 4;
        #pragma unroll
        for (int u = 0; u < 8; u++) {
            const int s = tid + u * 256;
            const int f = s >> 5, w16 = s & 31;
            const int mt8 = f >> 3, sub = f & 7;
            const int half = sub >> 2, rem = sub & 3;
            const unsigned* src = Afr +
                ((((size_t)(gmt0 + mt8) * KT + kt2 * 2 + half) * 4 + rem) * 128)
                + w16 * 4;
            cp16(base + (f * 128 + w16 * 4) * 4, src);
        }
        #pragma unroll
        for (int u = 0; u < 8; u++) {
            const int s = tid + u * 256;
            const int hl = s >> 10, rem = s & 1023;
            const int p = rem >> 5, w16 = rem & 31;
            const unsigned* src = Bp + (size_t)hl * bplane +
                (size_t)(kt2 * 32 + p) * N + col0 + w16 * 4;
            cp16(base + (OFF_B + hl * 32 * B_STU + p * B_STU + w16 * 4) * 4, src);
        }
        CP_COMMIT();
    };

    float acc[4][4][4];
    #pragma unroll
    for (int mt = 0; mt < 4; mt++)
        #pragma unroll
        for (int nt = 0; nt < 4; nt++)
            #pragma unroll
            for (int r = 0; r < 4; r++) acc[mt][nt][r] = 0.f;

    const int nk = K >> 6;
    issue(0, 0);
    issue(1, 1);

    for (int ki = 0; ki < nk; ki++) {
        if (ki + 1 < nk) { CP_WAIT1(); } else { CP_WAIT0(); }
        __syncthreads();
        if (ki + 2 < nk) issue(ki + 2, (ki + 2) % NSTAGE);

        const unsigned* cur = smbuf + (ki % NSTAGE) * STAGE_U;
        const unsigned* Bh = cur + OFF_B;
        const unsigned* Bl = cur + OFF_B + 32 * B_STU;
        #pragma unroll
        for (int half = 0; half < 2; half++) {
            #pragma unroll
            for (int st = 0; st < 2; st++) {
                const int pb = half * 16 + st * 8;
                unsigned ah[4][4], al[4][4];
                #pragma unroll
                for (int mt = 0; mt < 4; mt++) {
                    const int fb = (wmt + mt) * 8 + half * 4 + st * 2;
                    uint4 av = *(const uint4*)&cur[fb * 128 + lane * 4];
                    ah[mt][0] = av.x; ah[mt][1] = av.y; ah[mt][2] = av.z; ah[mt][3] = av.w;
                    uint4 lv = *(const uint4*)&cur[(fb + 1) * 128 + lane * 4];
                    al[mt][0] = lv.x; al[mt][1] = lv.y; al[mt][2] = lv.z; al[mt][3] = lv.w;
                }
                unsigned bh[4][2], bl[4][2];
                #pragma unroll
                for (int nt = 0; nt < 4; nt++) {
                    const int n = wn + nt * 8 + g;
                    const int c0i = (pb + tig) * B_STU + n;
                    const int c1i = (pb + tig + 4) * B_STU + n;
                    bh[nt][0] = Bh[c0i]; bh[nt][1] = Bh[c1i];
                    bl[nt][0] = Bl[c0i]; bl[nt][1] = Bl[c1i];
                }
                #pragma unroll
                for (int mt = 0; mt < 4; mt++)
                    #pragma unroll
                    for (int nt = 0; nt < 4; nt++) {
                        mma_bf16(acc[mt][nt], ah[mt][0], ah[mt][1], ah[mt][2], ah[mt][3],
                                 bh[nt][0], bh[nt][1]);
                        mma_bf16(acc[mt][nt], al[mt][0], al[mt][1], al[mt][2], al[mt][3],
                                 bh[nt][0], bh[nt][1]);
                        mma_bf16(acc[mt][nt], ah[mt][0], ah[mt][1], ah[mt][2], ah[mt][3],
                                 bl[nt][0], bl[nt][1]);
                    }
            }
        }
    }
    __syncthreads();

    // ---- epilogue
    const int KTo = N >> 5;
    #pragma unroll
    for (int mt = 0; mt < 4; mt++) {
        #pragma unroll
        for (int half = 0; half < 2; half++) {
            const int r = row0 + wm + mt * 16 + g + half * 8;
            const float rv = rowvec ? rowvec[r] : 0.f;
            #pragma unroll
            for (int nt = 0; nt < 4; nt++) {
                const int c = col0 + wn + nt * 8 + 2 * tig;
                float v0 = acc[mt][nt][half * 2 + 0];
                float v1 = acc[mt][nt][half * 2 + 1];
                if (bias)    { v0 += bias[c];    v1 += bias[c + 1]; }
                if (biasadd) { v0 += biasadd[c]; v1 += biasadd[c + 1]; }
                if (rowvec)  { v0 += rv * colvec[c]; v1 += rv * colvec[c + 1]; }
                if (gelu_flag) {
                    v0 = 0.5f * v0 * (1.f + erff(v0 * 0.70710678118654752f));
                    v1 = 0.5f * v1 * (1.f + erff(v1 * 0.70710678118654752f));
                }
                if (residual) {
                    float2 rr = *(const float2*)(residual + (size_t)r * N + c);
                    v0 += rr.x; v1 += rr.y;
                }
                if (Cfr) {
                    unsigned h, l;
                    splitp_bf16(v0, v1, h, l);
                    const size_t o = afr_index(r, c >> 1, KTo);
                    Cfr[o] = h;
                    Cfr[o + 128] = l;
                } else {
                    float2 o; o.x = v0; o.y = v1;
                    *(float2*)(Cg + (size_t)r * N + c) = o;
                }
            }
        }
    }
}

// ---------------- LayerNorm: one block per token, frag-major split out -----
__global__ __launch_bounds__(256) void ln_kernel(
    const float* __restrict__ x, const float* __restrict__ g,
    const float* __restrict__ bta, unsigned* __restrict__ outf)
{
    const int t = blockIdx.x;
    const int tid = threadIdx.x;
    const float* xr = x + (size_t)t * D_;
    const int c4 = tid * 4;

    float4 v = *(const float4*)(xr + c4);
    float s  = v.x + v.y + v.z + v.w;
    float s2 = v.x*v.x + v.y*v.y + v.z*v.z + v.w*v.w;
    #pragma unroll
    for (int o = 16; o; o >>= 1) {
        s  += __shfl_xor_sync(0xffffffffu, s,  o);
        s2 += __shfl_xor_sync(0xffffffffu, s2, o);
    }
    __shared__ float ss[8], ss2[8];
    if ((tid & 31) == 0) { ss[tid >> 5] = s; ss2[tid >> 5] = s2; }
    __syncthreads();
    s = 0.f; s2 = 0.f;
    #pragma unroll
    for (int w = 0; w < 8; w++) { s += ss[w]; s2 += ss2[w]; }

    const float mean = s * (1.f / D_);
    const float var  = s2 * (1.f / D_) - mean * mean;
    const float inv  = rsqrtf(var + 1e-5f);

    const float4 gg = *(const float4*)(g + c4);
    const float4 bb = *(const float4*)(bta + c4);
    const float y0 = (v.x - mean) * inv * gg.x + bb.x;
    const float y1 = (v.y - mean) * inv * gg.y + bb.y;
    const float y2 = (v.z - mean) * inv * gg.z + bb.z;
    const float y3 = (v.w - mean) * inv * gg.w + bb.w;

    unsigned h, l;
    splitp_bf16(y0, y1, h, l);
    size_t o = afr_index(t, c4 >> 1, D_ / 32);
    outf[o] = h; outf[o + 128] = l;
    splitp_bf16(y2, y3, h, l);
    o = afr_index(t, (c4 >> 1) + 1, D_ / 32);
    outf[o] = h; outf[o + 128] = l;
}

// ---------------- fused flash attention with in-loader RoPE ----------------
// grid (S/64, B*H), block 256. Q/K tiles roped on load (same math as the old
// rope_kernel). Online softmax; output frag-major.
#define FL_QS 0
#define FL_KS (64*65)
#define FL_PS (2*64*65)
#define FL_VS (3*64*65)
#define FLASH_FLOATS (3*64*65 + 64*68)
#define FLASH_SMEM (FLASH_FLOATS*4)   // 67,392 B

__global__ __launch_bounds__(256) void flash_kernel(
    const float* __restrict__ q, const float* __restrict__ k,
    const float* __restrict__ v, const int* __restrict__ mask,
    unsigned* __restrict__ attnf)
{
    extern __shared__ float fsm[];
    float* Qs = fsm + FL_QS;
    float* Ks = fsm + FL_KS;
    float* Ps = fsm + FL_PS;
    float* Vs = fsm + FL_VS;

    const int bh = blockIdx.y;
    const int b = bh >> 4, h = bh & 15;
    const int qt = blockIdx.x * 64;

    const int tid = threadIdx.x;
    const int ty = tid >> 4, tx = tid & 15;
    const int lr = tid >> 4;
    const int lc = (tid & 15) * 4;

    // load + rope Q tile (transposed: Qs[d][m]); pairs (j, j+32)
    #pragma unroll
    for (int it = 0; it < 2; it++) {
        const int m  = (tid >> 3) + it * 32;     // 0..63
        const int jj = (tid & 7) * 4;            // 0..28
        const int qpos = qt + m;                 // sequence position
        const float* qp = q + ((size_t)qpos * B_ + b) * D_ + h * HD_;
        float4 a  = *(const float4*)(qp + jj);
        float4 bb = *(const float4*)(qp + jj + 32);
        float av[4] = {a.x, a.y, a.z, a.w};
        float bv[4] = {bb.x, bb.y, bb.z, bb.w};
        #pragma unroll
        for (int i2 = 0; i2 < 4; i2++) {
            const float invf = powf(10000.f, -((float)(2*(jj+i2))) * (1.f / HD_));
            float sn, cs;
            sincosf((float)qpos * invf, &sn, &cs);
            Qs[(jj+i2)*65 + m]    = av[i2]*cs - bv[i2]*sn;
            Qs[(jj+i2+32)*65 + m] = bv[i2]*cs + av[i2]*sn;
        }
    }

    float mrow[4], ssum[4], acc_o[4][4];
    #pragma unroll
    for (int i = 0; i < 4; i++) {
        mrow[i] = -3.0e38f; ssum[i] = 0.f;
        #pragma unroll
        for (int j = 0; j < 4; j++) acc_o[i][j] = 0.f;
    }

    const float scale = 0.125f;

    for (int kt = 0; kt < S_; kt += 64) {
        // load + rope K tile (transposed)
        #pragma unroll
        for (int it = 0; it < 2; it++) {
            const int m  = (tid >> 3) + it * 32;
            const int jj = (tid & 7) * 4;
            const int kpos = kt + m;
            const float* kp = k + ((size_t)kpos * B_ + b) * D_ + h * HD_;
            float4 a  = *(const float4*)(kp + jj);
            float4 bb = *(const float4*)(kp + jj + 32);
            float av[4] = {a.x, a.y, a.z, a.w};
            float bv[4] = {bb.x, bb.y, bb.z, bb.w};
            #pragma unroll
            for (int i2 = 0; i2 < 4; i2++) {
                const float invf = powf(10000.f, -((float)(2*(jj+i2))) * (1.f / HD_));
                float sn, cs;
                sincosf((float)kpos * invf, &sn, &cs);
                Ks[(jj+i2)*65 + m]    = av[i2]*cs - bv[i2]*sn;
                Ks[(jj+i2+32)*65 + m] = bv[i2]*cs + av[i2]*sn;
            }
        }
        // load V tile
        #pragma unroll
        for (int it = 0; it < 4; it++) {
            const int m = lr + it * 16;
            float4 vv4 = *(const float4*)(v + ((size_t)(kt + m) * B_ + b) * D_ + h*HD_ + lc);
            *(float4*)&Vs[m*68 + lc] = vv4;
        }
        __syncthreads();

        // S = scale * Q K^T (4x4 per thread)
        float sacc[4][4];
        #pragma unroll
        for (int i = 0; i < 4; i++)
            #pragma unroll
            for (int j = 0; j < 4; j++) sacc[i][j] = 0.f;
        #pragma unroll 16
        for (int kk = 0; kk < HD_; kk++) {
            float av[4], bv[4];
            #pragma unroll
            for (int i = 0; i < 4; i++) av[i] = Qs[kk*65 + ty*4 + i];
            #pragma unroll
            for (int j = 0; j < 4; j++) bv[j] = Ks[kk*65 + tx*4 + j];
            #pragma unroll
            for (int i = 0; i < 4; i++)
                #pragma unroll
                for (int j = 0; j < 4; j++)
                    sacc[i][j] = fmaf(av[i], bv[j], sacc[i][j]);
        }
        // mask + scale
        #pragma unroll
        for (int j = 0; j < 4; j++) {
            const int kpos = kt + tx*4 + j;
            const bool masked = (mask[b*S_ + kpos] != 0);
            #pragma unroll
            for (int i = 0; i < 4; i++) {
                float sv = sacc[i][j] * scale;
                sacc[i][j] = masked ? -1e30f : sv;
            }
        }
        // online softmax update per row
        #pragma unroll
        for (int i = 0; i < 4; i++) {
            float rmax = fmaxf(fmaxf(sacc[i][0], sacc[i][1]),
                               fmaxf(sacc[i][2], sacc[i][3]));
            #pragma unroll
            for (int o = 8; o; o >>= 1)
                rmax = fmaxf(rmax, __shfl_xor_sync(0xffffffffu, rmax, o));
            const float mnew = fmaxf(mrow[i], rmax);
            const float corr = __expf(mrow[i] - mnew);
            float rsum = 0.f;
            #pragma unroll
            for (int j = 0; j < 4; j++) {
                const float p = __expf(sacc[i][j] - mnew);
                sacc[i][j] = p;
                rsum += p;
            }
            #pragma unroll
            for (int o = 8; o; o >>= 1)
                rsum += __shfl_xor_sync(0xffffffffu, rsum, o);
            mrow[i] = mnew;
            ssum[i] = ssum[i] * corr + rsum;
            #pragma unroll
            for (int j = 0; j < 4; j++) acc_o[i][j] *= corr;
        }
        // write P transposed
        #pragma unroll
        for (int i = 0; i < 4; i++)
            #pragma unroll
            for (int j = 0; j < 4; j++)
                Ps[(tx*4 + j)*65 + ty*4 + i] = sacc[i][j];
        __syncthreads();

        // O += P V
        #pragma unroll 16
        for (int kk = 0; kk < 64; kk++) {
            float pv[4], vv[4];
            #pragma unroll
            for (int i = 0; i < 4; i++) pv[i] = Ps[kk*65 + ty*4 + i];
            #pragma unroll
            for (int j = 0; j < 4; j++) vv[j] = Vs[kk*68 + tx*4 + j];
            #pragma unroll
            for (int i = 0; i < 4; i++)
                #pragma unroll
                for (int j = 0; j < 4; j++)
                    acc_o[i][j] = fmaf(pv[i], vv[j], acc_o[i][j]);
        }
        __syncthreads();
    }

    // normalize + frag-major split scatter
    #pragma unroll
    for (int i = 0; i < 4; i++) {
        const float inv = 1.f / ssum[i];
        const int qpos = qt + ty*4 + i;
        const int t = qpos * B_ + b;
        const int c0 = h * HD_ + tx * 4;
        unsigned hh, ll;
        splitp_bf16(acc_o[i][0] * inv, acc_o[i][1] * inv, hh, ll);
        size_t o = afr_index(t, c0 >> 1, D_ / 32);
        attnf[o] = hh; attnf[o + 128] = ll;
        splitp_bf16(acc_o[i][2] * inv, acc_o[i][3] * inv, hh, ll);
        o = afr_index(t, (c0 >> 1) + 1, D_ / 32);
        attnf[o] = hh; attnf[o + 128] = ll;
    }
}

// ---------------- host orchestration ---------------------------------------
extern "C" void kernel_launch(void* const* d_in, const int* in_sizes, int n_in,
                              void* d_out, int out_size)
{
    (void)in_sizes; (void)n_in; (void)out_size;

    const float* segments  = (const float*)d_in[0];
    const float* durations = (const float*)d_in[1];
    const int*   padmask   = (const int*)d_in[2];
    const float* Wproj = (const float*)d_in[3];
    const float* bproj = (const float*)d_in[4];
    const float* Wdur  = (const float*)d_in[5];
    const float* bdur  = (const float*)d_in[6];
    const float* ln1_g = (const float*)d_in[7];
    const float* ln1_b = (const float*)d_in[8];
    const float* Wq = (const float*)d_in[9];
    const float* bq = (const float*)d_in[10];
    const float* Wk = (const float*)d_in[11];
    const float* bk = (const float*)d_in[12];
    const float* Wv = (const float*)d_in[13];
    const float* bv = (const float*)d_in[14];
    const float* Wo = (const float*)d_in[15];
    const float* bo = (const float*)d_in[16];
    const float* ln2_g = (const float*)d_in[17];
    const float* ln2_b = (const float*)d_in[18];
    const float* Wff1 = (const float*)d_in[19];
    const float* bff1 = (const float*)d_in[20];
    const float* Wff2 = (const float*)d_in[21];
    const float* bff2 = (const float*)d_in[22];

    float* x = (float*)d_out;

    float *q, *k, *v;
    unsigned *segf, *hf, *attnf, *fff;
    unsigned *wprojp, *wqp, *wkp, *wvp, *wop, *w1p, *w2p;
    cudaGetSymbolAddress((void**)&q,      g_q);
    cudaGetSymbolAddress((void**)&k,      g_k);
    cudaGetSymbolAddress((void**)&v,      g_v);
    cudaGetSymbolAddress((void**)&segf,   g_segf);
    cudaGetSymbolAddress((void**)&hf,     g_hf);
    cudaGetSymbolAddress((void**)&attnf,  g_attnf);
    cudaGetSymbolAddress((void**)&fff,    g_fff);
    cudaGetSymbolAddress((void**)&wprojp, g_wprojp);
    cudaGetSymbolAddress((void**)&wqp,    g_wqp);
    cudaGetSymbolAddress((void**)&wkp,    g_wkp);
    cudaGetSymbolAddress((void**)&wvp,    g_wvp);
    cudaGetSymbolAddress((void**)&wop,    g_wop);
    cudaGetSymbolAddress((void**)&w1p,    g_w1p);
    cudaGetSymbolAddress((void**)&w2p,    g_w2p);

    cudaFuncSetAttribute(gemm_tc,
        cudaFuncAttributeMaxDynamicSharedMemorySize, SMEM_BYTES);
    cudaFuncSetAttribute(flash_kernel,
        cudaFuncAttributeMaxDynamicSharedMemorySize, FLASH_SMEM);

    // ---- prep pass
    asplit<<<1184, 256>>>(segments, segf, DIN_);
    wsplit<<<dim3(1184, 1, 1),  256>>>(Wproj, wprojp, DIN_, D_);
    wsplit<<<dim3(256, 1, L_),  256>>>(Wq, wqp, D_, D_);
    wsplit<<<dim3(256, 1, L_),  256>>>(Wk, wkp, D_, D_);
    wsplit<<<dim3(256, 1, L_),  256>>>(Wv, wvp, D_, D_);
    wsplit<<<dim3(256, 1, L_),  256>>>(Wo, wop, D_, D_);
    wsplit<<<dim3(1024, 1, L_), 256>>>(Wff1, w1p, D_, F_);
    wsplit<<<dim3(1024, 1, L_), 256>>>(Wff2, w2p, F_, D_);

    const dim3 blk(256);

    // proj: x = segments @ Wproj + bproj + durations*Wdur + bdur
    gemm_tc<<<dim3(D_/TBN, T_/TBM), blk, SMEM_BYTES>>>(
        segf, wprojp, wprojp, wprojp, bproj, bproj, bproj, bdur,
        durations, Wdur, nullptr,
        x, x, x, nullptr, T_, D_, DIN_, 0);

    for (int l = 0; l < L_; l++) {
        const size_t od = (size_t)l*D_*D_;
        const size_t o1 = (size_t)l*D_*F_;
        const size_t o2 = (size_t)l*F_*D_;

        ln_kernel<<<T_, 256>>>(x, ln1_g + l*D_, ln1_b + l*D_, hf);

        // fused QKV: 3 segments, grid 24 x 16 = 384 CTAs
        gemm_tc<<<dim3(3*D_/TBN, T_/TBM), blk, SMEM_BYTES>>>(
            hf, wqp + od, wkp + od, wvp + od,
            bq + l*D_, bk + l*D_, bv + l*D_, nullptr,
            nullptr, nullptr, nullptr,
            q, k, v, nullptr, T_, D_, D_, 0);

        // flash attention with fused RoPE
        flash_kernel<<<dim3(S_/64, B_*H_), blk, FLASH_SMEM>>>(
            q, k, v, padmask, attnf);

        // x = x + attn @ Wo + bo
        gemm_tc<<<dim3(D_/TBN, T_/TBM), blk, SMEM_BYTES>>>(
            attnf, wop + od, wop + od, wop + od,
            bo + l*D_, bo + l*D_, bo + l*D_, nullptr,
            nullptr, nullptr, x,
            x, x, x, nullptr, T_, D_, D_, 0);

        ln_kernel<<<T_, 256>>>(x, ln2_g + l*D_, ln2_b + l*D_, hf);

        // ff = gelu(h @ W1 + b1), frag-major output
        gemm_tc<<<dim3(F_/TBN, T_/TBM), blk, SMEM_BYTES>>>(
            hf, w1p + o1, w1p + o1, w1p + o1,
            bff1 + l*F_, bff1 + l*F_, bff1 + l*F_, nullptr,
            nullptr, nullptr, nullptr,
            nullptr, nullptr, nullptr, fff, T_, F_, D_, 1);

        // x = x + ff @ W2 + b2
        gemm_tc<<<dim3(D_/TBN, T_/TBM), blk, SMEM_BYTES>>>(
            fff, w2p + o2, w2p + o2, w2p + o2,
            bff2 + l*D_, bff2 + l*D_, bff2 + l*D_, nullptr,
            nullptr, nullptr, x,
            x, x, x, nullptr, T_, D_, F_, 0);
    }
}

// round 15
// speedup vs baseline: 1.1599x; 1.0241x over previous
#include <cuda_runtime.h>
#include <math.h>
#include <stdint.h>

#define L_   12
#define S_   512
#define B_   4
#define DIN_ 768
#define D_   1024
#define H_   16
#define F_   4096
#define HD_  64
#define T_   (S_*B_)   // 2048 tokens

// ---------------- scratch (static device globals; no runtime allocation) ----
__device__ float g_q[T_*D_];
__device__ float g_k[T_*D_];
__device__ float g_v[T_*D_];

// frag-major bf16x2 hi/lo activation buffers
__device__ unsigned g_segf[T_*DIN_];
__device__ unsigned g_hf[T_*D_];
__device__ unsigned g_attnf[T_*D_];
__device__ unsigned g_fff[(size_t)T_*F_];

// packed k-pair bf16x2 hi/lo weight planes ([layer][2 planes][K/2][N] u32)
__device__ unsigned g_wprojp[DIN_*D_];
__device__ unsigned g_wqp[(size_t)L_*D_*D_];
__device__ unsigned g_wkp[(size_t)L_*D_*D_];
__device__ unsigned g_wvp[(size_t)L_*D_*D_];
__device__ unsigned g_wop[(size_t)L_*D_*D_];
__device__ unsigned g_w1p[(size_t)L_*D_*F_];
__device__ unsigned g_w2p[(size_t)L_*F_*D_];

// ---------------- bf16 split helpers ---------------------------------------
__device__ __forceinline__ unsigned pack_bf16(float x0, float x1) {
    unsigned u;
    asm("cvt.rn.bf16x2.f32 %0, %1, %2;" : "=r"(u) : "f"(x1), "f"(x0));
    return u;
}
__device__ __forceinline__ void splitp_bf16(float a, float b, unsigned& h, unsigned& l)
{
    h = pack_bf16(a, b);
    const float ha = __uint_as_float(h << 16);
    const float hb = __uint_as_float(h & 0xffff0000u);
    l = pack_bf16(a - ha, b - hb);
}

__device__ __forceinline__ void mma_bf16(float c[4],
    unsigned a0, unsigned a1, unsigned a2, unsigned a3,
    unsigned b0, unsigned b1)
{
    asm volatile(
        "mma.sync.aligned.m16n8k16.row.col.f32.bf16.bf16.f32 "
        "{%0,%1,%2,%3}, {%4,%5,%6,%7}, {%8,%9}, {%0,%1,%2,%3};"
        : "+f"(c[0]), "+f"(c[1]), "+f"(c[2]), "+f"(c[3])
        : "r"(a0), "r"(a1), "r"(a2), "r"(a3), "r"(b0), "r"(b1));
}

__device__ __forceinline__ void cp16(uint32_t dst, const void* src) {
    asm volatile("cp.async.cg.shared.global [%0], [%1], 16;"
                 :: "r"(dst), "l"(src) : "memory");
}
#define CP_COMMIT() asm volatile("cp.async.commit_group;" ::: "memory")
#define CP_WAIT1()  asm volatile("cp.async.wait_group 1;" ::: "memory")
#define CP_WAIT0()  asm volatile("cp.async.wait_group 0;" ::: "memory")

// A-frag index: element (row r, k-pair p), KT = K/32 k-tiles (granularity 32)
__device__ __forceinline__ size_t afr_index(int r, int p, int KT) {
    const int gmt = r >> 4, rr = r & 15;
    const int kt = p >> 4, step = (p >> 3) & 1, pp = p & 7;
    const int lane = (rr & 7) * 4 + (pp & 3);
    const int reg  = (rr >> 3) + ((pp >> 2) << 1);
    return (((size_t)gmt * KT + kt) * 4 + step * 2) * 128 + lane * 4 + reg;
}

// ---------------- prep kernels (vectorized) ---------------------------------
// weight pack: [K][N] -> 2 planes [K/2][N] u32; one thread = 4 columns x 1 k-pair
__global__ void wsplit(const float* __restrict__ in, unsigned* __restrict__ out,
                       int K, int N)
{
    const size_t half = (size_t)(K / 2) * N;
    in  += (size_t)blockIdx.z * K * N;
    out += (size_t)blockIdx.z * K * N;
    const int n4 = N >> 2;
    const int total = (K >> 1) * n4;
    for (int idx = blockIdx.x * 256 + threadIdx.x; idx < total;
         idx += gridDim.x * 256) {
        const int p  = idx / n4;
        const int nq = (idx - p * n4) * 4;
        const float4 r0 = *(const float4*)(in + (size_t)(2 * p)     * N + nq);
        const float4 r1 = *(const float4*)(in + (size_t)(2 * p + 1) * N + nq);
        uint4 h, l;
        splitp_bf16(r0.x, r1.x, h.x, l.x);
        splitp_bf16(r0.y, r1.y, h.y, l.y);
        splitp_bf16(r0.z, r1.z, h.z, l.z);
        splitp_bf16(r0.w, r1.w, h.w, l.w);
        *(uint4*)(out + (size_t)p * N + nq) = h;
        *(uint4*)(out + half + (size_t)p * N + nq) = l;
    }
}

__global__ void asplit(const float* __restrict__ in, unsigned* __restrict__ out,
                       int K)
{
    const int KP = K / 2, KT = K / 32;
    const int total = T_ * KP;
    for (int idx = blockIdx.x * 256 + threadIdx.x; idx < total;
         idx += gridDim.x * 256) {
        const int t = idx / KP, p = idx % KP;
        unsigned h, l;
        splitp_bf16(in[(size_t)t * K + 2 * p], in[(size_t)t * K + 2 * p + 1], h, l);
        const size_t o = afr_index(t, p, KT);
        out[o] = h;
        out[o + 128] = l;
    }
}

// ---------------- tensor-core GEMM (bf16 3-term, TBK=64, 3-stage) ----------
#define TBM 128
#define TBN 128
#define B_STU 136
#define AFRAG_U 8192                     // A per stage: 64 frag blocks x 128
#define OFF_B 8192
#define STAGE_U (AFRAG_U + 2*32*B_STU)   // 16896
#define NSTAGE 3
#define SMEM_BYTES (NSTAGE*STAGE_U*4)    // 202752

__global__ __launch_bounds__(256, 1) void gemm_tc(
    const unsigned* __restrict__ Afr,
    const unsigned* __restrict__ Bp0, const unsigned* __restrict__ Bp1,
    const unsigned* __restrict__ Bp2,
    const float* __restrict__ bias0s, const float* __restrict__ bias1s,
    const float* __restrict__ bias2s,
    const float* __restrict__ biasadd,
    const float* __restrict__ rowvec, const float* __restrict__ colvec,
    const float* __restrict__ residual,
    float* __restrict__ C0, float* __restrict__ C1, float* __restrict__ C2,
    unsigned* __restrict__ Cfr,
    int M, int N, int K, int gelu_flag)
{
    extern __shared__ unsigned smbuf[];
    const uint32_t smu = (uint32_t)__cvta_generic_to_shared(smbuf);

    const int tid  = threadIdx.x;
    const int warp = tid >> 5;
    const int lane = tid & 31;
    const int g    = lane >> 2;
    const int tig  = lane & 3;
    const int wmt  = (warp >> 2) * 4;
    const int wm   = wmt * 16;
    const int wn   = (warp & 3) * 32;

    const int nxb  = N / TBN;
    const int seg  = blockIdx.x / nxb;
    const int col0 = (blockIdx.x - seg * nxb) * TBN;
    const int row0 = blockIdx.y * TBM;
    const int KT   = K >> 5;             // kt blocks of 32
    const int gmt0 = row0 >> 4;
    const size_t bplane = (size_t)(K >> 1) * N;

    const unsigned* Bp = (seg == 0) ? Bp0 : (seg == 1) ? Bp1 : Bp2;
    const float* bias  = (seg == 0) ? bias0s : (seg == 1) ? bias1s : bias2s;
    float* Cg          = (seg == 0) ? C0 : (seg == 1) ? C1 : C2;

    // stage covers 64 k (2 kt blocks); pure cp.async
    auto issue = [&](int kt2, int stg) {
        const uint32_t base = smu + stg * STAGE_U * 4;
        #pragma unroll
        for (int u = 0; u < 8; u++) {
            const int s = tid + u * 256;
            const int f = s >> 5, w16 = s & 31;
            const int mt8 = f >> 3, sub = f & 7;
            const int half = sub >> 2, rem = sub & 3;
            const unsigned* src = Afr +
                ((((size_t)(gmt0 + mt8) * KT + kt2 * 2 + half) * 4 + rem) * 128)
                + w16 * 4;
            cp16(base + (f * 128 + w16 * 4) * 4, src);
        }
        #pragma unroll
        for (int u = 0; u < 8; u++) {
            const int s = tid + u * 256;
            const int hl = s >> 10, rem = s & 1023;
            const int p = rem >> 5, w16 = rem & 31;
            const unsigned* src = Bp + (size_t)hl * bplane +
                (size_t)(kt2 * 32 + p) * N + col0 + w16 * 4;
            cp16(base + (OFF_B + hl * 32 * B_STU + p * B_STU + w16 * 4) * 4, src);
        }
        CP_COMMIT();
    };

    float acc[4][4][4];
    #pragma unroll
    for (int mt = 0; mt < 4; mt++)
        #pragma unroll
        for (int nt = 0; nt < 4; nt++)
            #pragma unroll
            for (int r = 0; r < 4; r++) acc[mt][nt][r] = 0.f;

    const int nk = K >> 6;
    issue(0, 0);
    issue(1, 1);

    for (int ki = 0; ki < nk; ki++) {
        if (ki + 1 < nk) { CP_WAIT1(); } else { CP_WAIT0(); }
        __syncthreads();
        if (ki + 2 < nk) issue(ki + 2, (ki + 2) % NSTAGE);

        const unsigned* cur = smbuf + (ki % NSTAGE) * STAGE_U;
        const unsigned* Bh = cur + OFF_B;
        const unsigned* Bl = cur + OFF_B + 32 * B_STU;
        #pragma unroll
        for (int half = 0; half < 2; half++) {
            #pragma unroll
            for (int st = 0; st < 2; st++) {
                const int pb = half * 16 + st * 8;
                unsigned ah[4][4], al[4][4];
                #pragma unroll
                for (int mt = 0; mt < 4; mt++) {
                    const int fb = (wmt + mt) * 8 + half * 4 + st * 2;
                    uint4 av = *(const uint4*)&cur[fb * 128 + lane * 4];
                    ah[mt][0] = av.x; ah[mt][1] = av.y; ah[mt][2] = av.z; ah[mt][3] = av.w;
                    uint4 lv = *(const uint4*)&cur[(fb + 1) * 128 + lane * 4];
                    al[mt][0] = lv.x; al[mt][1] = lv.y; al[mt][2] = lv.z; al[mt][3] = lv.w;
                }
                unsigned bh[4][2], bl[4][2];
                #pragma unroll
                for (int nt = 0; nt < 4; nt++) {
                    const int n = wn + nt * 8 + g;
                    const int c0i = (pb + tig) * B_STU + n;
                    const int c1i = (pb + tig + 4) * B_STU + n;
                    bh[nt][0] = Bh[c0i]; bh[nt][1] = Bh[c1i];
                    bl[nt][0] = Bl[c0i]; bl[nt][1] = Bl[c1i];
                }
                #pragma unroll
                for (int mt = 0; mt < 4; mt++)
                    #pragma unroll
                    for (int nt = 0; nt < 4; nt++) {
                        mma_bf16(acc[mt][nt], ah[mt][0], ah[mt][1], ah[mt][2], ah[mt][3],
                                 bh[nt][0], bh[nt][1]);
                        mma_bf16(acc[mt][nt], al[mt][0], al[mt][1], al[mt][2], al[mt][3],
                                 bh[nt][0], bh[nt][1]);
                        mma_bf16(acc[mt][nt], ah[mt][0], ah[mt][1], ah[mt][2], ah[mt][3],
                                 bl[nt][0], bl[nt][1]);
                    }
            }
        }
    }
    __syncthreads();

    // ---- epilogue
    const int KTo = N >> 5;
    #pragma unroll
    for (int mt = 0; mt < 4; mt++) {
        #pragma unroll
        for (int half = 0; half < 2; half++) {
            const int r = row0 + wm + mt * 16 + g + half * 8;
            const float rv = rowvec ? rowvec[r] : 0.f;
            #pragma unroll
            for (int nt = 0; nt < 4; nt++) {
                const int c = col0 + wn + nt * 8 + 2 * tig;
                float v0 = acc[mt][nt][half * 2 + 0];
                float v1 = acc[mt][nt][half * 2 + 1];
                if (bias)    { v0 += bias[c];    v1 += bias[c + 1]; }
                if (biasadd) { v0 += biasadd[c]; v1 += biasadd[c + 1]; }
                if (rowvec)  { v0 += rv * colvec[c]; v1 += rv * colvec[c + 1]; }
                if (gelu_flag) {
                    v0 = 0.5f * v0 * (1.f + erff(v0 * 0.70710678118654752f));
                    v1 = 0.5f * v1 * (1.f + erff(v1 * 0.70710678118654752f));
                }
                if (residual) {
                    float2 rr = *(const float2*)(residual + (size_t)r * N + c);
                    v0 += rr.x; v1 += rr.y;
                }
                if (Cfr) {
                    unsigned h, l;
                    splitp_bf16(v0, v1, h, l);
                    const size_t o = afr_index(r, c >> 1, KTo);
                    Cfr[o] = h;
                    Cfr[o + 128] = l;
                } else {
                    float2 o; o.x = v0; o.y = v1;
                    *(float2*)(Cg + (size_t)r * N + c) = o;
                }
            }
        }
    }
}

// ---------------- LayerNorm: one block per token, frag-major split out -----
__global__ __launch_bounds__(256) void ln_kernel(
    const float* __restrict__ x, const float* __restrict__ g,
    const float* __restrict__ bta, unsigned* __restrict__ outf)
{
    const int t = blockIdx.x;
    const int tid = threadIdx.x;
    const float* xr = x + (size_t)t * D_;
    const int c4 = tid * 4;

    float4 v = *(const float4*)(xr + c4);
    float s  = v.x + v.y + v.z + v.w;
    float s2 = v.x*v.x + v.y*v.y + v.z*v.z + v.w*v.w;
    #pragma unroll
    for (int o = 16; o; o >>= 1) {
        s  += __shfl_xor_sync(0xffffffffu, s,  o);
        s2 += __shfl_xor_sync(0xffffffffu, s2, o);
    }
    __shared__ float ss[8], ss2[8];
    if ((tid & 31) == 0) { ss[tid >> 5] = s; ss2[tid >> 5] = s2; }
    __syncthreads();
    s = 0.f; s2 = 0.f;
    #pragma unroll
    for (int w = 0; w < 8; w++) { s += ss[w]; s2 += ss2[w]; }

    const float mean = s * (1.f / D_);
    const float var  = s2 * (1.f / D_) - mean * mean;
    const float inv  = rsqrtf(var + 1e-5f);

    const float4 gg = *(const float4*)(g + c4);
    const float4 bb = *(const float4*)(bta + c4);
    const float y0 = (v.x - mean) * inv * gg.x + bb.x;
    const float y1 = (v.y - mean) * inv * gg.y + bb.y;
    const float y2 = (v.z - mean) * inv * gg.z + bb.z;
    const float y3 = (v.w - mean) * inv * gg.w + bb.w;

    unsigned h, l;
    splitp_bf16(y0, y1, h, l);
    size_t o = afr_index(t, c4 >> 1, D_ / 32);
    outf[o] = h; outf[o + 128] = l;
    splitp_bf16(y2, y3, h, l);
    o = afr_index(t, (c4 >> 1) + 1, D_ / 32);
    outf[o] = h; outf[o + 128] = l;
}

// ---------------- fused flash attention with in-loader RoPE ----------------
// grid (S/64, B*H), block 256. Q/K roped on load; RoPE inverse frequencies
// hoisted into registers (thread-fixed) — no powf in the k-loop.
#define FL_QS 0
#define FL_KS (64*65)
#define FL_PS (2*64*65)
#define FL_VS (3*64*65)
#define FLASH_FLOATS (3*64*65 + 64*68)
#define FLASH_SMEM (FLASH_FLOATS*4)   // 67,392 B

__global__ __launch_bounds__(256) void flash_kernel(
    const float* __restrict__ q, const float* __restrict__ k,
    const float* __restrict__ v, const int* __restrict__ mask,
    unsigned* __restrict__ attnf)
{
    extern __shared__ float fsm[];
    float* Qs = fsm + FL_QS;
    float* Ks = fsm + FL_KS;
    float* Ps = fsm + FL_PS;
    float* Vs = fsm + FL_VS;

    const int bh = blockIdx.y;
    const int b = bh >> 4, h = bh & 15;
    const int qt = blockIdx.x * 64;

    const int tid = threadIdx.x;
    const int ty = tid >> 4, tx = tid & 15;
    const int lr = tid >> 4;
    const int lc = (tid & 15) * 4;

    // hoisted RoPE inverse frequencies for this thread's jj..jj+3
    const int jj = (tid & 7) * 4;
    float invf[4];
    #pragma unroll
    for (int i2 = 0; i2 < 4; i2++)
        invf[i2] = powf(10000.f, -((float)(2*(jj+i2))) * (1.f / HD_));

    // load + rope Q tile (transposed: Qs[d][m]); pairs (j, j+32)
    #pragma unroll
    for (int it = 0; it < 2; it++) {
        const int m  = (tid >> 3) + it * 32;     // 0..63
        const int qpos = qt + m;                 // sequence position
        const float* qp = q + ((size_t)qpos * B_ + b) * D_ + h * HD_;
        float4 a  = *(const float4*)(qp + jj);
        float4 bb = *(const float4*)(qp + jj + 32);
        float av[4] = {a.x, a.y, a.z, a.w};
        float bv[4] = {bb.x, bb.y, bb.z, bb.w};
        #pragma unroll
        for (int i2 = 0; i2 < 4; i2++) {
            float sn, cs;
            sincosf((float)qpos * invf[i2], &sn, &cs);
            Qs[(jj+i2)*65 + m]    = av[i2]*cs - bv[i2]*sn;
            Qs[(jj+i2+32)*65 + m] = bv[i2]*cs + av[i2]*sn;
        }
    }

    float mrow[4], ssum[4], acc_o[4][4];
    #pragma unroll
    for (int i = 0; i < 4; i++) {
        mrow[i] = -3.0e38f; ssum[i] = 0.f;
        #pragma unroll
        for (int j = 0; j < 4; j++) acc_o[i][j] = 0.f;
    }

    const float scale = 0.125f;

    for (int kt = 0; kt < S_; kt += 64) {
        // load + rope K tile (transposed)
        #pragma unroll
        for (int it = 0; it < 2; it++) {
            const int m  = (tid >> 3) + it * 32;
            const int kpos = kt + m;
            const float* kp = k + ((size_t)kpos * B_ + b) * D_ + h * HD_;
            float4 a  = *(const float4*)(kp + jj);
            float4 bb = *(const float4*)(kp + jj + 32);
            float av[4] = {a.x, a.y, a.z, a.w};
            float bv[4] = {bb.x, bb.y, bb.z, bb.w};
            #pragma unroll
            for (int i2 = 0; i2 < 4; i2++) {
                float sn, cs;
                sincosf((float)kpos * invf[i2], &sn, &cs);
                Ks[(jj+i2)*65 + m]    = av[i2]*cs - bv[i2]*sn;
                Ks[(jj+i2+32)*65 + m] = bv[i2]*cs + av[i2]*sn;
            }
        }
        // load V tile
        #pragma unroll
        for (int it = 0; it < 4; it++) {
            const int m = lr + it * 16;
            float4 vv4 = *(const float4*)(v + ((size_t)(kt + m) * B_ + b) * D_ + h*HD_ + lc);
            *(float4*)&Vs[m*68 + lc] = vv4;
        }
        __syncthreads();

        // S = scale * Q K^T (4x4 per thread)
        float sacc[4][4];
        #pragma unroll
        for (int i = 0; i < 4; i++)
            #pragma unroll
            for (int j = 0; j < 4; j++) sacc[i][j] = 0.f;
        #pragma unroll 16
        for (int kk = 0; kk < HD_; kk++) {
            float av[4], bv[4];
            #pragma unroll
            for (int i = 0; i < 4; i++) av[i] = Qs[kk*65 + ty*4 + i];
            #pragma unroll
            for (int j = 0; j < 4; j++) bv[j] = Ks[kk*65 + tx*4 + j];
            #pragma unroll
            for (int i = 0; i < 4; i++)
                #pragma unroll
                for (int j = 0; j < 4; j++)
                    sacc[i][j] = fmaf(av[i], bv[j], sacc[i][j]);
        }
        // mask + scale
        #pragma unroll
        for (int j = 0; j < 4; j++) {
            const int kpos = kt + tx*4 + j;
            const bool masked = (mask[b*S_ + kpos] != 0);
            #pragma unroll
            for (int i = 0; i < 4; i++) {
                float sv = sacc[i][j] * scale;
                sacc[i][j] = masked ? -1e30f : sv;
            }
        }
        // online softmax update per row
        #pragma unroll
        for (int i = 0; i < 4; i++) {
            float rmax = fmaxf(fmaxf(sacc[i][0], sacc[i][1]),
                               fmaxf(sacc[i][2], sacc[i][3]));
            #pragma unroll
            for (int o = 8; o; o >>= 1)
                rmax = fmaxf(rmax, __shfl_xor_sync(0xffffffffu, rmax, o));
            const float mnew = fmaxf(mrow[i], rmax);
            const float corr = __expf(mrow[i] - mnew);
            float rsum = 0.f;
            #pragma unroll
            for (int j = 0; j < 4; j++) {
                const float p = __expf(sacc[i][j] - mnew);
                sacc[i][j] = p;
                rsum += p;
            }
            #pragma unroll
            for (int o = 8; o; o >>= 1)
                rsum += __shfl_xor_sync(0xffffffffu, rsum, o);
            mrow[i] = mnew;
            ssum[i] = ssum[i] * corr + rsum;
            #pragma unroll
            for (int j = 0; j < 4; j++) acc_o[i][j] *= corr;
        }
        // write P transposed
        #pragma unroll
        for (int i = 0; i < 4; i++)
            #pragma unroll
            for (int j = 0; j < 4; j++)
                Ps[(tx*4 + j)*65 + ty*4 + i] = sacc[i][j];
        __syncthreads();

        // O += P V
        #pragma unroll 16
        for (int kk = 0; kk < 64; kk++) {
            float pv[4], vv[4];
            #pragma unroll
            for (int i = 0; i < 4; i++) pv[i] = Ps[kk*65 + ty*4 + i];
            #pragma unroll
            for (int j = 0; j < 4; j++) vv[j] = Vs[kk*68 + tx*4 + j];
            #pragma unroll
            for (int i = 0; i < 4; i++)
                #pragma unroll
                for (int j = 0; j < 4; j++)
                    acc_o[i][j] = fmaf(pv[i], vv[j], acc_o[i][j]);
        }
        __syncthreads();
    }

    // normalize + frag-major split scatter
    #pragma unroll
    for (int i = 0; i < 4; i++) {
        const float inv = 1.f / ssum[i];
        const int qpos = qt + ty*4 + i;
        const int t = qpos * B_ + b;
        const int c0 = h * HD_ + tx * 4;
        unsigned hh, ll;
        splitp_bf16(acc_o[i][0] * inv, acc_o[i][1] * inv, hh, ll);
        size_t o = afr_index(t, c0 >> 1, D_ / 32);
        attnf[o] = hh; attnf[o + 128] = ll;
        splitp_bf16(acc_o[i][2] * inv, acc_o[i][3] * inv, hh, ll);
        o = afr_index(t, (c0 >> 1) + 1, D_ / 32);
        attnf[o] = hh; attnf[o + 128] = ll;
    }
}

// ---------------- host orchestration ---------------------------------------
extern "C" void kernel_launch(void* const* d_in, const int* in_sizes, int n_in,
                              void* d_out, int out_size)
{
    (void)in_sizes; (void)n_in; (void)out_size;

    const float* segments  = (const float*)d_in[0];
    const float* durations = (const float*)d_in[1];
    const int*   padmask   = (const int*)d_in[2];
    const float* Wproj = (const float*)d_in[3];
    const float* bproj = (const float*)d_in[4];
    const float* Wdur  = (const float*)d_in[5];
    const float* bdur  = (const float*)d_in[6];
    const float* ln1_g = (const float*)d_in[7];
    const float* ln1_b = (const float*)d_in[8];
    const float* Wq = (const float*)d_in[9];
    const float* bq = (const float*)d_in[10];
    const float* Wk = (const float*)d_in[11];
    const float* bk = (const float*)d_in[12];
    const float* Wv = (const float*)d_in[13];
    const float* bv = (const float*)d_in[14];
    const float* Wo = (const float*)d_in[15];
    const float* bo = (const float*)d_in[16];
    const float* ln2_g = (const float*)d_in[17];
    const float* ln2_b = (const float*)d_in[18];
    const float* Wff1 = (const float*)d_in[19];
    const float* bff1 = (const float*)d_in[20];
    const float* Wff2 = (const float*)d_in[21];
    const float* bff2 = (const float*)d_in[22];

    float* x = (float*)d_out;

    float *q, *k, *v;
    unsigned *segf, *hf, *attnf, *fff;
    unsigned *wprojp, *wqp, *wkp, *wvp, *wop, *w1p, *w2p;
    cudaGetSymbolAddress((void**)&q,      g_q);
    cudaGetSymbolAddress((void**)&k,      g_k);
    cudaGetSymbolAddress((void**)&v,      g_v);
    cudaGetSymbolAddress((void**)&segf,   g_segf);
    cudaGetSymbolAddress((void**)&hf,     g_hf);
    cudaGetSymbolAddress((void**)&attnf,  g_attnf);
    cudaGetSymbolAddress((void**)&fff,    g_fff);
    cudaGetSymbolAddress((void**)&wprojp, g_wprojp);
    cudaGetSymbolAddress((void**)&wqp,    g_wqp);
    cudaGetSymbolAddress((void**)&wkp,    g_wkp);
    cudaGetSymbolAddress((void**)&wvp,    g_wvp);
    cudaGetSymbolAddress((void**)&wop,    g_wop);
    cudaGetSymbolAddress((void**)&w1p,    g_w1p);
    cudaGetSymbolAddress((void**)&w2p,    g_w2p);

    cudaFuncSetAttribute(gemm_tc,
        cudaFuncAttributeMaxDynamicSharedMemorySize, SMEM_BYTES);
    cudaFuncSetAttribute(flash_kernel,
        cudaFuncAttributeMaxDynamicSharedMemorySize, FLASH_SMEM);

    // ---- prep pass (vectorized splitters)
    asplit<<<1184, 256>>>(segments, segf, DIN_);
    wsplit<<<dim3(296, 1, 1),  256>>>(Wproj, wprojp, DIN_, D_);
    wsplit<<<dim3(128, 1, L_), 256>>>(Wq, wqp, D_, D_);
    wsplit<<<dim3(128, 1, L_), 256>>>(Wk, wkp, D_, D_);
    wsplit<<<dim3(128, 1, L_), 256>>>(Wv, wvp, D_, D_);
    wsplit<<<dim3(128, 1, L_), 256>>>(Wo, wop, D_, D_);
    wsplit<<<dim3(512, 1, L_), 256>>>(Wff1, w1p, D_, F_);
    wsplit<<<dim3(512, 1, L_), 256>>>(Wff2, w2p, F_, D_);

    const dim3 blk(256);

    // proj: x = segments @ Wproj + bproj + durations*Wdur + bdur
    gemm_tc<<<dim3(D_/TBN, T_/TBM), blk, SMEM_BYTES>>>(
        segf, wprojp, wprojp, wprojp, bproj, bproj, bproj, bdur,
        durations, Wdur, nullptr,
        x, x, x, nullptr, T_, D_, DIN_, 0);

    for (int l = 0; l < L_; l++) {
        const size_t od = (size_t)l*D_*D_;
        const size_t o1 = (size_t)l*D_*F_;
        const size_t o2 = (size_t)l*F_*D_;

        ln_kernel<<<T_, 256>>>(x, ln1_g + l*D_, ln1_b + l*D_, hf);

        // fused QKV: 3 segments, grid 24 x 16 = 384 CTAs
        gemm_tc<<<dim3(3*D_/TBN, T_/TBM), blk, SMEM_BYTES>>>(
            hf, wqp + od, wkp + od, wvp + od,
            bq + l*D_, bk + l*D_, bv + l*D_, nullptr,
            nullptr, nullptr, nullptr,
            q, k, v, nullptr, T_, D_, D_, 0);

        // flash attention with fused RoPE
        flash_kernel<<<dim3(S_/64, B_*H_), blk, FLASH_SMEM>>>(
            q, k, v, padmask, attnf);

        // x = x + attn @ Wo + bo
        gemm_tc<<<dim3(D_/TBN, T_/TBM), blk, SMEM_BYTES>>>(
            attnf, wop + od, wop + od, wop + od,
            bo + l*D_, bo + l*D_, bo + l*D_, nullptr,
            nullptr, nullptr, x,
            x, x, x, nullptr, T_, D_, D_, 0);

        ln_kernel<<<T_, 256>>>(x, ln2_g + l*D_, ln2_b + l*D_, hf);

        // ff = gelu(h @ W1 + b1), frag-major output
        gemm_tc<<<dim3(F_/TBN, T_/TBM), blk, SMEM_BYTES>>>(
            hf, w1p + o1, w1p + o1, w1p + o1,
            bff1 + l*F_, bff1 + l*F_, bff1 + l*F_, nullptr,
            nullptr, nullptr, nullptr,
            nullptr, nullptr, nullptr, fff, T_, F_, D_, 1);

        // x = x + ff @ W2 + b2
        gemm_tc<<<dim3(D_/TBN, T_/TBM), blk, SMEM_BYTES>>>(
            fff, w2p + o2, w2p + o2, w2p + o2,
            bff2 + l*D_, bff2 + l*D_, bff2 + l*D_, nullptr,
            nullptr, nullptr, x,
            x, x, x, nullptr, T_, D_, F_, 0);
    }
}

// round 16
// speedup vs baseline: 1.3204x; 1.1384x over previous
#include <cuda_runtime.h>
#include <math.h>
#include <stdint.h>

#define L_   12
#define S_   512
#define B_   4
#define DIN_ 768
#define D_   1024
#define H_   16
#define F_   4096
#define HD_  64
#define T_   (S_*B_)   // 2048 tokens

// ---------------- scratch (static device globals; no runtime allocation) ----
__device__ float g_q[T_*D_];
__device__ float g_k[T_*D_];
__device__ float g_v[T_*D_];

// frag-major bf16x2 hi/lo activation buffers
__device__ unsigned g_segf[T_*DIN_];
__device__ unsigned g_hf[T_*D_];
__device__ unsigned g_attnf[T_*D_];
__device__ unsigned g_fff[(size_t)T_*F_];

// packed k-pair bf16x2 hi/lo weight planes ([layer][2 planes][K/2][N] u32)
__device__ unsigned g_wprojp[DIN_*D_];
__device__ unsigned g_wqp[(size_t)L_*D_*D_];
__device__ unsigned g_wkp[(size_t)L_*D_*D_];
__device__ unsigned g_wvp[(size_t)L_*D_*D_];
__device__ unsigned g_wop[(size_t)L_*D_*D_];
__device__ unsigned g_w1p[(size_t)L_*D_*F_];
__device__ unsigned g_w2p[(size_t)L_*F_*D_];

// ---------------- bf16 split helpers ---------------------------------------
__device__ __forceinline__ unsigned pack_bf16(float x0, float x1) {
    unsigned u;
    asm("cvt.rn.bf16x2.f32 %0, %1, %2;" : "=r"(u) : "f"(x1), "f"(x0));
    return u;
}
__device__ __forceinline__ void splitp_bf16(float a, float b, unsigned& h, unsigned& l)
{
    h = pack_bf16(a, b);
    const float ha = __uint_as_float(h << 16);
    const float hb = __uint_as_float(h & 0xffff0000u);
    l = pack_bf16(a - ha, b - hb);
}

__device__ __forceinline__ void mma_bf16(float c[4],
    unsigned a0, unsigned a1, unsigned a2, unsigned a3,
    unsigned b0, unsigned b1)
{
    asm volatile(
        "mma.sync.aligned.m16n8k16.row.col.f32.bf16.bf16.f32 "
        "{%0,%1,%2,%3}, {%4,%5,%6,%7}, {%8,%9}, {%0,%1,%2,%3};"
        : "+f"(c[0]), "+f"(c[1]), "+f"(c[2]), "+f"(c[3])
        : "r"(a0), "r"(a1), "r"(a2), "r"(a3), "r"(b0), "r"(b1));
}

__device__ __forceinline__ void cp16(uint32_t dst, const void* src) {
    asm volatile("cp.async.cg.shared.global [%0], [%1], 16;"
                 :: "r"(dst), "l"(src) : "memory");
}
#define CP_COMMIT() asm volatile("cp.async.commit_group;" ::: "memory")
#define CP_WAIT1()  asm volatile("cp.async.wait_group 1;" ::: "memory")
#define CP_WAIT0()  asm volatile("cp.async.wait_group 0;" ::: "memory")

// A-frag index: element (row r, k-pair p), KT = K/32 k-tiles (granularity 32)
__device__ __forceinline__ size_t afr_index(int r, int p, int KT) {
    const int gmt = r >> 4, rr = r & 15;
    const int kt = p >> 4, step = (p >> 3) & 1, pp = p & 7;
    const int lane = (rr & 7) * 4 + (pp & 3);
    const int reg  = (rr >> 3) + ((pp >> 2) << 1);
    return (((size_t)gmt * KT + kt) * 4 + step * 2) * 128 + lane * 4 + reg;
}

// ---------------- prep kernels (vectorized) ---------------------------------
__global__ void wsplit(const float* __restrict__ in, unsigned* __restrict__ out,
                       int K, int N)
{
    const size_t half = (size_t)(K / 2) * N;
    in  += (size_t)blockIdx.z * K * N;
    out += (size_t)blockIdx.z * K * N;
    const int n4 = N >> 2;
    const int total = (K >> 1) * n4;
    for (int idx = blockIdx.x * 256 + threadIdx.x; idx < total;
         idx += gridDim.x * 256) {
        const int p  = idx / n4;
        const int nq = (idx - p * n4) * 4;
        const float4 r0 = *(const float4*)(in + (size_t)(2 * p)     * N + nq);
        const float4 r1 = *(const float4*)(in + (size_t)(2 * p + 1) * N + nq);
        uint4 h, l;
        splitp_bf16(r0.x, r1.x, h.x, l.x);
        splitp_bf16(r0.y, r1.y, h.y, l.y);
        splitp_bf16(r0.z, r1.z, h.z, l.z);
        splitp_bf16(r0.w, r1.w, h.w, l.w);
        *(uint4*)(out + (size_t)p * N + nq) = h;
        *(uint4*)(out + half + (size_t)p * N + nq) = l;
    }
}

__global__ void asplit(const float* __restrict__ in, unsigned* __restrict__ out,
                       int K)
{
    const int KP = K / 2, KT = K / 32;
    const int total = T_ * KP;
    for (int idx = blockIdx.x * 256 + threadIdx.x; idx < total;
         idx += gridDim.x * 256) {
        const int t = idx / KP, p = idx % KP;
        unsigned h, l;
        splitp_bf16(in[(size_t)t * K + 2 * p], in[(size_t)t * K + 2 * p + 1], h, l);
        const size_t o = afr_index(t, p, KT);
        out[o] = h;
        out[o + 128] = l;
    }
}

// ---------------- tensor-core GEMM (bf16 3-term, TBK=64, 3-stage) ----------
#define TBM 128
#define TBN 128
#define B_STU 136
#define AFRAG_U 8192
#define OFF_B 8192
#define STAGE_U (AFRAG_U + 2*32*B_STU)   // 16896
#define NSTAGE 3
#define SMEM_BYTES (NSTAGE*STAGE_U*4)    // 202752

__global__ __launch_bounds__(256, 1) void gemm_tc(
    const unsigned* __restrict__ Afr,
    const unsigned* __restrict__ Bp0, const unsigned* __restrict__ Bp1,
    const unsigned* __restrict__ Bp2,
    const float* __restrict__ bias0s, const float* __restrict__ bias1s,
    const float* __restrict__ bias2s,
    const float* __restrict__ biasadd,
    const float* __restrict__ rowvec, const float* __restrict__ colvec,
    const float* __restrict__ residual,
    float* __restrict__ C0, float* __restrict__ C1, float* __restrict__ C2,
    unsigned* __restrict__ Cfr,
    int M, int N, int K, int gelu_flag)
{
    extern __shared__ unsigned smbuf[];
    const uint32_t smu = (uint32_t)__cvta_generic_to_shared(smbuf);

    const int tid  = threadIdx.x;
    const int warp = tid >> 5;
    const int lane = tid & 31;
    const int g    = lane >> 2;
    const int tig  = lane & 3;
    const int wmt  = (warp >> 2) * 4;
    const int wm   = wmt * 16;
    const int wn   = (warp & 3) * 32;

    const int nxb  = N / TBN;
    const int seg  = blockIdx.x / nxb;
    const int col0 = (blockIdx.x - seg * nxb) * TBN;
    const int row0 = blockIdx.y * TBM;
    const int KT   = K >> 5;
    const int gmt0 = row0 >> 4;
    const size_t bplane = (size_t)(K >> 1) * N;

    const unsigned* Bp = (seg == 0) ? Bp0 : (seg == 1) ? Bp1 : Bp2;
    const float* bias  = (seg == 0) ? bias0s : (seg == 1) ? bias1s : bias2s;
    float* Cg          = (seg == 0) ? C0 : (seg == 1) ? C1 : C2;

    auto issue = [&](int kt2, int stg) {
        const uint32_t base = smu + stg * STAGE_U * 4;
        #pragma unroll
        for (int u = 0; u < 8; u++) {
            const int s = tid + u * 256;
            const int f = s >> 5, w16 = s & 31;
            const int mt8 = f >> 3, sub = f & 7;
            const int half = sub >> 2, rem = sub & 3;
            const unsigned* src = Afr +
                ((((size_t)(gmt0 + mt8) * KT + kt2 * 2 + half) * 4 + rem) * 128)
                + w16 * 4;
            cp16(base + (f * 128 + w16 * 4) * 4, src);
        }
        #pragma unroll
        for (int u = 0; u < 8; u++) {
            const int s = tid + u * 256;
            const int hl = s >> 10, rem = s & 1023;
            const int p = rem >> 5, w16 = rem & 31;
            const unsigned* src = Bp + (size_t)hl * bplane +
                (size_t)(kt2 * 32 + p) * N + col0 + w16 * 4;
            cp16(base + (OFF_B + hl * 32 * B_STU + p * B_STU + w16 * 4) * 4, src);
        }
        CP_COMMIT();
    };

    float acc[4][4][4];
    #pragma unroll
    for (int mt = 0; mt < 4; mt++)
        #pragma unroll
        for (int nt = 0; nt < 4; nt++)
            #pragma unroll
            for (int r = 0; r < 4; r++) acc[mt][nt][r] = 0.f;

    const int nk = K >> 6;
    issue(0, 0);
    issue(1, 1);

    for (int ki = 0; ki < nk; ki++) {
        if (ki + 1 < nk) { CP_WAIT1(); } else { CP_WAIT0(); }
        __syncthreads();
        if (ki + 2 < nk) issue(ki + 2, (ki + 2) % NSTAGE);

        const unsigned* cur = smbuf + (ki % NSTAGE) * STAGE_U;
        const unsigned* Bh = cur + OFF_B;
        const unsigned* Bl = cur + OFF_B + 32 * B_STU;
        #pragma unroll
        for (int half = 0; half < 2; half++) {
            #pragma unroll
            for (int st = 0; st < 2; st++) {
                const int pb = half * 16 + st * 8;
                unsigned ah[4][4], al[4][4];
                #pragma unroll
                for (int mt = 0; mt < 4; mt++) {
                    const int fb = (wmt + mt) * 8 + half * 4 + st * 2;
                    uint4 av = *(const uint4*)&cur[fb * 128 + lane * 4];
                    ah[mt][0] = av.x; ah[mt][1] = av.y; ah[mt][2] = av.z; ah[mt][3] = av.w;
                    uint4 lv = *(const uint4*)&cur[(fb + 1) * 128 + lane * 4];
                    al[mt][0] = lv.x; al[mt][1] = lv.y; al[mt][2] = lv.z; al[mt][3] = lv.w;
                }
                unsigned bh[4][2], bl[4][2];
                #pragma unroll
                for (int nt = 0; nt < 4; nt++) {
                    const int n = wn + nt * 8 + g;
                    const int c0i = (pb + tig) * B_STU + n;
                    const int c1i = (pb + tig + 4) * B_STU + n;
                    bh[nt][0] = Bh[c0i]; bh[nt][1] = Bh[c1i];
                    bl[nt][0] = Bl[c0i]; bl[nt][1] = Bl[c1i];
                }
                #pragma unroll
                for (int mt = 0; mt < 4; mt++)
                    #pragma unroll
                    for (int nt = 0; nt < 4; nt++) {
                        mma_bf16(acc[mt][nt], ah[mt][0], ah[mt][1], ah[mt][2], ah[mt][3],
                                 bh[nt][0], bh[nt][1]);
                        mma_bf16(acc[mt][nt], al[mt][0], al[mt][1], al[mt][2], al[mt][3],
                                 bh[nt][0], bh[nt][1]);
                        mma_bf16(acc[mt][nt], ah[mt][0], ah[mt][1], ah[mt][2], ah[mt][3],
                                 bl[nt][0], bl[nt][1]);
                    }
            }
        }
    }
    __syncthreads();

    // ---- epilogue
    const int KTo = N >> 5;
    #pragma unroll
    for (int mt = 0; mt < 4; mt++) {
        #pragma unroll
        for (int half = 0; half < 2; half++) {
            const int r = row0 + wm + mt * 16 + g + half * 8;
            const float rv = rowvec ? rowvec[r] : 0.f;
            #pragma unroll
            for (int nt = 0; nt < 4; nt++) {
                const int c = col0 + wn + nt * 8 + 2 * tig;
                float v0 = acc[mt][nt][half * 2 + 0];
                float v1 = acc[mt][nt][half * 2 + 1];
                if (bias)    { v0 += bias[c];    v1 += bias[c + 1]; }
                if (biasadd) { v0 += biasadd[c]; v1 += biasadd[c + 1]; }
                if (rowvec)  { v0 += rv * colvec[c]; v1 += rv * colvec[c + 1]; }
                if (gelu_flag) {
                    v0 = 0.5f * v0 * (1.f + erff(v0 * 0.70710678118654752f));
                    v1 = 0.5f * v1 * (1.f + erff(v1 * 0.70710678118654752f));
                }
                if (residual) {
                    float2 rr = *(const float2*)(residual + (size_t)r * N + c);
                    v0 += rr.x; v1 += rr.y;
                }
                if (Cfr) {
                    unsigned h, l;
                    splitp_bf16(v0, v1, h, l);
                    const size_t o = afr_index(r, c >> 1, KTo);
                    Cfr[o] = h;
                    Cfr[o + 128] = l;
                } else {
                    float2 o; o.x = v0; o.y = v1;
                    *(float2*)(Cg + (size_t)r * N + c) = o;
                }
            }
        }
    }
}

// ---------------- LayerNorm: one block per token, frag-major split out -----
__global__ __launch_bounds__(256) void ln_kernel(
    const float* __restrict__ x, const float* __restrict__ g,
    const float* __restrict__ bta, unsigned* __restrict__ outf)
{
    const int t = blockIdx.x;
    const int tid = threadIdx.x;
    const float* xr = x + (size_t)t * D_;
    const int c4 = tid * 4;

    float4 v = *(const float4*)(xr + c4);
    float s  = v.x + v.y + v.z + v.w;
    float s2 = v.x*v.x + v.y*v.y + v.z*v.z + v.w*v.w;
    #pragma unroll
    for (int o = 16; o; o >>= 1) {
        s  += __shfl_xor_sync(0xffffffffu, s,  o);
        s2 += __shfl_xor_sync(0xffffffffu, s2, o);
    }
    __shared__ float ss[8], ss2[8];
    if ((tid & 31) == 0) { ss[tid >> 5] = s; ss2[tid >> 5] = s2; }
    __syncthreads();
    s = 0.f; s2 = 0.f;
    #pragma unroll
    for (int w = 0; w < 8; w++) { s += ss[w]; s2 += ss2[w]; }

    const float mean = s * (1.f / D_);
    const float var  = s2 * (1.f / D_) - mean * mean;
    const float inv  = rsqrtf(var + 1e-5f);

    const float4 gg = *(const float4*)(g + c4);
    const float4 bb = *(const float4*)(bta + c4);
    const float y0 = (v.x - mean) * inv * gg.x + bb.x;
    const float y1 = (v.y - mean) * inv * gg.y + bb.y;
    const float y2 = (v.z - mean) * inv * gg.z + bb.z;
    const float y3 = (v.w - mean) * inv * gg.w + bb.w;

    unsigned h, l;
    splitp_bf16(y0, y1, h, l);
    size_t o = afr_index(t, c4 >> 1, D_ / 32);
    outf[o] = h; outf[o + 128] = l;
    splitp_bf16(y2, y3, h, l);
    o = afr_index(t, (c4 >> 1) + 1, D_ / 32);
    outf[o] = h; outf[o + 128] = l;
}

// ---------------- flash attention v2: tensor-core QK and PV ----------------
// grid (S/64, B*H), block 256 (8 warps: warp-m = warp>>1, warp-n = warp&1).
// S acc layout doubles as the A-frag source for PV (register-only P convert).
#define FB_ST 68
#define FQ_OFF 0                         // Q A-frags: 4x4x2x128 = 4096 u32
#define FK_OFF 4096                      // K planes hi/lo: 2*32*68 = 4352
#define FV_OFF (4096 + 4352)             // V planes hi/lo: 4352
#define FST_OFF (4096 + 2*4352)          // pmax[2][64] + psum[2][64] = 256
#define FOC_OFF FK_OFF                   // O-combine aliases dead K region
#define FLASH_U (4096 + 2*4352 + 256)    // 13056
#define FLASH_SMEM (FLASH_U*4)           // 52224

__global__ __launch_bounds__(256) void flash_kernel(
    const float* __restrict__ q, const float* __restrict__ k,
    const float* __restrict__ v, const int* __restrict__ mask,
    unsigned* __restrict__ attnf)
{
    extern __shared__ unsigned fsm[];
    unsigned* Qf = fsm + FQ_OFF;
    unsigned* Kb = fsm + FK_OFF;
    unsigned* Vb = fsm + FV_OFF;
    float* pmax = (float*)(fsm + FST_OFF);        // [2][64]
    float* psum = (float*)(fsm + FST_OFF + 128);  // [2][64]
    float* Ocomb = (float*)(fsm + FOC_OFF);       // [64][65]

    const int bh = blockIdx.y;
    const int b = bh >> 4, h = bh & 15;
    const int qt = blockIdx.x * 64;

    const int tid  = threadIdx.x;
    const int warp = tid >> 5;
    const int lane = tid & 31;
    const int g    = lane >> 2;
    const int tig  = lane & 3;
    const int wms  = (warp >> 1) * 16;   // warp's 16 rows
    const int wns  = (warp & 1) * 32;    // warp's 32 keys
    const int wn_  = warp & 1;

    // RoPE freqs for this thread's dims jj..jj+3 (loader mapping)
    const int jj = (tid & 7) * 4;
    float invf[4];
    #pragma unroll
    for (int i2 = 0; i2 < 4; i2++)
        invf[i2] = powf(10000.f, -((float)(2*(jj+i2))) * (1.f / HD_));

    // ---- Q loader: rope + split into A-frag layout ----
    // frag index: ((mt*4 + kstep)*2 + hl)*128 + lane*4 + reg
    auto put_pair = [&](unsigned* base, int m, int p, float ve, float vo) {
        const int mt = m >> 4, rr = m & 15;
        const int kstep = p >> 3, pp = p & 7;
        const int fl = (rr & 7) * 4 + (pp & 3);
        const int rg = (rr >> 3) + ((pp >> 2) << 1);
        unsigned hh, ll;
        splitp_bf16(ve, vo, hh, ll);
        base[((mt * 4 + kstep) * 2 + 0) * 128 + fl * 4 + rg] = hh;
        base[((mt * 4 + kstep) * 2 + 1) * 128 + fl * 4 + rg] = ll;
    };
    #pragma unroll
    for (int it = 0; it < 2; it++) {
        const int m = (tid >> 3) + it * 32;
        const int qpos = qt + m;
        const float* qp = q + ((size_t)qpos * B_ + b) * D_ + h * HD_;
        float4 a  = *(const float4*)(qp + jj);
        float4 bb = *(const float4*)(qp + jj + 32);
        float d[4], e[4];
        float av[4] = {a.x, a.y, a.z, a.w};
        float bv[4] = {bb.x, bb.y, bb.z, bb.w};
        #pragma unroll
        for (int i2 = 0; i2 < 4; i2++) {
            float sn, cs;
            sincosf((float)qpos * invf[i2], &sn, &cs);
            d[i2] = av[i2]*cs - bv[i2]*sn;
            e[i2] = bv[i2]*cs + av[i2]*sn;
        }
        put_pair(Qf, m, (jj >> 1),      d[0], d[1]);
        put_pair(Qf, m, (jj >> 1) + 1,  d[2], d[3]);
        put_pair(Qf, m, (jj >> 1) + 16, e[0], e[1]);
        put_pair(Qf, m, (jj >> 1) + 17, e[2], e[3]);
    }

    float mrow0 = -3.0e38f, mrow1 = -3.0e38f;
    float ssum0 = 0.f, ssum1 = 0.f;
    float oacc[8][4];
    #pragma unroll
    for (int nt = 0; nt < 8; nt++)
        #pragma unroll
        for (int r = 0; r < 4; r++) oacc[nt][r] = 0.f;

    const float scale = 0.125f;
    const int mt_q = warp >> 1;

    for (int kt = 0; kt < S_; kt += 64) {
        // ---- K loader: rope + split into [dim-pair][key] planes ----
        #pragma unroll
        for (int it = 0; it < 2; it++) {
            const int m = (tid >> 3) + it * 32;      // key
            const int kpos = kt + m;
            const float* kp = k + ((size_t)kpos * B_ + b) * D_ + h * HD_;
            float4 a  = *(const float4*)(kp + jj);
            float4 bb = *(const float4*)(kp + jj + 32);
            float av[4] = {a.x, a.y, a.z, a.w};
            float bv[4] = {bb.x, bb.y, bb.z, bb.w};
            float d[4], e[4];
            #pragma unroll
            for (int i2 = 0; i2 < 4; i2++) {
                float sn, cs;
                sincosf((float)kpos * invf[i2], &sn, &cs);
                d[i2] = av[i2]*cs - bv[i2]*sn;
                e[i2] = bv[i2]*cs + av[i2]*sn;
            }
            unsigned hh, ll;
            const int p0 = jj >> 1;
            splitp_bf16(d[0], d[1], hh, ll);
            Kb[p0*FB_ST + m] = hh; Kb[(32+p0)*FB_ST + m] = ll;
            splitp_bf16(d[2], d[3], hh, ll);
            Kb[(p0+1)*FB_ST + m] = hh; Kb[(32+p0+1)*FB_ST + m] = ll;
            splitp_bf16(e[0], e[1], hh, ll);
            Kb[(p0+16)*FB_ST + m] = hh; Kb[(32+p0+16)*FB_ST + m] = ll;
            splitp_bf16(e[2], e[3], hh, ll);
            Kb[(p0+17)*FB_ST + m] = hh; Kb[(32+p0+17)*FB_ST + m] = ll;
        }
        // ---- V loader: split cross key-pairs into [key-pair][dim] planes ----
        #pragma unroll
        for (int it = 0; it < 2; it++) {
            const int s = tid + it * 256;
            const int kp2 = s >> 4;          // key-pair 0..31
            const int dq  = (s & 15) * 4;    // dim
            const float* v0 = v + ((size_t)(kt + 2*kp2)     * B_ + b) * D_ + h*HD_ + dq;
            const float* v1 = v + ((size_t)(kt + 2*kp2 + 1) * B_ + b) * D_ + h*HD_ + dq;
            float4 r0 = *(const float4*)v0;
            float4 r1 = *(const float4*)v1;
            uint4 hh, ll;
            splitp_bf16(r0.x, r1.x, hh.x, ll.x);
            splitp_bf16(r0.y, r1.y, hh.y, ll.y);
            splitp_bf16(r0.z, r1.z, hh.z, ll.z);
            splitp_bf16(r0.w, r1.w, hh.w, ll.w);
            *(uint4*)&Vb[kp2*FB_ST + dq] = hh;
            *(uint4*)&Vb[(32+kp2)*FB_ST + dq] = ll;
        }
        __syncthreads();

        // ---- S = scale * Q K^T via split mma ----
        float sacc[4][4];
        #pragma unroll
        for (int nt = 0; nt < 4; nt++)
            #pragma unroll
            for (int r = 0; r < 4; r++) sacc[nt][r] = 0.f;
        #pragma unroll
        for (int kstep = 0; kstep < 4; kstep++) {
            const int fb = (mt_q * 4 + kstep) * 2;
            uint4 av = *(const uint4*)&Qf[fb * 128 + lane * 4];
            uint4 lv = *(const uint4*)&Qf[(fb + 1) * 128 + lane * 4];
            #pragma unroll
            for (int nt = 0; nt < 4; nt++) {
                const int n = wns + nt * 8 + g;
                const unsigned bh0 = Kb[(kstep*8 + tig)*FB_ST + n];
                const unsigned bh1 = Kb[(kstep*8 + tig + 4)*FB_ST + n];
                const unsigned bl0 = Kb[(32 + kstep*8 + tig)*FB_ST + n];
                const unsigned bl1 = Kb[(32 + kstep*8 + tig + 4)*FB_ST + n];
                mma_bf16(sacc[nt], av.x, av.y, av.z, av.w, bh0, bh1);
                mma_bf16(sacc[nt], lv.x, lv.y, lv.z, lv.w, bh0, bh1);
                mma_bf16(sacc[nt], av.x, av.y, av.z, av.w, bl0, bl1);
            }
        }
        // ---- scale + mask ----
        #pragma unroll
        for (int nt = 0; nt < 4; nt++) {
            const int c0 = kt + wns + nt * 8 + 2 * tig;
            const bool m0 = (mask[b*S_ + c0] != 0);
            const bool m1 = (mask[b*S_ + c0 + 1] != 0);
            sacc[nt][0] = m0 ? -1e30f : sacc[nt][0] * scale;
            sacc[nt][2] = m0 ? -1e30f : sacc[nt][2] * scale;
            sacc[nt][1] = m1 ? -1e30f : sacc[nt][1] * scale;
            sacc[nt][3] = m1 ? -1e30f : sacc[nt][3] * scale;
        }
        // ---- partial row max (tig-group reduce) ----
        float rm0 = -3.0e38f, rm1 = -3.0e38f;
        #pragma unroll
        for (int nt = 0; nt < 4; nt++) {
            rm0 = fmaxf(rm0, fmaxf(sacc[nt][0], sacc[nt][1]));
            rm1 = fmaxf(rm1, fmaxf(sacc[nt][2], sacc[nt][3]));
        }
        #pragma unroll
        for (int o = 1; o < 4; o <<= 1) {
            rm0 = fmaxf(rm0, __shfl_xor_sync(0xffffffffu, rm0, o));
            rm1 = fmaxf(rm1, __shfl_xor_sync(0xffffffffu, rm1, o));
        }
        if (tig == 0) {
            pmax[wn_ * 64 + wms + g]     = rm0;
            pmax[wn_ * 64 + wms + g + 8] = rm1;
        }
        __syncthreads();
        const float mnew0 = fmaxf(mrow0, fmaxf(pmax[wms + g],     pmax[64 + wms + g]));
        const float mnew1 = fmaxf(mrow1, fmaxf(pmax[wms + g + 8], pmax[64 + wms + g + 8]));
        const float corr0 = __expf(mrow0 - mnew0);
        const float corr1 = __expf(mrow1 - mnew1);
        float rs0 = 0.f, rs1 = 0.f;
        #pragma unroll
        for (int nt = 0; nt < 4; nt++) {
            sacc[nt][0] = __expf(sacc[nt][0] - mnew0);
            sacc[nt][1] = __expf(sacc[nt][1] - mnew0);
            sacc[nt][2] = __expf(sacc[nt][2] - mnew1);
            sacc[nt][3] = __expf(sacc[nt][3] - mnew1);
            rs0 += sacc[nt][0] + sacc[nt][1];
            rs1 += sacc[nt][2] + sacc[nt][3];
        }
        #pragma unroll
        for (int o = 1; o < 4; o <<= 1) {
            rs0 += __shfl_xor_sync(0xffffffffu, rs0, o);
            rs1 += __shfl_xor_sync(0xffffffffu, rs1, o);
        }
        if (tig == 0) {
            psum[wn_ * 64 + wms + g]     = rs0;
            psum[wn_ * 64 + wms + g + 8] = rs1;
        }
        __syncthreads();
        ssum0 = ssum0 * corr0 + psum[wms + g]     + psum[64 + wms + g];
        ssum1 = ssum1 * corr1 + psum[wms + g + 8] + psum[64 + wms + g + 8];
        mrow0 = mnew0; mrow1 = mnew1;
        #pragma unroll
        for (int nt = 0; nt < 8; nt++) {
            oacc[nt][0] *= corr0; oacc[nt][1] *= corr0;
            oacc[nt][2] *= corr1; oacc[nt][3] *= corr1;
        }

        // ---- O += P V via split mma (P from registers) ----
        #pragma unroll
        for (int st = 0; st < 2; st++) {
            unsigned pa[4], pl[4];
            splitp_bf16(sacc[st*2][0],   sacc[st*2][1],   pa[0], pl[0]);
            splitp_bf16(sacc[st*2][2],   sacc[st*2][3],   pa[1], pl[1]);
            splitp_bf16(sacc[st*2+1][0], sacc[st*2+1][1], pa[2], pl[2]);
            splitp_bf16(sacc[st*2+1][2], sacc[st*2+1][3], pa[3], pl[3]);
            const int kpb = (wns >> 1) + st * 8;
            #pragma unroll
            for (int nt = 0; nt < 8; nt++) {
                const int dd = nt * 8 + g;
                const unsigned bh0 = Vb[(kpb + tig)*FB_ST + dd];
                const unsigned bh1 = Vb[(kpb + tig + 4)*FB_ST + dd];
                const unsigned bl0 = Vb[(32 + kpb + tig)*FB_ST + dd];
                const unsigned bl1 = Vb[(32 + kpb + tig + 4)*FB_ST + dd];
                mma_bf16(oacc[nt], pa[0], pa[1], pa[2], pa[3], bh0, bh1);
                mma_bf16(oacc[nt], pl[0], pl[1], pl[2], pl[3], bh0, bh1);
                mma_bf16(oacc[nt], pa[0], pa[1], pa[2], pa[3], bl0, bl1);
            }
        }
        __syncthreads();   // before next tile's loaders overwrite Kb/Vb
    }

    // ---- combine warp-n halves, normalize, write frag-major ----
    if (wn_ == 1) {
        #pragma unroll
        for (int nt = 0; nt < 8; nt++) {
            const int dd = nt * 8 + 2 * tig;
            Ocomb[(wms + g)     * 65 + dd]     = oacc[nt][0];
            Ocomb[(wms + g)     * 65 + dd + 1] = oacc[nt][1];
            Ocomb[(wms + g + 8) * 65 + dd]     = oacc[nt][2];
            Ocomb[(wms + g + 8) * 65 + dd + 1] = oacc[nt][3];
        }
    }
    __syncthreads();
    if (wn_ == 0) {
        const float n0 = 1.f / ssum0;
        const float n1 = 1.f / ssum1;
        const int r0 = wms + g, r1 = wms + g + 8;
        const int t0 = (qt + r0) * B_ + b;
        const int t1 = (qt + r1) * B_ + b;
        #pragma unroll
        for (int nt = 0; nt < 8; nt++) {
            const int dd = nt * 8 + 2 * tig;
            const float a0 = (oacc[nt][0] + Ocomb[r0 * 65 + dd])     * n0;
            const float a1 = (oacc[nt][1] + Ocomb[r0 * 65 + dd + 1]) * n0;
            const float a2 = (oacc[nt][2] + Ocomb[r1 * 65 + dd])     * n1;
            const float a3 = (oacc[nt][3] + Ocomb[r1 * 65 + dd + 1]) * n1;
            unsigned hh, ll;
            const int cp = (h * HD_ + dd) >> 1;
            splitp_bf16(a0, a1, hh, ll);
            size_t o = afr_index(t0, cp, D_ / 32);
            attnf[o] = hh; attnf[o + 128] = ll;
            splitp_bf16(a2, a3, hh, ll);
            o = afr_index(t1, cp, D_ / 32);
            attnf[o] = hh; attnf[o + 128] = ll;
        }
    }
}

// ---------------- host orchestration ---------------------------------------
extern "C" void kernel_launch(void* const* d_in, const int* in_sizes, int n_in,
                              void* d_out, int out_size)
{
    (void)in_sizes; (void)n_in; (void)out_size;

    const float* segments  = (const float*)d_in[0];
    const float* durations = (const float*)d_in[1];
    const int*   padmask   = (const int*)d_in[2];
    const float* Wproj = (const float*)d_in[3];
    const float* bproj = (const float*)d_in[4];
    const float* Wdur  = (const float*)d_in[5];
    const float* bdur  = (const float*)d_in[6];
    const float* ln1_g = (const float*)d_in[7];
    const float* ln1_b = (const float*)d_in[8];
    const float* Wq = (const float*)d_in[9];
    const float* bq = (const float*)d_in[10];
    const float* Wk = (const float*)d_in[11];
    const float* bk = (const float*)d_in[12];
    const float* Wv = (const float*)d_in[13];
    const float* bv = (const float*)d_in[14];
    const float* Wo = (const float*)d_in[15];
    const float* bo = (const float*)d_in[16];
    const float* ln2_g = (const float*)d_in[17];
    const float* ln2_b = (const float*)d_in[18];
    const float* Wff1 = (const float*)d_in[19];
    const float* bff1 = (const float*)d_in[20];
    const float* Wff2 = (const float*)d_in[21];
    const float* bff2 = (const float*)d_in[22];

    float* x = (float*)d_out;

    float *q, *k, *v;
    unsigned *segf, *hf, *attnf, *fff;
    unsigned *wprojp, *wqp, *wkp, *wvp, *wop, *w1p, *w2p;
    cudaGetSymbolAddress((void**)&q,      g_q);
    cudaGetSymbolAddress((void**)&k,      g_k);
    cudaGetSymbolAddress((void**)&v,      g_v);
    cudaGetSymbolAddress((void**)&segf,   g_segf);
    cudaGetSymbolAddress((void**)&hf,     g_hf);
    cudaGetSymbolAddress((void**)&attnf,  g_attnf);
    cudaGetSymbolAddress((void**)&fff,    g_fff);
    cudaGetSymbolAddress((void**)&wprojp, g_wprojp);
    cudaGetSymbolAddress((void**)&wqp,    g_wqp);
    cudaGetSymbolAddress((void**)&wkp,    g_wkp);
    cudaGetSymbolAddress((void**)&wvp,    g_wvp);
    cudaGetSymbolAddress((void**)&wop,    g_wop);
    cudaGetSymbolAddress((void**)&w1p,    g_w1p);
    cudaGetSymbolAddress((void**)&w2p,    g_w2p);

    cudaFuncSetAttribute(gemm_tc,
        cudaFuncAttributeMaxDynamicSharedMemorySize, SMEM_BYTES);
    cudaFuncSetAttribute(flash_kernel,
        cudaFuncAttributeMaxDynamicSharedMemorySize, FLASH_SMEM);

    // ---- prep pass (vectorized splitters)
    asplit<<<1184, 256>>>(segments, segf, DIN_);
    wsplit<<<dim3(296, 1, 1),  256>>>(Wproj, wprojp, DIN_, D_);
    wsplit<<<dim3(128, 1, L_), 256>>>(Wq, wqp, D_, D_);
    wsplit<<<dim3(128, 1, L_), 256>>>(Wk, wkp, D_, D_);
    wsplit<<<dim3(128, 1, L_), 256>>>(Wv, wvp, D_, D_);
    wsplit<<<dim3(128, 1, L_), 256>>>(Wo, wop, D_, D_);
    wsplit<<<dim3(512, 1, L_), 256>>>(Wff1, w1p, D_, F_);
    wsplit<<<dim3(512, 1, L_), 256>>>(Wff2, w2p, F_, D_);

    const dim3 blk(256);

    // proj: x = segments @ Wproj + bproj + durations*Wdur + bdur
    gemm_tc<<<dim3(D_/TBN, T_/TBM), blk, SMEM_BYTES>>>(
        segf, wprojp, wprojp, wprojp, bproj, bproj, bproj, bdur,
        durations, Wdur, nullptr,
        x, x, x, nullptr, T_, D_, DIN_, 0);

    for (int l = 0; l < L_; l++) {
        const size_t od = (size_t)l*D_*D_;
        const size_t o1 = (size_t)l*D_*F_;
        const size_t o2 = (size_t)l*F_*D_;

        ln_kernel<<<T_, 256>>>(x, ln1_g + l*D_, ln1_b + l*D_, hf);

        // fused QKV: 3 segments, grid 24 x 16 = 384 CTAs
        gemm_tc<<<dim3(3*D_/TBN, T_/TBM), blk, SMEM_BYTES>>>(
            hf, wqp + od, wkp + od, wvp + od,
            bq + l*D_, bk + l*D_, bv + l*D_, nullptr,
            nullptr, nullptr, nullptr,
            q, k, v, nullptr, T_, D_, D_, 0);

        // flash attention v2 (tensor-core QK/PV, fused RoPE)
        flash_kernel<<<dim3(S_/64, B_*H_), blk, FLASH_SMEM>>>(
            q, k, v, padmask, attnf);

        // x = x + attn @ Wo + bo
        gemm_tc<<<dim3(D_/TBN, T_/TBM), blk, SMEM_BYTES>>>(
            attnf, wop + od, wop + od, wop + od,
            bo + l*D_, bo + l*D_, bo + l*D_, nullptr,
            nullptr, nullptr, x,
            x, x, x, nullptr, T_, D_, D_, 0);

        ln_kernel<<<T_, 256>>>(x, ln2_g + l*D_, ln2_b + l*D_, hf);

        // ff = gelu(h @ W1 + b1), frag-major output
        gemm_tc<<<dim3(F_/TBN, T_/TBM), blk, SMEM_BYTES>>>(
            hf, w1p + o1, w1p + o1, w1p + o1,
            bff1 + l*F_, bff1 + l*F_, bff1 + l*F_, nullptr,
            nullptr, nullptr, nullptr,
            nullptr, nullptr, nullptr, fff, T_, F_, D_, 1);

        // x = x + ff @ W2 + b2
        gemm_tc<<<dim3(D_/TBN, T_/TBM), blk, SMEM_BYTES>>>(
            fff, w2p + o2, w2p + o2, w2p + o2,
            bff2 + l*D_, bff2 + l*D_, bff2 + l*D_, nullptr,
            nullptr, nullptr, x,
            x, x, x, nullptr, T_, D_, F_, 0);
    }
}

// round 17
// speedup vs baseline: 1.3283x; 1.0060x over previous
#include <cuda_runtime.h>
#include <math.h>
#include <stdint.h>

#define L_   12
#define S_   512
#define B_   4
#define DIN_ 768
#define D_   1024
#define H_   16
#define F_   4096
#define HD_  64
#define T_   (S_*B_)   // 2048 tokens

// ---------------- scratch (static device globals; no runtime allocation) ----
__device__ float g_q[T_*D_];
__device__ float g_k[T_*D_];
__device__ float g_v[T_*D_];

// frag-major bf16x2 hi/lo activation buffers
__device__ unsigned g_segf[T_*DIN_];
__device__ unsigned g_hf[T_*D_];
__device__ unsigned g_attnf[T_*D_];
__device__ unsigned g_fff[(size_t)T_*F_];

// packed k-pair bf16x2 hi/lo weight planes ([layer][2 planes][K/2][N] u32)
__device__ unsigned g_wprojp[DIN_*D_];
__device__ unsigned g_wqp[(size_t)L_*D_*D_];
__device__ unsigned g_wkp[(size_t)L_*D_*D_];
__device__ unsigned g_wvp[(size_t)L_*D_*D_];
__device__ unsigned g_wop[(size_t)L_*D_*D_];
__device__ unsigned g_w1p[(size_t)L_*D_*F_];
__device__ unsigned g_w2p[(size_t)L_*F_*D_];

// ---------------- bf16 split helpers ---------------------------------------
__device__ __forceinline__ unsigned pack_bf16(float x0, float x1) {
    unsigned u;
    asm("cvt.rn.bf16x2.f32 %0, %1, %2;" : "=r"(u) : "f"(x1), "f"(x0));
    return u;
}
__device__ __forceinline__ void splitp_bf16(float a, float b, unsigned& h, unsigned& l)
{
    h = pack_bf16(a, b);
    const float ha = __uint_as_float(h << 16);
    const float hb = __uint_as_float(h & 0xffff0000u);
    l = pack_bf16(a - ha, b - hb);
}

__device__ __forceinline__ void mma_bf16(float c[4],
    unsigned a0, unsigned a1, unsigned a2, unsigned a3,
    unsigned b0, unsigned b1)
{
    asm volatile(
        "mma.sync.aligned.m16n8k16.row.col.f32.bf16.bf16.f32 "
        "{%0,%1,%2,%3}, {%4,%5,%6,%7}, {%8,%9}, {%0,%1,%2,%3};"
        : "+f"(c[0]), "+f"(c[1]), "+f"(c[2]), "+f"(c[3])
        : "r"(a0), "r"(a1), "r"(a2), "r"(a3), "r"(b0), "r"(b1));
}

__device__ __forceinline__ void cp16(uint32_t dst, const void* src) {
    asm volatile("cp.async.cg.shared.global [%0], [%1], 16;"
                 :: "r"(dst), "l"(src) : "memory");
}
#define CP_COMMIT() asm volatile("cp.async.commit_group;" ::: "memory")
#define CP_WAIT1()  asm volatile("cp.async.wait_group 1;" ::: "memory")
#define CP_WAIT0()  asm volatile("cp.async.wait_group 0;" ::: "memory")

// A-frag index: element (row r, k-pair p), KT = K/32 k-tiles (granularity 32)
__device__ __forceinline__ size_t afr_index(int r, int p, int KT) {
    const int gmt = r >> 4, rr = r & 15;
    const int kt = p >> 4, step = (p >> 3) & 1, pp = p & 7;
    const int lane = (rr & 7) * 4 + (pp & 3);
    const int reg  = (rr >> 3) + ((pp >> 2) << 1);
    return (((size_t)gmt * KT + kt) * 4 + step * 2) * 128 + lane * 4 + reg;
}

// ---------------- prep kernels (vectorized) ---------------------------------
__global__ void wsplit(const float* __restrict__ in, unsigned* __restrict__ out,
                       int K, int N)
{
    const size_t half = (size_t)(K / 2) * N;
    in  += (size_t)blockIdx.z * K * N;
    out += (size_t)blockIdx.z * K * N;
    const int n4 = N >> 2;
    const int total = (K >> 1) * n4;
    for (int idx = blockIdx.x * 256 + threadIdx.x; idx < total;
         idx += gridDim.x * 256) {
        const int p  = idx / n4;
        const int nq = (idx - p * n4) * 4;
        const float4 r0 = *(const float4*)(in + (size_t)(2 * p)     * N + nq);
        const float4 r1 = *(const float4*)(in + (size_t)(2 * p + 1) * N + nq);
        uint4 h, l;
        splitp_bf16(r0.x, r1.x, h.x, l.x);
        splitp_bf16(r0.y, r1.y, h.y, l.y);
        splitp_bf16(r0.z, r1.z, h.z, l.z);
        splitp_bf16(r0.w, r1.w, h.w, l.w);
        *(uint4*)(out + (size_t)p * N + nq) = h;
        *(uint4*)(out + half + (size_t)p * N + nq) = l;
    }
}

__global__ void asplit(const float* __restrict__ in, unsigned* __restrict__ out,
                       int K)
{
    const int KP = K / 2, KT = K / 32;
    const int total = T_ * KP;
    for (int idx = blockIdx.x * 256 + threadIdx.x; idx < total;
         idx += gridDim.x * 256) {
        const int t = idx / KP, p = idx % KP;
        unsigned h, l;
        splitp_bf16(in[(size_t)t * K + 2 * p], in[(size_t)t * K + 2 * p + 1], h, l);
        const size_t o = afr_index(t, p, KT);
        out[o] = h;
        out[o + 128] = l;
    }
}

// ---------------- tensor-core GEMM (bf16 3-term, TBK=64, 3-stage) ----------
#define TBM 128
#define TBN 128
#define B_STU 136
#define AFRAG_U 8192
#define OFF_B 8192
#define STAGE_U (AFRAG_U + 2*32*B_STU)   // 16896
#define NSTAGE 3
#define SMEM_BYTES (NSTAGE*STAGE_U*4)    // 202752

__global__ __launch_bounds__(256, 1) void gemm_tc(
    const unsigned* __restrict__ Afr,
    const unsigned* __restrict__ Bp0, const unsigned* __restrict__ Bp1,
    const unsigned* __restrict__ Bp2,
    const float* __restrict__ bias0s, const float* __restrict__ bias1s,
    const float* __restrict__ bias2s,
    const float* __restrict__ biasadd,
    const float* __restrict__ rowvec, const float* __restrict__ colvec,
    const float* __restrict__ residual,
    float* __restrict__ C0, float* __restrict__ C1, float* __restrict__ C2,
    unsigned* __restrict__ Cfr,
    int M, int N, int K, int gelu_flag)
{
    extern __shared__ unsigned smbuf[];
    const uint32_t smu = (uint32_t)__cvta_generic_to_shared(smbuf);

    const int tid  = threadIdx.x;
    const int warp = tid >> 5;
    const int lane = tid & 31;
    const int g    = lane >> 2;
    const int tig  = lane & 3;
    const int wmt  = (warp >> 2) * 4;
    const int wm   = wmt * 16;
    const int wn   = (warp & 3) * 32;

    const int nxb  = N / TBN;
    const int seg  = blockIdx.x / nxb;
    const int col0 = (blockIdx.x - seg * nxb) * TBN;
    const int row0 = blockIdx.y * TBM;
    const int KT   = K >> 5;
    const int gmt0 = row0 >> 4;
    const size_t bplane = (size_t)(K >> 1) * N;

    const unsigned* Bp = (seg == 0) ? Bp0 : (seg == 1) ? Bp1 : Bp2;
    const float* bias  = (seg == 0) ? bias0s : (seg == 1) ? bias1s : bias2s;
    float* Cg          = (seg == 0) ? C0 : (seg == 1) ? C1 : C2;

    auto issue = [&](int kt2, int stg) {
        const uint32_t base = smu + stg * STAGE_U * 4;
        #pragma unroll
        for (int u = 0; u < 8; u++) {
            const int s = tid + u * 256;
            const int f = s >> 5, w16 = s & 31;
            const int mt8 = f >> 3, sub = f & 7;
            const int half = sub >> 2, rem = sub & 3;
            const unsigned* src = Afr +
                ((((size_t)(gmt0 + mt8) * KT + kt2 * 2 + half) * 4 + rem) * 128)
                + w16 * 4;
            cp16(base + (f * 128 + w16 * 4) * 4, src);
        }
        #pragma unroll
        for (int u = 0; u < 8; u++) {
            const int s = tid + u * 256;
            const int hl = s >> 10, rem = s & 1023;
            const int p = rem >> 5, w16 = rem & 31;
            const unsigned* src = Bp + (size_t)hl * bplane +
                (size_t)(kt2 * 32 + p) * N + col0 + w16 * 4;
            cp16(base + (OFF_B + hl * 32 * B_STU + p * B_STU + w16 * 4) * 4, src);
        }
        CP_COMMIT();
    };

    float acc[4][4][4];
    #pragma unroll
    for (int mt = 0; mt < 4; mt++)
        #pragma unroll
        for (int nt = 0; nt < 4; nt++)
            #pragma unroll
            for (int r = 0; r < 4; r++) acc[mt][nt][r] = 0.f;

    const int nk = K >> 6;
    issue(0, 0);
    issue(1, 1);

    for (int ki = 0; ki < nk; ki++) {
        if (ki + 1 < nk) { CP_WAIT1(); } else { CP_WAIT0(); }
        __syncthreads();
        if (ki + 2 < nk) issue(ki + 2, (ki + 2) % NSTAGE);

        const unsigned* cur = smbuf + (ki % NSTAGE) * STAGE_U;
        const unsigned* Bh = cur + OFF_B;
        const unsigned* Bl = cur + OFF_B + 32 * B_STU;
        #pragma unroll
        for (int half = 0; half < 2; half++) {
            #pragma unroll
            for (int st = 0; st < 2; st++) {
                const int pb = half * 16 + st * 8;
                unsigned ah[4][4], al[4][4];
                #pragma unroll
                for (int mt = 0; mt < 4; mt++) {
                    const int fb = (wmt + mt) * 8 + half * 4 + st * 2;
                    uint4 av = *(const uint4*)&cur[fb * 128 + lane * 4];
                    ah[mt][0] = av.x; ah[mt][1] = av.y; ah[mt][2] = av.z; ah[mt][3] = av.w;
                    uint4 lv = *(const uint4*)&cur[(fb + 1) * 128 + lane * 4];
                    al[mt][0] = lv.x; al[mt][1] = lv.y; al[mt][2] = lv.z; al[mt][3] = lv.w;
                }
                unsigned bh[4][2], bl[4][2];
                #pragma unroll
                for (int nt = 0; nt < 4; nt++) {
                    const int n = wn + nt * 8 + g;
                    const int c0i = (pb + tig) * B_STU + n;
                    const int c1i = (pb + tig + 4) * B_STU + n;
                    bh[nt][0] = Bh[c0i]; bh[nt][1] = Bh[c1i];
                    bl[nt][0] = Bl[c0i]; bl[nt][1] = Bl[c1i];
                }
                #pragma unroll
                for (int mt = 0; mt < 4; mt++)
                    #pragma unroll
                    for (int nt = 0; nt < 4; nt++) {
                        mma_bf16(acc[mt][nt], ah[mt][0], ah[mt][1], ah[mt][2], ah[mt][3],
                                 bh[nt][0], bh[nt][1]);
                        mma_bf16(acc[mt][nt], al[mt][0], al[mt][1], al[mt][2], al[mt][3],
                                 bh[nt][0], bh[nt][1]);
                        mma_bf16(acc[mt][nt], ah[mt][0], ah[mt][1], ah[mt][2], ah[mt][3],
                                 bl[nt][0], bl[nt][1]);
                    }
            }
        }
    }
    __syncthreads();

    // ---- epilogue
    const int KTo = N >> 5;
    #pragma unroll
    for (int mt = 0; mt < 4; mt++) {
        #pragma unroll
        for (int half = 0; half < 2; half++) {
            const int r = row0 + wm + mt * 16 + g + half * 8;
            const float rv = rowvec ? rowvec[r] : 0.f;
            #pragma unroll
            for (int nt = 0; nt < 4; nt++) {
                const int c = col0 + wn + nt * 8 + 2 * tig;
                float v0 = acc[mt][nt][half * 2 + 0];
                float v1 = acc[mt][nt][half * 2 + 1];
                if (bias)    { v0 += bias[c];    v1 += bias[c + 1]; }
                if (biasadd) { v0 += biasadd[c]; v1 += biasadd[c + 1]; }
                if (rowvec)  { v0 += rv * colvec[c]; v1 += rv * colvec[c + 1]; }
                if (gelu_flag) {
                    v0 = 0.5f * v0 * (1.f + erff(v0 * 0.70710678118654752f));
                    v1 = 0.5f * v1 * (1.f + erff(v1 * 0.70710678118654752f));
                }
                if (residual) {
                    float2 rr = *(const float2*)(residual + (size_t)r * N + c);
                    v0 += rr.x; v1 += rr.y;
                }
                if (Cfr) {
                    unsigned h, l;
                    splitp_bf16(v0, v1, h, l);
                    const size_t o = afr_index(r, c >> 1, KTo);
                    Cfr[o] = h;
                    Cfr[o + 128] = l;
                } else {
                    float2 o; o.x = v0; o.y = v1;
                    *(float2*)(Cg + (size_t)r * N + c) = o;
                }
            }
        }
    }
}

// ---------------- LayerNorm: one block per token, frag-major split out -----
__global__ __launch_bounds__(256) void ln_kernel(
    const float* __restrict__ x, const float* __restrict__ g,
    const float* __restrict__ bta, unsigned* __restrict__ outf)
{
    const int t = blockIdx.x;
    const int tid = threadIdx.x;
    const float* xr = x + (size_t)t * D_;
    const int c4 = tid * 4;

    float4 v = *(const float4*)(xr + c4);
    float s  = v.x + v.y + v.z + v.w;
    float s2 = v.x*v.x + v.y*v.y + v.z*v.z + v.w*v.w;
    #pragma unroll
    for (int o = 16; o; o >>= 1) {
        s  += __shfl_xor_sync(0xffffffffu, s,  o);
        s2 += __shfl_xor_sync(0xffffffffu, s2, o);
    }
    __shared__ float ss[8], ss2[8];
    if ((tid & 31) == 0) { ss[tid >> 5] = s; ss2[tid >> 5] = s2; }
    __syncthreads();
    s = 0.f; s2 = 0.f;
    #pragma unroll
    for (int w = 0; w < 8; w++) { s += ss[w]; s2 += ss2[w]; }

    const float mean = s * (1.f / D_);
    const float var  = s2 * (1.f / D_) - mean * mean;
    const float inv  = rsqrtf(var + 1e-5f);

    const float4 gg = *(const float4*)(g + c4);
    const float4 bb = *(const float4*)(bta + c4);
    const float y0 = (v.x - mean) * inv * gg.x + bb.x;
    const float y1 = (v.y - mean) * inv * gg.y + bb.y;
    const float y2 = (v.z - mean) * inv * gg.z + bb.z;
    const float y3 = (v.w - mean) * inv * gg.w + bb.w;

    unsigned h, l;
    splitp_bf16(y0, y1, h, l);
    size_t o = afr_index(t, c4 >> 1, D_ / 32);
    outf[o] = h; outf[o + 128] = l;
    splitp_bf16(y2, y3, h, l);
    o = afr_index(t, (c4 >> 1) + 1, D_ / 32);
    outf[o] = h; outf[o + 128] = l;
}

// ---------------- flash attention v2: tensor-core QK and PV ----------------
// grid (S/64, B*H), block 256 (8 warps: warp-m = warp>>1, warp-n = warp&1).
// Deferred cross-half sum combine: only pmax syncs per tile (3 barriers/tile).
#define FB_ST 68
#define FQ_OFF 0
#define FK_OFF 4096
#define FV_OFF (4096 + 4352)
#define FST_OFF (4096 + 2*4352)          // pmax[2][64] + endsum[64]
#define FOC_OFF FK_OFF
#define FLASH_U (4096 + 2*4352 + 256)
#define FLASH_SMEM (FLASH_U*4)           // 52224

__global__ __launch_bounds__(256, 2) void flash_kernel(
    const float* __restrict__ q, const float* __restrict__ k,
    const float* __restrict__ v, const int* __restrict__ mask,
    unsigned* __restrict__ attnf)
{
    extern __shared__ unsigned fsm[];
    unsigned* Qf = fsm + FQ_OFF;
    unsigned* Kb = fsm + FK_OFF;
    unsigned* Vb = fsm + FV_OFF;
    float* pmax   = (float*)(fsm + FST_OFF);        // [2][64]
    float* endsum = (float*)(fsm + FST_OFF + 128);  // [64]
    float* Ocomb  = (float*)(fsm + FOC_OFF);        // [64][65]

    const int bh = blockIdx.y;
    const int b = bh >> 4, h = bh & 15;
    const int qt = blockIdx.x * 64;

    const int tid  = threadIdx.x;
    const int warp = tid >> 5;
    const int lane = tid & 31;
    const int g    = lane >> 2;
    const int tig  = lane & 3;
    const int wms  = (warp >> 1) * 16;
    const int wns  = (warp & 1) * 32;
    const int wn_  = warp & 1;

    const int jj = (tid & 7) * 4;
    float invf[4];
    #pragma unroll
    for (int i2 = 0; i2 < 4; i2++)
        invf[i2] = powf(10000.f, -((float)(2*(jj+i2))) * (1.f / HD_));

    auto put_pair = [&](unsigned* base, int m, int p, float ve, float vo) {
        const int mt = m >> 4, rr = m & 15;
        const int kstep = p >> 3, pp = p & 7;
        const int fl = (rr & 7) * 4 + (pp & 3);
        const int rg = (rr >> 3) + ((pp >> 2) << 1);
        unsigned hh, ll;
        splitp_bf16(ve, vo, hh, ll);
        base[((mt * 4 + kstep) * 2 + 0) * 128 + fl * 4 + rg] = hh;
        base[((mt * 4 + kstep) * 2 + 1) * 128 + fl * 4 + rg] = ll;
    };
    #pragma unroll
    for (int it = 0; it < 2; it++) {
        const int m = (tid >> 3) + it * 32;
        const int qpos = qt + m;
        const float* qp = q + ((size_t)qpos * B_ + b) * D_ + h * HD_;
        float4 a  = *(const float4*)(qp + jj);
        float4 bb = *(const float4*)(qp + jj + 32);
        float d[4], e[4];
        float av[4] = {a.x, a.y, a.z, a.w};
        float bv[4] = {bb.x, bb.y, bb.z, bb.w};
        #pragma unroll
        for (int i2 = 0; i2 < 4; i2++) {
            float sn, cs;
            sincosf((float)qpos * invf[i2], &sn, &cs);
            d[i2] = av[i2]*cs - bv[i2]*sn;
            e[i2] = bv[i2]*cs + av[i2]*sn;
        }
        put_pair(Qf, m, (jj >> 1),      d[0], d[1]);
        put_pair(Qf, m, (jj >> 1) + 1,  d[2], d[3]);
        put_pair(Qf, m, (jj >> 1) + 16, e[0], e[1]);
        put_pair(Qf, m, (jj >> 1) + 17, e[2], e[3]);
    }

    float mrow0 = -3.0e38f, mrow1 = -3.0e38f;
    float ssum0 = 0.f, ssum1 = 0.f;      // this warp's key-half only
    float oacc[8][4];
    #pragma unroll
    for (int nt = 0; nt < 8; nt++)
        #pragma unroll
        for (int r = 0; r < 4; r++) oacc[nt][r] = 0.f;

    const float scale = 0.125f;
    const int mt_q = warp >> 1;

    for (int kt = 0; kt < S_; kt += 64) {
        // K loader (rope + split planes)
        #pragma unroll
        for (int it = 0; it < 2; it++) {
            const int m = (tid >> 3) + it * 32;
            const int kpos = kt + m;
            const float* kp = k + ((size_t)kpos * B_ + b) * D_ + h * HD_;
            float4 a  = *(const float4*)(kp + jj);
            float4 bb = *(const float4*)(kp + jj + 32);
            float av[4] = {a.x, a.y, a.z, a.w};
            float bv[4] = {bb.x, bb.y, bb.z, bb.w};
            float d[4], e[4];
            #pragma unroll
            for (int i2 = 0; i2 < 4; i2++) {
                float sn, cs;
                sincosf((float)kpos * invf[i2], &sn, &cs);
                d[i2] = av[i2]*cs - bv[i2]*sn;
                e[i2] = bv[i2]*cs + av[i2]*sn;
            }
            unsigned hh, ll;
            const int p0 = jj >> 1;
            splitp_bf16(d[0], d[1], hh, ll);
            Kb[p0*FB_ST + m] = hh; Kb[(32+p0)*FB_ST + m] = ll;
            splitp_bf16(d[2], d[3], hh, ll);
            Kb[(p0+1)*FB_ST + m] = hh; Kb[(32+p0+1)*FB_ST + m] = ll;
            splitp_bf16(e[0], e[1], hh, ll);
            Kb[(p0+16)*FB_ST + m] = hh; Kb[(32+p0+16)*FB_ST + m] = ll;
            splitp_bf16(e[2], e[3], hh, ll);
            Kb[(p0+17)*FB_ST + m] = hh; Kb[(32+p0+17)*FB_ST + m] = ll;
        }
        // V loader (split planes)
        #pragma unroll
        for (int it = 0; it < 2; it++) {
            const int s = tid + it * 256;
            const int kp2 = s >> 4;
            const int dq  = (s & 15) * 4;
            const float* v0 = v + ((size_t)(kt + 2*kp2)     * B_ + b) * D_ + h*HD_ + dq;
            const float* v1 = v + ((size_t)(kt + 2*kp2 + 1) * B_ + b) * D_ + h*HD_ + dq;
            float4 r0 = *(const float4*)v0;
            float4 r1 = *(const float4*)v1;
            uint4 hh, ll;
            splitp_bf16(r0.x, r1.x, hh.x, ll.x);
            splitp_bf16(r0.y, r1.y, hh.y, ll.y);
            splitp_bf16(r0.z, r1.z, hh.z, ll.z);
            splitp_bf16(r0.w, r1.w, hh.w, ll.w);
            *(uint4*)&Vb[kp2*FB_ST + dq] = hh;
            *(uint4*)&Vb[(32+kp2)*FB_ST + dq] = ll;
        }
        __syncthreads();

        // S = scale * Q K^T
        float sacc[4][4];
        #pragma unroll
        for (int nt = 0; nt < 4; nt++)
            #pragma unroll
            for (int r = 0; r < 4; r++) sacc[nt][r] = 0.f;
        #pragma unroll
        for (int kstep = 0; kstep < 4; kstep++) {
            const int fb = (mt_q * 4 + kstep) * 2;
            uint4 av = *(const uint4*)&Qf[fb * 128 + lane * 4];
            uint4 lv = *(const uint4*)&Qf[(fb + 1) * 128 + lane * 4];
            #pragma unroll
            for (int nt = 0; nt < 4; nt++) {
                const int n = wns + nt * 8 + g;
                const unsigned bh0 = Kb[(kstep*8 + tig)*FB_ST + n];
                const unsigned bh1 = Kb[(kstep*8 + tig + 4)*FB_ST + n];
                const unsigned bl0 = Kb[(32 + kstep*8 + tig)*FB_ST + n];
                const unsigned bl1 = Kb[(32 + kstep*8 + tig + 4)*FB_ST + n];
                mma_bf16(sacc[nt], av.x, av.y, av.z, av.w, bh0, bh1);
                mma_bf16(sacc[nt], lv.x, lv.y, lv.z, lv.w, bh0, bh1);
                mma_bf16(sacc[nt], av.x, av.y, av.z, av.w, bl0, bl1);
            }
        }
        // scale + mask
        #pragma unroll
        for (int nt = 0; nt < 4; nt++) {
            const int c0 = kt + wns + nt * 8 + 2 * tig;
            const bool m0 = (mask[b*S_ + c0] != 0);
            const bool m1 = (mask[b*S_ + c0 + 1] != 0);
            sacc[nt][0] = m0 ? -1e30f : sacc[nt][0] * scale;
            sacc[nt][2] = m0 ? -1e30f : sacc[nt][2] * scale;
            sacc[nt][1] = m1 ? -1e30f : sacc[nt][1] * scale;
            sacc[nt][3] = m1 ? -1e30f : sacc[nt][3] * scale;
        }
        // partial row max
        float rm0 = -3.0e38f, rm1 = -3.0e38f;
        #pragma unroll
        for (int nt = 0; nt < 4; nt++) {
            rm0 = fmaxf(rm0, fmaxf(sacc[nt][0], sacc[nt][1]));
            rm1 = fmaxf(rm1, fmaxf(sacc[nt][2], sacc[nt][3]));
        }
        #pragma unroll
        for (int o = 1; o < 4; o <<= 1) {
            rm0 = fmaxf(rm0, __shfl_xor_sync(0xffffffffu, rm0, o));
            rm1 = fmaxf(rm1, __shfl_xor_sync(0xffffffffu, rm1, o));
        }
        if (tig == 0) {
            pmax[wn_ * 64 + wms + g]     = rm0;
            pmax[wn_ * 64 + wms + g + 8] = rm1;
        }
        __syncthreads();
        const float mnew0 = fmaxf(mrow0, fmaxf(pmax[wms + g],     pmax[64 + wms + g]));
        const float mnew1 = fmaxf(mrow1, fmaxf(pmax[wms + g + 8], pmax[64 + wms + g + 8]));
        const float corr0 = __expf(mrow0 - mnew0);
        const float corr1 = __expf(mrow1 - mnew1);
        float rs0 = 0.f, rs1 = 0.f;
        #pragma unroll
        for (int nt = 0; nt < 4; nt++) {
            sacc[nt][0] = __expf(sacc[nt][0] - mnew0);
            sacc[nt][1] = __expf(sacc[nt][1] - mnew0);
            sacc[nt][2] = __expf(sacc[nt][2] - mnew1);
            sacc[nt][3] = __expf(sacc[nt][3] - mnew1);
            rs0 += sacc[nt][0] + sacc[nt][1];
            rs1 += sacc[nt][2] + sacc[nt][3];
        }
        #pragma unroll
        for (int o = 1; o < 4; o <<= 1) {
            rs0 += __shfl_xor_sync(0xffffffffu, rs0, o);
            rs1 += __shfl_xor_sync(0xffffffffu, rs1, o);
        }
        // local (this key-half) running sum — no cross-warp sync needed here
        ssum0 = ssum0 * corr0 + rs0;
        ssum1 = ssum1 * corr1 + rs1;
        mrow0 = mnew0; mrow1 = mnew1;
        #pragma unroll
        for (int nt = 0; nt < 8; nt++) {
            oacc[nt][0] *= corr0; oacc[nt][1] *= corr0;
            oacc[nt][2] *= corr1; oacc[nt][3] *= corr1;
        }

        // O += P V
        #pragma unroll
        for (int st = 0; st < 2; st++) {
            unsigned pa[4], pl[4];
            splitp_bf16(sacc[st*2][0],   sacc[st*2][1],   pa[0], pl[0]);
            splitp_bf16(sacc[st*2][2],   sacc[st*2][3],   pa[1], pl[1]);
            splitp_bf16(sacc[st*2+1][0], sacc[st*2+1][1], pa[2], pl[2]);
            splitp_bf16(sacc[st*2+1][2], sacc[st*2+1][3], pa[3], pl[3]);
            const int kpb = (wns >> 1) + st * 8;
            #pragma unroll
            for (int nt = 0; nt < 8; nt++) {
                const int dd = nt * 8 + g;
                const unsigned bh0 = Vb[(kpb + tig)*FB_ST + dd];
                const unsigned bh1 = Vb[(kpb + tig + 4)*FB_ST + dd];
                const unsigned bl0 = Vb[(32 + kpb + tig)*FB_ST + dd];
                const unsigned bl1 = Vb[(32 + kpb + tig + 4)*FB_ST + dd];
                mma_bf16(oacc[nt], pa[0], pa[1], pa[2], pa[3], bh0, bh1);
                mma_bf16(oacc[nt], pl[0], pl[1], pl[2], pl[3], bh0, bh1);
                mma_bf16(oacc[nt], pa[0], pa[1], pa[2], pa[3], bl0, bl1);
            }
        }
        __syncthreads();
    }

    // combine halves (O and ssum), normalize, write frag-major
    if (wn_ == 1) {
        #pragma unroll
        for (int nt = 0; nt < 8; nt++) {
            const int dd = nt * 8 + 2 * tig;
            Ocomb[(wms + g)     * 65 + dd]     = oacc[nt][0];
            Ocomb[(wms + g)     * 65 + dd + 1] = oacc[nt][1];
            Ocomb[(wms + g + 8) * 65 + dd]     = oacc[nt][2];
            Ocomb[(wms + g + 8) * 65 + dd + 1] = oacc[nt][3];
        }
        if (tig == 0) {
            endsum[wms + g]     = ssum0;
            endsum[wms + g + 8] = ssum1;
        }
    }
    __syncthreads();
    if (wn_ == 0) {
        const int r0 = wms + g, r1 = wms + g + 8;
        const float n0 = 1.f / (ssum0 + endsum[r0]);
        const float n1 = 1.f / (ssum1 + endsum[r1]);
        const int t0 = (qt + r0) * B_ + b;
        const int t1 = (qt + r1) * B_ + b;
        #pragma unroll
        for (int nt = 0; nt < 8; nt++) {
            const int dd = nt * 8 + 2 * tig;
            const float a0 = (oacc[nt][0] + Ocomb[r0 * 65 + dd])     * n0;
            const float a1 = (oacc[nt][1] + Ocomb[r0 * 65 + dd + 1]) * n0;
            const float a2 = (oacc[nt][2] + Ocomb[r1 * 65 + dd])     * n1;
            const float a3 = (oacc[nt][3] + Ocomb[r1 * 65 + dd + 1]) * n1;
            unsigned hh, ll;
            const int cp = (h * HD_ + dd) >> 1;
            splitp_bf16(a0, a1, hh, ll);
            size_t o = afr_index(t0, cp, D_ / 32);
            attnf[o] = hh; attnf[o + 128] = ll;
            splitp_bf16(a2, a3, hh, ll);
            o = afr_index(t1, cp, D_ / 32);
            attnf[o] = hh; attnf[o + 128] = ll;
        }
    }
}

// ---------------- host orchestration ---------------------------------------
extern "C" void kernel_launch(void* const* d_in, const int* in_sizes, int n_in,
                              void* d_out, int out_size)
{
    (void)in_sizes; (void)n_in; (void)out_size;

    const float* segments  = (const float*)d_in[0];
    const float* durations = (const float*)d_in[1];
    const int*   padmask   = (const int*)d_in[2];
    const float* Wproj = (const float*)d_in[3];
    const float* bproj = (const float*)d_in[4];
    const float* Wdur  = (const float*)d_in[5];
    const float* bdur  = (const float*)d_in[6];
    const float* ln1_g = (const float*)d_in[7];
    const float* ln1_b = (const float*)d_in[8];
    const float* Wq = (const float*)d_in[9];
    const float* bq = (const float*)d_in[10];
    const float* Wk = (const float*)d_in[11];
    const float* bk = (const float*)d_in[12];
    const float* Wv = (const float*)d_in[13];
    const float* bv = (const float*)d_in[14];
    const float* Wo = (const float*)d_in[15];
    const float* bo = (const float*)d_in[16];
    const float* ln2_g = (const float*)d_in[17];
    const float* ln2_b = (const float*)d_in[18];
    const float* Wff1 = (const float*)d_in[19];
    const float* bff1 = (const float*)d_in[20];
    const float* Wff2 = (const float*)d_in[21];
    const float* bff2 = (const float*)d_in[22];

    float* x = (float*)d_out;

    float *q, *k, *v;
    unsigned *segf, *hf, *attnf, *fff;
    unsigned *wprojp, *wqp, *wkp, *wvp, *wop, *w1p, *w2p;
    cudaGetSymbolAddress((void**)&q,      g_q);
    cudaGetSymbolAddress((void**)&k,      g_k);
    cudaGetSymbolAddress((void**)&v,      g_v);
    cudaGetSymbolAddress((void**)&segf,   g_segf);
    cudaGetSymbolAddress((void**)&hf,     g_hf);
    cudaGetSymbolAddress((void**)&attnf,  g_attnf);
    cudaGetSymbolAddress((void**)&fff,    g_fff);
    cudaGetSymbolAddress((void**)&wprojp, g_wprojp);
    cudaGetSymbolAddress((void**)&wqp,    g_wqp);
    cudaGetSymbolAddress((void**)&wkp,    g_wkp);
    cudaGetSymbolAddress((void**)&wvp,    g_wvp);
    cudaGetSymbolAddress((void**)&wop,    g_wop);
    cudaGetSymbolAddress((void**)&w1p,    g_w1p);
    cudaGetSymbolAddress((void**)&w2p,    g_w2p);

    cudaFuncSetAttribute(gemm_tc,
        cudaFuncAttributeMaxDynamicSharedMemorySize, SMEM_BYTES);
    cudaFuncSetAttribute(flash_kernel,
        cudaFuncAttributeMaxDynamicSharedMemorySize, FLASH_SMEM);

    // second stream for layer-weight prep (capture-fork via events)
    static cudaStream_t s2 = nullptr;
    static cudaEvent_t ev_fork = nullptr, ev_join = nullptr;
    if (!s2) {
        cudaStreamCreateWithFlags(&s2, cudaStreamNonBlocking);
        cudaEventCreateWithFlags(&ev_fork, cudaEventDisableTiming);
        cudaEventCreateWithFlags(&ev_join, cudaEventDisableTiming);
    }

    cudaEventRecord(ev_fork, 0);
    cudaStreamWaitEvent(s2, ev_fork, 0);

    // layer-weight prep on s2 (overlaps asplit/proj/ln on main stream)
    wsplit<<<dim3(128, 1, L_), 256, 0, s2>>>(Wq, wqp, D_, D_);
    wsplit<<<dim3(128, 1, L_), 256, 0, s2>>>(Wk, wkp, D_, D_);
    wsplit<<<dim3(128, 1, L_), 256, 0, s2>>>(Wv, wvp, D_, D_);
    wsplit<<<dim3(128, 1, L_), 256, 0, s2>>>(Wo, wop, D_, D_);
    wsplit<<<dim3(512, 1, L_), 256, 0, s2>>>(Wff1, w1p, D_, F_);
    wsplit<<<dim3(512, 1, L_), 256, 0, s2>>>(Wff2, w2p, F_, D_);
    cudaEventRecord(ev_join, s2);

    const dim3 blk(256);

    // main stream: input prep + proj
    asplit<<<1184, 256>>>(segments, segf, DIN_);
    wsplit<<<dim3(296, 1, 1), 256>>>(Wproj, wprojp, DIN_, D_);

    gemm_tc<<<dim3(D_/TBN, T_/TBM), blk, SMEM_BYTES>>>(
        segf, wprojp, wprojp, wprojp, bproj, bproj, bproj, bdur,
        durations, Wdur, nullptr,
        x, x, x, nullptr, T_, D_, DIN_, 0);

    // join before the first layer needs layer weights
    cudaStreamWaitEvent(0, ev_join, 0);

    for (int l = 0; l < L_; l++) {
        const size_t od = (size_t)l*D_*D_;
        const size_t o1 = (size_t)l*D_*F_;
        const size_t o2 = (size_t)l*F_*D_;

        ln_kernel<<<T_, 256>>>(x, ln1_g + l*D_, ln1_b + l*D_, hf);

        gemm_tc<<<dim3(3*D_/TBN, T_/TBM), blk, SMEM_BYTES>>>(
            hf, wqp + od, wkp + od, wvp + od,
            bq + l*D_, bk + l*D_, bv + l*D_, nullptr,
            nullptr, nullptr, nullptr,
            q, k, v, nullptr, T_, D_, D_, 0);

        flash_kernel<<<dim3(S_/64, B_*H_), blk, FLASH_SMEM>>>(
            q, k, v, padmask, attnf);

        gemm_tc<<<dim3(D_/TBN, T_/TBM), blk, SMEM_BYTES>>>(
            attnf, wop + od, wop + od, wop + od,
            bo + l*D_, bo + l*D_, bo + l*D_, nullptr,
            nullptr, nullptr, x,
            x, x, x, nullptr, T_, D_, D_, 0);

        ln_kernel<<<T_, 256>>>(x, ln2_g + l*D_, ln2_b + l*D_, hf);

        gemm_tc<<<dim3(F_/TBN, T_/TBM), blk, SMEM_BYTES>>>(
            hf, w1p + o1, w1p + o1, w1p + o1,
            bff1 + l*F_, bff1 + l*F_, bff1 + l*F_, nullptr,
            nullptr, nullptr, nullptr,
            nullptr, nullptr, nullptr, fff, T_, F_, D_, 1);

        gemm_tc<<<dim3(D_/TBN, T_/TBM), blk, SMEM_BYTES>>>(
            fff, w2p + o2, w2p + o2, w2p + o2,
            bff2 + l*D_, bff2 + l*D_, bff2 + l*D_, nullptr,
            nullptr, nullptr, x,
            x, x, x, nullptr, T_, D_, F_, 0);
    }
}